// round 5
// baseline (speedup 1.0000x reference)
#include <cuda_runtime.h>
#include <cuda_bf16.h>
#include <math.h>

// ---------------------------------------------------------------------------
// Problem constants
// ---------------------------------------------------------------------------
#define N_SRC0   262144
#define N_DST0   65536
#define N_DST1   8192
#define HID      128
#define N_CATS   9
#define CAT_VOCAB 101
#define CAT_DIM  16
#define GENRE_DIM 20
#define NE0      1048576
#define NE1      131072
#define NP       8192
#define NS       16384

// ---------------------------------------------------------------------------
// Static device scratch
// ---------------------------------------------------------------------------
__device__ float g_T[N_CATS * CAT_VOCAB * HID];
__device__ float g_h[(size_t)N_SRC0 * HID];
__device__ float g_n[(size_t)N_SRC0 * HID];
__device__ float g_agg0[(size_t)N_DST0 * HID];
__device__ float g_ws0[N_DST0];
__device__ float g_h1[(size_t)N_DST0 * HID];
__device__ float g_agg1[(size_t)N_DST1 * HID];
__device__ float g_ws1[N_DST1];
__device__ float g_hitem[(size_t)N_DST1 * HID];
__device__ float g_scores[NS];
__device__ unsigned int g_rank_sum;

// ---------------------------------------------------------------------------
// tf32 helpers
// ---------------------------------------------------------------------------
__device__ __forceinline__ unsigned f2tf32(float f) {
    unsigned u;
    asm("cvt.rna.tf32.f32 %0, %1;" : "=r"(u) : "f"(f));
    return u;
}
__device__ __forceinline__ uint2 split2(float f) {
    unsigned hi = f2tf32(f);
    float r = f - __uint_as_float(hi);
    return make_uint2(hi, f2tf32(r));
}
__device__ __forceinline__ void mma_tf32(float* c, const unsigned* a, const unsigned* b) {
    asm volatile(
        "mma.sync.aligned.m16n8k8.row.col.f32.tf32.tf32.f32 "
        "{%0,%1,%2,%3}, {%4,%5,%6,%7}, {%8,%9}, {%0,%1,%2,%3};"
        : "+f"(c[0]), "+f"(c[1]), "+f"(c[2]), "+f"(c[3])
        : "r"(a[0]), "r"(a[1]), "r"(a[2]), "r"(a[3]), "r"(b[0]), "r"(b[1]));
}

// ---------------------------------------------------------------------------
// GEMM core: 128x128 block tile, K-step 16, 8 warps (4x2), warp tile 32x64.
// Pre-split tf32 (hi,lo) planes in shared memory as uint2.
//   A plane: [row][k]  stride A_STR2 uint2 (20: conflict-free, 20 % 16 == 4)
//   B plane: [k][n]    stride B_STR2 uint2 (132: conflict-free, 132 % 16 == 4)
// ---------------------------------------------------------------------------
#define A_STR2 20
#define B_STR2 132
#define A_PLANE (128 * A_STR2)      // uint2 units per buffer
#define B_PLANE (16 * B_STR2)
#define GEMM_SMEM_BYTES ((2 * A_PLANE + 2 * B_PLANE) * 8)

__device__ __forceinline__ void tile_compute(const uint2* __restrict__ As2,
                                             const uint2* __restrict__ Bs2,
                                             float acc[2][8][4],
                                             int g, int t, int warp_m, int warp_n) {
    #pragma unroll
    for (int ks = 0; ks < 2; ks++) {
        int kb = ks * 8;
        uint2 a[2][4];
        #pragma unroll
        for (int mi = 0; mi < 2; mi++) {
            int rb = warp_m * 32 + mi * 16 + g;
            a[mi][0] = As2[rb * A_STR2 + kb + t];
            a[mi][1] = As2[(rb + 8) * A_STR2 + kb + t];
            a[mi][2] = As2[rb * A_STR2 + kb + t + 4];
            a[mi][3] = As2[(rb + 8) * A_STR2 + kb + t + 4];
        }
        #pragma unroll
        for (int ni = 0; ni < 8; ni++) {
            int n0 = warp_n * 64 + ni * 8 + g;
            uint2 b0 = Bs2[(kb + t) * B_STR2 + n0];
            uint2 b1 = Bs2[(kb + t + 4) * B_STR2 + n0];
            unsigned bh[2] = {b0.x, b1.x};
            unsigned bl[2] = {b0.y, b1.y};
            #pragma unroll
            for (int mi = 0; mi < 2; mi++) {
                unsigned ah[4] = {a[mi][0].x, a[mi][1].x, a[mi][2].x, a[mi][3].x};
                unsigned al[4] = {a[mi][0].y, a[mi][1].y, a[mi][2].y, a[mi][3].y};
                mma_tf32(acc[mi][ni], ah, bh);
                mma_tf32(acc[mi][ni], al, bh);
                mma_tf32(acc[mi][ni], ah, bl);
            }
        }
    }
}

__device__ __forceinline__ void store_a8(uint2* dst, float4 v0, float4 v1) {
    dst[0] = split2(v0.x); dst[1] = split2(v0.y);
    dst[2] = split2(v0.z); dst[3] = split2(v0.w);
    dst[4] = split2(v1.x); dst[5] = split2(v1.y);
    dst[6] = split2(v1.z); dst[7] = split2(v1.w);
}

// ---- Q GEMM: out = relu(A @ W + b), K = 128 --------------------------------
__global__ __launch_bounds__(256, 2)
void gemm_q_kernel(const float* __restrict__ A,
                   const float* __restrict__ W,
                   const float* __restrict__ bvec,
                   float* __restrict__ out) {
    extern __shared__ uint2 dsm[];
    uint2* As2 = dsm;                  // 2 buffers
    uint2* Bs2 = dsm + 2 * A_PLANE;    // 2 buffers

    const int K = 128;
    const int NIT = K / 16;
    int tid = threadIdx.x;
    int wid = tid >> 5, lane = tid & 31;
    int g = lane >> 2, t = lane & 3;
    int warp_m = wid & 3, warp_n = wid >> 2;
    int r0 = blockIdx.x * 128;

    int lr = tid >> 1;             // A load row 0..127
    int lkq = (tid & 1) * 8;       // A k offset 0 or 8
    int bk = tid >> 4;             // B load k 0..15
    int bn = (tid & 15) * 8;       // B load n

    float acc[2][8][4] = {};

    float4 ra0 = *(const float4*)&A[(size_t)(r0 + lr) * K + lkq];
    float4 ra1 = *(const float4*)&A[(size_t)(r0 + lr) * K + lkq + 4];
    float4 rb0 = *(const float4*)&W[bk * 128 + bn];
    float4 rb1 = *(const float4*)&W[bk * 128 + bn + 4];
    store_a8(&As2[lr * A_STR2 + lkq], ra0, ra1);
    store_a8(&Bs2[bk * B_STR2 + bn], rb0, rb1);
    __syncthreads();

    for (int it = 0; it < NIT; it++) {
        if (it + 1 < NIT) {
            int k0 = (it + 1) * 16;
            ra0 = *(const float4*)&A[(size_t)(r0 + lr) * K + k0 + lkq];
            ra1 = *(const float4*)&A[(size_t)(r0 + lr) * K + k0 + lkq + 4];
            rb0 = *(const float4*)&W[(k0 + bk) * 128 + bn];
            rb1 = *(const float4*)&W[(k0 + bk) * 128 + bn + 4];
        }
        int cur = it & 1;
        tile_compute(As2 + cur * A_PLANE, Bs2 + cur * B_PLANE, acc, g, t, warp_m, warp_n);
        if (it + 1 < NIT) {
            int nb = (it + 1) & 1;
            store_a8(&As2[nb * A_PLANE + lr * A_STR2 + lkq], ra0, ra1);
            store_a8(&Bs2[nb * B_PLANE + bk * B_STR2 + bn], rb0, rb1);
        }
        __syncthreads();
    }

    #pragma unroll
    for (int ni = 0; ni < 8; ni++) {
        int col = warp_n * 64 + ni * 8 + 2 * t;
        float2 bv = *(const float2*)&bvec[col];
        #pragma unroll
        for (int mi = 0; mi < 2; mi++) {
            int row0 = r0 + warp_m * 32 + mi * 16 + g;
            float2 o0, o1;
            o0.x = fmaxf(acc[mi][ni][0] + bv.x, 0.f);
            o0.y = fmaxf(acc[mi][ni][1] + bv.y, 0.f);
            o1.x = fmaxf(acc[mi][ni][2] + bv.x, 0.f);
            o1.y = fmaxf(acc[mi][ni][3] + bv.y, 0.f);
            *(float2*)&out[(size_t)row0 * 128 + col]       = o0;
            *(float2*)&out[(size_t)(row0 + 8) * 128 + col] = o1;
        }
    }
}

// ---- W GEMM + row L2-normalize (+ optional residual), K = 256 --------------
__global__ __launch_bounds__(256, 2)
void gemm_wnorm_kernel(const float* __restrict__ agg,
                       const float* __restrict__ ws,
                       const float* __restrict__ hdst,
                       const float* __restrict__ W,
                       const float* __restrict__ bvec,
                       const float* __restrict__ addsrc,
                       float* __restrict__ out) {
    extern __shared__ uint2 dsm[];
    uint2* As2 = dsm;
    uint2* Bs2 = dsm + 2 * A_PLANE;
    __shared__ float Ss[128][2];

    const int K = 256;
    const int NIT = K / 16;
    int tid = threadIdx.x;
    int wid = tid >> 5, lane = tid & 31;
    int g = lane >> 2, t = lane & 3;
    int warp_m = wid & 3, warp_n = wid >> 2;
    int r0 = blockIdx.x * 128;

    int lr = tid >> 1;
    int lkq = (tid & 1) * 8;
    int bk = tid >> 4;
    int bn = (tid & 15) * 8;

    float iw = 1.0f / fmaxf(ws[r0 + lr], 1.0f);

    float acc[2][8][4] = {};

    auto loadA = [&](int kg, float4& v0, float4& v1) {
        if (kg < 128) {
            v0 = *(const float4*)&agg[(size_t)(r0 + lr) * 128 + kg];
            v1 = *(const float4*)&agg[(size_t)(r0 + lr) * 128 + kg + 4];
            v0.x *= iw; v0.y *= iw; v0.z *= iw; v0.w *= iw;
            v1.x *= iw; v1.y *= iw; v1.z *= iw; v1.w *= iw;
        } else {
            v0 = *(const float4*)&hdst[(size_t)(r0 + lr) * 128 + (kg - 128)];
            v1 = *(const float4*)&hdst[(size_t)(r0 + lr) * 128 + (kg - 128) + 4];
        }
    };

    float4 ra0, ra1, rb0, rb1;
    loadA(lkq, ra0, ra1);
    rb0 = *(const float4*)&W[bk * 128 + bn];
    rb1 = *(const float4*)&W[bk * 128 + bn + 4];
    store_a8(&As2[lr * A_STR2 + lkq], ra0, ra1);
    store_a8(&Bs2[bk * B_STR2 + bn], rb0, rb1);
    __syncthreads();

    for (int it = 0; it < NIT; it++) {
        if (it + 1 < NIT) {
            int k0 = (it + 1) * 16;
            loadA(k0 + lkq, ra0, ra1);
            rb0 = *(const float4*)&W[(k0 + bk) * 128 + bn];
            rb1 = *(const float4*)&W[(k0 + bk) * 128 + bn + 4];
        }
        int cur = it & 1;
        tile_compute(As2 + cur * A_PLANE, Bs2 + cur * B_PLANE, acc, g, t, warp_m, warp_n);
        if (it + 1 < NIT) {
            int nb = (it + 1) & 1;
            store_a8(&As2[nb * A_PLANE + lr * A_STR2 + lkq], ra0, ra1);
            store_a8(&Bs2[nb * B_PLANE + bk * B_STR2 + bn], rb0, rb1);
        }
        __syncthreads();
    }

    // ---- epilogue: z = relu(acc + bias); per-row L2 norm; +residual --------
    float ssl[2][2] = {};
    #pragma unroll
    for (int ni = 0; ni < 8; ni++) {
        int col = warp_n * 64 + ni * 8 + 2 * t;
        float2 bv = *(const float2*)&bvec[col];
        #pragma unroll
        for (int mi = 0; mi < 2; mi++) {
            float z0 = fmaxf(acc[mi][ni][0] + bv.x, 0.f);
            float z1 = fmaxf(acc[mi][ni][1] + bv.y, 0.f);
            float z2 = fmaxf(acc[mi][ni][2] + bv.x, 0.f);
            float z3 = fmaxf(acc[mi][ni][3] + bv.y, 0.f);
            acc[mi][ni][0] = z0; acc[mi][ni][1] = z1;
            acc[mi][ni][2] = z2; acc[mi][ni][3] = z3;
            ssl[mi][0] += z0 * z0 + z1 * z1;
            ssl[mi][1] += z2 * z2 + z3 * z3;
        }
    }
    #pragma unroll
    for (int mi = 0; mi < 2; mi++)
        #pragma unroll
        for (int h = 0; h < 2; h++) {
            float s = ssl[mi][h];
            s += __shfl_xor_sync(0xffffffffu, s, 1);
            s += __shfl_xor_sync(0xffffffffu, s, 2);
            ssl[mi][h] = s;
        }
    if (t == 0) {
        #pragma unroll
        for (int mi = 0; mi < 2; mi++) {
            int r = warp_m * 32 + mi * 16 + g;
            Ss[r][warp_n]     = ssl[mi][0];
            Ss[r + 8][warp_n] = ssl[mi][1];
        }
    }
    __syncthreads();
    #pragma unroll
    for (int mi = 0; mi < 2; mi++) {
        int rl0 = warp_m * 32 + mi * 16 + g;
        float ss0 = Ss[rl0][0] + Ss[rl0][1];
        float ss1 = Ss[rl0 + 8][0] + Ss[rl0 + 8][1];
        float in0 = (ss0 > 0.f) ? rsqrtf(ss0) : 1.0f;
        float in1 = (ss1 > 0.f) ? rsqrtf(ss1) : 1.0f;
        size_t row0 = (size_t)(r0 + rl0);
        #pragma unroll
        for (int ni = 0; ni < 8; ni++) {
            int col = warp_n * 64 + ni * 8 + 2 * t;
            float2 o0, o1;
            o0.x = acc[mi][ni][0] * in0; o0.y = acc[mi][ni][1] * in0;
            o1.x = acc[mi][ni][2] * in1; o1.y = acc[mi][ni][3] * in1;
            if (addsrc) {
                float2 a0 = *(const float2*)&addsrc[row0 * 128 + col];
                float2 a1 = *(const float2*)&addsrc[(row0 + 8) * 128 + col];
                o0.x += a0.x; o0.y += a0.y;
                o1.x += a1.x; o1.y += a1.y;
            }
            *(float2*)&out[row0 * 128 + col]       = o0;
            *(float2*)&out[(row0 + 8) * 128 + col] = o1;
        }
    }
}

// ---------------------------------------------------------------------------
// Fused zero kernel
// ---------------------------------------------------------------------------
__global__ void zero_all_kernel(float* agg0, float* ws0, float* agg1, float* ws1,
                                unsigned int* R) {
    int i = blockIdx.x * blockDim.x + threadIdx.x;
    int st = gridDim.x * blockDim.x;
    float4 z = {0.f, 0.f, 0.f, 0.f};
    for (int j = i; j < N_DST0 * HID / 4; j += st) ((float4*)agg0)[j] = z;
    for (int j = i; j < N_DST1 * HID / 4; j += st) ((float4*)agg1)[j] = z;
    for (int j = i; j < N_DST0; j += st) ws0[j] = 0.f;
    for (int j = i; j < N_DST1; j += st) ws1[j] = 0.f;
    if (i == 0) *R = 0u;
}

// ---------------------------------------------------------------------------
// Precompute T[c,v,:] = cat_embs[c,v,:] @ fc_W[16c:16c+16, :]
// ---------------------------------------------------------------------------
__global__ void precompute_T_kernel(const float* __restrict__ cat_embs,
                                    const float* __restrict__ fcW,
                                    float* __restrict__ T) {
    int cv = blockIdx.x;
    int c = cv / CAT_VOCAB;
    int n = threadIdx.x;
    const float* e = &cat_embs[cv * CAT_DIM];
    float acc = 0.f;
    #pragma unroll
    for (int d = 0; d < CAT_DIM; d++)
        acc += __ldg(&e[d]) * fcW[(c * CAT_DIM + d) * HID + n];
    T[cv * HID + n] = acc;
}

// ---------------------------------------------------------------------------
// proj
// ---------------------------------------------------------------------------
#define ROWS_PER_WARP 16
__global__ __launch_bounds__(256)
void proj_kernel(const int* __restrict__ ids,
                 const int* __restrict__ cats,
                 const float* __restrict__ genre,
                 const float* __restrict__ T,
                 const float* __restrict__ fcW,
                 const float* __restrict__ fcb,
                 const float* __restrict__ track_emb,
                 float* __restrict__ out) {
    int warp = threadIdx.x >> 5, lane = threadIdx.x & 31;
    float4 Wg[GENRE_DIM];
    #pragma unroll
    for (int g = 0; g < GENRE_DIM; g++)
        Wg[g] = *(const float4*)&fcW[(144 + g) * HID + lane * 4];
    float4 bb = *(const float4*)&fcb[lane * 4];

    int rbase = (blockIdx.x * 8 + warp) * ROWS_PER_WARP;
    for (int rr = 0; rr < ROWS_PER_WARP; rr++) {
        int r = rbase + rr;
        int myc = (lane < N_CATS) ? cats[r * N_CATS + lane] : 0;
        float gv = (lane < GENRE_DIM) ? genre[(size_t)r * GENRE_DIM + lane] : 0.f;
        int id = ids[r];
        float4 acc = bb;
        #pragma unroll
        for (int c = 0; c < N_CATS; c++) {
            int v = __shfl_sync(0xffffffffu, myc, c);
            float4 t = *(const float4*)&T[(c * CAT_VOCAB + v) * HID + lane * 4];
            acc.x += t.x; acc.y += t.y; acc.z += t.z; acc.w += t.w;
        }
        #pragma unroll
        for (int g = 0; g < GENRE_DIM; g++) {
            float s = __shfl_sync(0xffffffffu, gv, g);
            acc.x += s * Wg[g].x; acc.y += s * Wg[g].y;
            acc.z += s * Wg[g].z; acc.w += s * Wg[g].w;
        }
        float4 te = *(const float4*)&track_emb[(size_t)id * HID + lane * 4];
        acc.x += te.x; acc.y += te.y; acc.z += te.z; acc.w += te.w;
        *(float4*)&out[(size_t)r * HID + lane * 4] = acc;
    }
}

// ---------------------------------------------------------------------------
// Edge aggregation: vector red.global.add.v4.f32 (sm_90+), 1 warp / edge
// ---------------------------------------------------------------------------
__global__ __launch_bounds__(256)
void edge_agg_kernel(const float* __restrict__ nmat,
                     const int* __restrict__ es,
                     const int* __restrict__ ed,
                     const float* __restrict__ w,
                     float* __restrict__ agg,
                     float* __restrict__ ws,
                     int nE) {
    int wid = (blockIdx.x * blockDim.x + threadIdx.x) >> 5;
    int lane = threadIdx.x & 31;
    if (wid >= nE) return;
    int s = __ldg(&es[wid]);
    int d = __ldg(&ed[wid]);
    float wt = __ldg(&w[wid]);
    float4 v = *(const float4*)&nmat[(size_t)s * 128 + lane * 4];
    float* dst = &agg[(size_t)d * 128 + lane * 4];
#if !defined(__CUDA_ARCH__) || __CUDA_ARCH__ >= 900
    asm volatile("red.global.add.v4.f32 [%0], {%1,%2,%3,%4};"
                 :: "l"(dst), "f"(v.x * wt), "f"(v.y * wt), "f"(v.z * wt), "f"(v.w * wt)
                 : "memory");
#else
    atomicAdd(dst + 0, v.x * wt);
    atomicAdd(dst + 1, v.y * wt);
    atomicAdd(dst + 2, v.z * wt);
    atomicAdd(dst + 3, v.w * wt);
#endif
    if (lane == 0) atomicAdd(&ws[d], wt);
}

// ---------------------------------------------------------------------------
// Scores / loss / AUC
// ---------------------------------------------------------------------------
__global__ __launch_bounds__(256)
void score_kernel(const float* __restrict__ hi,
                  const int* __restrict__ ps, const int* __restrict__ pd,
                  const int* __restrict__ ns, const int* __restrict__ nd,
                  const int* __restrict__ nids,
                  const float* __restrict__ bias,
                  float* __restrict__ scores) {
    int wid = (blockIdx.x * blockDim.x + threadIdx.x) >> 5;
    int lane = threadIdx.x & 31;
    if (wid >= NS) return;
    int s, d;
    if (wid < NP) { s = ps[wid]; d = pd[wid]; }
    else          { s = ns[wid - NP]; d = nd[wid - NP]; }
    float4 a = *(const float4*)&hi[(size_t)s * 128 + lane * 4];
    float4 b = *(const float4*)&hi[(size_t)d * 128 + lane * 4];
    float p = a.x * b.x + a.y * b.y + a.z * b.z + a.w * b.w;
    #pragma unroll
    for (int off = 16; off > 0; off >>= 1)
        p += __shfl_xor_sync(0xffffffffu, p, off);
    if (lane == 0)
        scores[wid] = p + bias[nids[s]] + bias[nids[d]];
}

__global__ void loss_kernel(const float* __restrict__ scores, float* __restrict__ out) {
    int i = blockIdx.x * blockDim.x + threadIdx.x;
    if (i < NP)
        out[i] = fmaxf(scores[NP + i] - scores[i] + 1.0f, 0.0f);
}

#define AUC_JCH 2048
__global__ __launch_bounds__(256)
void auc_count_kernel(const float* __restrict__ scores, unsigned int* __restrict__ R) {
    __shared__ float ss[AUC_JCH];
    int tid = threadIdx.x;
    int j0 = blockIdx.y * AUC_JCH;
    for (int j = tid; j < AUC_JCH; j += blockDim.x) ss[j] = scores[j0 + j];
    __syncthreads();
    int i = blockIdx.x * blockDim.x + tid;
    float my = scores[i];
    unsigned int cnt = 0;
    #pragma unroll 4
    for (int jj = 0; jj < AUC_JCH; jj++) {
        float v = ss[jj];
        int j = j0 + jj;
        cnt += (v < my) || (v == my && j < i);
    }
    #pragma unroll
    for (int off = 16; off > 0; off >>= 1)
        cnt += __shfl_xor_sync(0xffffffffu, cnt, off);
    if ((tid & 31) == 0) atomicAdd(R, cnt);
}

__global__ void auc_final_kernel(const unsigned int* __restrict__ R, float* __restrict__ out) {
    double r = (double)(*R);
    double npos = (double)NP, nneg = (double)NP;
    out[0] = (float)((r - npos * (npos - 1.0) * 0.5) / (npos * nneg));
}

// ---------------------------------------------------------------------------
// Launch
// ---------------------------------------------------------------------------
extern "C" void kernel_launch(void* const* d_in, const int* in_sizes, int n_in,
                              void* d_out, int out_size) {
    const int*   src0_id   = (const int*)  d_in[0];
    const int*   src0_cats = (const int*)  d_in[1];
    const float* src0_genre= (const float*)d_in[2];
    const int*   es0       = (const int*)  d_in[3];
    const int*   ed0       = (const int*)  d_in[4];
    const float* w0        = (const float*)d_in[5];
    const int*   es1       = (const int*)  d_in[6];
    const int*   ed1       = (const int*)  d_in[7];
    const float* w1        = (const float*)d_in[8];
    const int*   pos_src   = (const int*)  d_in[9];
    const int*   pos_dst   = (const int*)  d_in[10];
    const int*   neg_src   = (const int*)  d_in[11];
    const int*   neg_dst   = (const int*)  d_in[12];
    const int*   seed_nids = (const int*)  d_in[13];
    const float* track_emb = (const float*)d_in[14];
    const float* cat_embs  = (const float*)d_in[15];
    const float* fc_W      = (const float*)d_in[16];
    const float* fc_b      = (const float*)d_in[17];
    const float* Q0_W      = (const float*)d_in[18];
    const float* Q0_b      = (const float*)d_in[19];
    const float* W0_W      = (const float*)d_in[20];
    const float* W0_b      = (const float*)d_in[21];
    const float* Q1_W      = (const float*)d_in[22];
    const float* Q1_b      = (const float*)d_in[23];
    const float* W1_W      = (const float*)d_in[24];
    const float* W1_b      = (const float*)d_in[25];
    const float* bias      = (const float*)d_in[26];
    float* out = (float*)d_out;

    float *p_T, *p_h, *p_n, *p_agg0, *p_ws0, *p_h1, *p_agg1, *p_ws1, *p_hitem, *p_scores;
    unsigned int* p_R;
    cudaGetSymbolAddress((void**)&p_T,     g_T);
    cudaGetSymbolAddress((void**)&p_h,     g_h);
    cudaGetSymbolAddress((void**)&p_n,     g_n);
    cudaGetSymbolAddress((void**)&p_agg0,  g_agg0);
    cudaGetSymbolAddress((void**)&p_ws0,   g_ws0);
    cudaGetSymbolAddress((void**)&p_h1,    g_h1);
    cudaGetSymbolAddress((void**)&p_agg1,  g_agg1);
    cudaGetSymbolAddress((void**)&p_ws1,   g_ws1);
    cudaGetSymbolAddress((void**)&p_hitem, g_hitem);
    cudaGetSymbolAddress((void**)&p_scores,g_scores);
    cudaGetSymbolAddress((void**)&p_R,     g_rank_sum);

    // opt-in dynamic smem (73 KB) for the tensor GEMMs
    cudaFuncSetAttribute(gemm_q_kernel,
                         cudaFuncAttributeMaxDynamicSharedMemorySize, GEMM_SMEM_BYTES);
    cudaFuncSetAttribute(gemm_wnorm_kernel,
                         cudaFuncAttributeMaxDynamicSharedMemorySize, GEMM_SMEM_BYTES);

    // Launch order keeps ncu (-s 5 -c 1) on launch #6 = gemm_wnorm0
    zero_all_kernel<<<1024, 256>>>(p_agg0, p_ws0, p_agg1, p_ws1, p_R);                   // 1
    precompute_T_kernel<<<N_CATS * CAT_VOCAB, 128>>>(cat_embs, fc_W, p_T);               // 2
    proj_kernel<<<N_SRC0 / (8 * ROWS_PER_WARP), 256>>>(src0_id, src0_cats, src0_genre,   // 3
                                                       p_T, fc_W, fc_b, track_emb, p_h);
    gemm_q_kernel<<<N_SRC0 / 128, 256, GEMM_SMEM_BYTES>>>(p_h, Q0_W, Q0_b, p_n);         // 4
    edge_agg_kernel<<<NE0 / 8, 256>>>(p_n, es0, ed0, w0, p_agg0, p_ws0, NE0);            // 5
    gemm_wnorm_kernel<<<N_DST0 / 128, 256, GEMM_SMEM_BYTES>>>(p_agg0, p_ws0, p_h,        // 6 (ncu)
                                                              W0_W, W0_b, nullptr, p_h1);

    gemm_q_kernel<<<N_DST0 / 128, 256, GEMM_SMEM_BYTES>>>(p_h1, Q1_W, Q1_b, p_n);
    edge_agg_kernel<<<NE1 / 8, 256>>>(p_n, es1, ed1, w1, p_agg1, p_ws1, NE1);
    gemm_wnorm_kernel<<<N_DST1 / 128, 256, GEMM_SMEM_BYTES>>>(p_agg1, p_ws1, p_h1,
                                                              W1_W, W1_b, p_h, p_hitem);

    score_kernel<<<NS / 8, 256>>>(p_hitem, pos_src, pos_dst, neg_src, neg_dst,
                                  seed_nids, bias, p_scores);
    loss_kernel<<<NP / 256, 256>>>(p_scores, out);

    dim3 auc_grid(NP / 256, NS / AUC_JCH);
    auc_count_kernel<<<auc_grid, 256>>>(p_scores, p_R);
    if (out_size >= NP + 1)
        auc_final_kernel<<<1, 1>>>(p_R, out + NP);
}

// round 6
// speedup vs baseline: 1.0411x; 1.0411x over previous
#include <cuda_runtime.h>
#include <cuda_bf16.h>
#include <math.h>

// ---------------------------------------------------------------------------
// Problem constants
// ---------------------------------------------------------------------------
#define N_SRC0   262144
#define N_DST0   65536
#define N_DST1   8192
#define HID      128
#define N_CATS   9
#define CAT_VOCAB 101
#define CAT_DIM  16
#define GENRE_DIM 20
#define NE0      1048576
#define NE1      131072
#define NP       8192
#define NS       16384

// ---------------------------------------------------------------------------
// Static device scratch
// ---------------------------------------------------------------------------
__device__ float g_T[N_CATS * CAT_VOCAB * HID];
__device__ float g_h[(size_t)N_SRC0 * HID];
__device__ float g_n[(size_t)N_SRC0 * HID];
__device__ float g_agg0[(size_t)N_DST0 * HID];   // pre-divided mean
__device__ float g_h1[(size_t)N_DST0 * HID];
__device__ float g_agg1[(size_t)N_DST1 * HID];
__device__ float g_hitem[(size_t)N_DST1 * HID];
__device__ float g_scores[NS];
__device__ unsigned int g_rank_sum;
// edge bucketing scratch
__device__ int g_cnt0[N_DST0];
__device__ int g_cnt0b[N_DST0];
__device__ int g_base0[N_DST0 + 1];
__device__ int g_sorted0[NE0];
__device__ int g_cnt1[N_DST1];
__device__ int g_cnt1b[N_DST1];
__device__ int g_base1[N_DST1 + 1];
__device__ int g_sorted1[NE1];

// ---------------------------------------------------------------------------
// tf32 helpers
// ---------------------------------------------------------------------------
__device__ __forceinline__ unsigned f2tf32(float f) {
    unsigned u;
    asm("cvt.rna.tf32.f32 %0, %1;" : "=r"(u) : "f"(f));
    return u;
}
__device__ __forceinline__ void split_tf32(float f, unsigned& hi, unsigned& lo) {
    hi = f2tf32(f);
    float r = f - __uint_as_float(hi);
    lo = f2tf32(r);
}
__device__ __forceinline__ void mma_tf32(float* c, const unsigned* a, const unsigned* b) {
    asm volatile(
        "mma.sync.aligned.m16n8k8.row.col.f32.tf32.tf32.f32 "
        "{%0,%1,%2,%3}, {%4,%5,%6,%7}, {%8,%9}, {%0,%1,%2,%3};"
        : "+f"(c[0]), "+f"(c[1]), "+f"(c[2]), "+f"(c[3])
        : "r"(a[0]), "r"(a[1]), "r"(a[2]), "r"(a[3]), "r"(b[0]), "r"(b[1]));
}

// ---------------------------------------------------------------------------
// GEMM core (R4 version): 128x128 tile, K-step 16, 8 warps (4x2),
// warp tile 32x64, tf32x3, split at smem read (hoisted per fragment).
// ---------------------------------------------------------------------------
#define A_STR 20
#define B_STR 136

__device__ __forceinline__ void tile_compute(const float* __restrict__ As,
                                             const float* __restrict__ Bs,
                                             float acc[2][8][4],
                                             int g, int t, int warp_m, int warp_n) {
    #pragma unroll
    for (int ks = 0; ks < 2; ks++) {
        int kb = ks * 8;
        unsigned ahi[2][4], alo[2][4];
        #pragma unroll
        for (int mi = 0; mi < 2; mi++) {
            int rb = warp_m * 32 + mi * 16 + g;
            float a0 = As[rb * A_STR + kb + t];
            float a1 = As[(rb + 8) * A_STR + kb + t];
            float a2 = As[rb * A_STR + kb + t + 4];
            float a3 = As[(rb + 8) * A_STR + kb + t + 4];
            split_tf32(a0, ahi[mi][0], alo[mi][0]);
            split_tf32(a1, ahi[mi][1], alo[mi][1]);
            split_tf32(a2, ahi[mi][2], alo[mi][2]);
            split_tf32(a3, ahi[mi][3], alo[mi][3]);
        }
        #pragma unroll
        for (int ni = 0; ni < 8; ni++) {
            int n0 = warp_n * 64 + ni * 8 + g;
            float b0 = Bs[(kb + t) * B_STR + n0];
            float b1 = Bs[(kb + t + 4) * B_STR + n0];
            unsigned bh[2], bl[2];
            split_tf32(b0, bh[0], bl[0]);
            split_tf32(b1, bh[1], bl[1]);
            #pragma unroll
            for (int mi = 0; mi < 2; mi++) {
                mma_tf32(acc[mi][ni], ahi[mi], bh);
                mma_tf32(acc[mi][ni], alo[mi], bh);
                mma_tf32(acc[mi][ni], ahi[mi], bl);
            }
        }
    }
}

// ---- Q GEMM: out = relu(A @ W + b), K = 128 --------------------------------
__global__ __launch_bounds__(256, 2)
void gemm_q_kernel(const float* __restrict__ A,
                   const float* __restrict__ W,
                   const float* __restrict__ bvec,
                   float* __restrict__ out) {
    __shared__ float As[2][128 * A_STR];
    __shared__ float Bs[2][16 * B_STR];

    const int K = 128;
    const int NIT = K / 16;
    int tid = threadIdx.x;
    int wid = tid >> 5, lane = tid & 31;
    int g = lane >> 2, t = lane & 3;
    int warp_m = wid & 3, warp_n = wid >> 2;
    int r0 = blockIdx.x * 128;

    int lr = tid >> 1;
    int lkq = (tid & 1) * 8;
    int bk = tid >> 4;
    int bn = (tid & 15) * 8;

    float acc[2][8][4] = {};

    float4 ra0 = *(const float4*)&A[(size_t)(r0 + lr) * K + lkq];
    float4 ra1 = *(const float4*)&A[(size_t)(r0 + lr) * K + lkq + 4];
    float4 rb0 = *(const float4*)&W[bk * 128 + bn];
    float4 rb1 = *(const float4*)&W[bk * 128 + bn + 4];
    *(float4*)&As[0][lr * A_STR + lkq]     = ra0;
    *(float4*)&As[0][lr * A_STR + lkq + 4] = ra1;
    *(float4*)&Bs[0][bk * B_STR + bn]     = rb0;
    *(float4*)&Bs[0][bk * B_STR + bn + 4] = rb1;
    __syncthreads();

    for (int it = 0; it < NIT; it++) {
        if (it + 1 < NIT) {
            int k0 = (it + 1) * 16;
            ra0 = *(const float4*)&A[(size_t)(r0 + lr) * K + k0 + lkq];
            ra1 = *(const float4*)&A[(size_t)(r0 + lr) * K + k0 + lkq + 4];
            rb0 = *(const float4*)&W[(k0 + bk) * 128 + bn];
            rb1 = *(const float4*)&W[(k0 + bk) * 128 + bn + 4];
        }
        tile_compute(As[it & 1], Bs[it & 1], acc, g, t, warp_m, warp_n);
        if (it + 1 < NIT) {
            int b = (it + 1) & 1;
            *(float4*)&As[b][lr * A_STR + lkq]     = ra0;
            *(float4*)&As[b][lr * A_STR + lkq + 4] = ra1;
            *(float4*)&Bs[b][bk * B_STR + bn]     = rb0;
            *(float4*)&Bs[b][bk * B_STR + bn + 4] = rb1;
        }
        __syncthreads();
    }

    #pragma unroll
    for (int ni = 0; ni < 8; ni++) {
        int col = warp_n * 64 + ni * 8 + 2 * t;
        float2 bv = *(const float2*)&bvec[col];
        #pragma unroll
        for (int mi = 0; mi < 2; mi++) {
            int row0 = r0 + warp_m * 32 + mi * 16 + g;
            float2 o0, o1;
            o0.x = fmaxf(acc[mi][ni][0] + bv.x, 0.f);
            o0.y = fmaxf(acc[mi][ni][1] + bv.y, 0.f);
            o1.x = fmaxf(acc[mi][ni][2] + bv.x, 0.f);
            o1.y = fmaxf(acc[mi][ni][3] + bv.y, 0.f);
            *(float2*)&out[(size_t)row0 * 128 + col]       = o0;
            *(float2*)&out[(size_t)(row0 + 8) * 128 + col] = o1;
        }
    }
}

// ---- W GEMM + row L2-normalize (+ optional residual), K = 256 --------------
// agg is already the weighted mean (pre-divided) — no ws needed.
__global__ __launch_bounds__(256, 2)
void gemm_wnorm_kernel(const float* __restrict__ agg,
                       const float* __restrict__ hdst,
                       const float* __restrict__ W,
                       const float* __restrict__ bvec,
                       const float* __restrict__ addsrc,
                       float* __restrict__ out) {
    __shared__ float As[2][128 * A_STR];
    __shared__ float Bs[2][16 * B_STR];
    __shared__ float Ss[128][2];

    const int K = 256;
    const int NIT = K / 16;
    int tid = threadIdx.x;
    int wid = tid >> 5, lane = tid & 31;
    int g = lane >> 2, t = lane & 3;
    int warp_m = wid & 3, warp_n = wid >> 2;
    int r0 = blockIdx.x * 128;

    int lr = tid >> 1;
    int lkq = (tid & 1) * 8;
    int bk = tid >> 4;
    int bn = (tid & 15) * 8;

    float acc[2][8][4] = {};

    auto loadA = [&](int kg, float4& v0, float4& v1) {
        if (kg < 128) {
            v0 = *(const float4*)&agg[(size_t)(r0 + lr) * 128 + kg];
            v1 = *(const float4*)&agg[(size_t)(r0 + lr) * 128 + kg + 4];
        } else {
            v0 = *(const float4*)&hdst[(size_t)(r0 + lr) * 128 + (kg - 128)];
            v1 = *(const float4*)&hdst[(size_t)(r0 + lr) * 128 + (kg - 128) + 4];
        }
    };

    float4 ra0, ra1, rb0, rb1;
    loadA(lkq, ra0, ra1);
    rb0 = *(const float4*)&W[bk * 128 + bn];
    rb1 = *(const float4*)&W[bk * 128 + bn + 4];
    *(float4*)&As[0][lr * A_STR + lkq]     = ra0;
    *(float4*)&As[0][lr * A_STR + lkq + 4] = ra1;
    *(float4*)&Bs[0][bk * B_STR + bn]     = rb0;
    *(float4*)&Bs[0][bk * B_STR + bn + 4] = rb1;
    __syncthreads();

    for (int it = 0; it < NIT; it++) {
        if (it + 1 < NIT) {
            int k0 = (it + 1) * 16;
            loadA(k0 + lkq, ra0, ra1);
            rb0 = *(const float4*)&W[(k0 + bk) * 128 + bn];
            rb1 = *(const float4*)&W[(k0 + bk) * 128 + bn + 4];
        }
        tile_compute(As[it & 1], Bs[it & 1], acc, g, t, warp_m, warp_n);
        if (it + 1 < NIT) {
            int b = (it + 1) & 1;
            *(float4*)&As[b][lr * A_STR + lkq]     = ra0;
            *(float4*)&As[b][lr * A_STR + lkq + 4] = ra1;
            *(float4*)&Bs[b][bk * B_STR + bn]     = rb0;
            *(float4*)&Bs[b][bk * B_STR + bn + 4] = rb1;
        }
        __syncthreads();
    }

    float ssl[2][2] = {};
    #pragma unroll
    for (int ni = 0; ni < 8; ni++) {
        int col = warp_n * 64 + ni * 8 + 2 * t;
        float2 bv = *(const float2*)&bvec[col];
        #pragma unroll
        for (int mi = 0; mi < 2; mi++) {
            float z0 = fmaxf(acc[mi][ni][0] + bv.x, 0.f);
            float z1 = fmaxf(acc[mi][ni][1] + bv.y, 0.f);
            float z2 = fmaxf(acc[mi][ni][2] + bv.x, 0.f);
            float z3 = fmaxf(acc[mi][ni][3] + bv.y, 0.f);
            acc[mi][ni][0] = z0; acc[mi][ni][1] = z1;
            acc[mi][ni][2] = z2; acc[mi][ni][3] = z3;
            ssl[mi][0] += z0 * z0 + z1 * z1;
            ssl[mi][1] += z2 * z2 + z3 * z3;
        }
    }
    #pragma unroll
    for (int mi = 0; mi < 2; mi++)
        #pragma unroll
        for (int h = 0; h < 2; h++) {
            float s = ssl[mi][h];
            s += __shfl_xor_sync(0xffffffffu, s, 1);
            s += __shfl_xor_sync(0xffffffffu, s, 2);
            ssl[mi][h] = s;
        }
    if (t == 0) {
        #pragma unroll
        for (int mi = 0; mi < 2; mi++) {
            int r = warp_m * 32 + mi * 16 + g;
            Ss[r][warp_n]     = ssl[mi][0];
            Ss[r + 8][warp_n] = ssl[mi][1];
        }
    }
    __syncthreads();
    #pragma unroll
    for (int mi = 0; mi < 2; mi++) {
        int rl0 = warp_m * 32 + mi * 16 + g;
        float ss0 = Ss[rl0][0] + Ss[rl0][1];
        float ss1 = Ss[rl0 + 8][0] + Ss[rl0 + 8][1];
        float in0 = (ss0 > 0.f) ? rsqrtf(ss0) : 1.0f;
        float in1 = (ss1 > 0.f) ? rsqrtf(ss1) : 1.0f;
        size_t row0 = (size_t)(r0 + rl0);
        #pragma unroll
        for (int ni = 0; ni < 8; ni++) {
            int col = warp_n * 64 + ni * 8 + 2 * t;
            float2 o0, o1;
            o0.x = acc[mi][ni][0] * in0; o0.y = acc[mi][ni][1] * in0;
            o1.x = acc[mi][ni][2] * in1; o1.y = acc[mi][ni][3] * in1;
            if (addsrc) {
                float2 a0 = *(const float2*)&addsrc[row0 * 128 + col];
                float2 a1 = *(const float2*)&addsrc[(row0 + 8) * 128 + col];
                o0.x += a0.x; o0.y += a0.y;
                o1.x += a1.x; o1.y += a1.y;
            }
            *(float2*)&out[row0 * 128 + col]       = o0;
            *(float2*)&out[(row0 + 8) * 128 + col] = o1;
        }
    }
}

// ---------------------------------------------------------------------------
// Edge bucketing: histogram -> scan -> scatter -> per-dst warp accumulate
// ---------------------------------------------------------------------------
__global__ void zero_all_kernel(int* c0, int* c0b, int* c1, int* c1b, unsigned int* R) {
    int i = blockIdx.x * blockDim.x + threadIdx.x;
    int st = gridDim.x * blockDim.x;
    for (int j = i; j < N_DST0; j += st) { c0[j] = 0; c0b[j] = 0; }
    for (int j = i; j < N_DST1; j += st) { c1[j] = 0; c1b[j] = 0; }
    if (i == 0) *R = 0u;
}

__global__ void hist_kernel(const int* __restrict__ ed, int* __restrict__ cnt, int nE) {
    int i = blockIdx.x * blockDim.x + threadIdx.x;
    int st = gridDim.x * blockDim.x;
    for (; i < nE; i += st) atomicAdd(&cnt[ed[i]], 1);
}

// single block, 1024 threads; n must be a multiple of 1024
__global__ __launch_bounds__(1024)
void scan_kernel(const int* __restrict__ cnt, int* __restrict__ base, int n) {
    __shared__ int wsums[32];
    int tid = threadIdx.x;
    int lane = tid & 31, wid = tid >> 5;
    int chunk = n >> 10;
    int start = tid * chunk;
    int s = 0;
    for (int j = 0; j < chunk; j++) s += cnt[start + j];
    // inclusive warp scan
    int v = s;
    #pragma unroll
    for (int off = 1; off < 32; off <<= 1) {
        int t = __shfl_up_sync(0xffffffffu, v, off);
        if (lane >= off) v += t;
    }
    if (lane == 31) wsums[wid] = v;
    __syncthreads();
    if (wid == 0) {
        int u = wsums[lane];
        #pragma unroll
        for (int off = 1; off < 32; off <<= 1) {
            int t = __shfl_up_sync(0xffffffffu, u, off);
            if (lane >= off) u += t;
        }
        wsums[lane] = u;
    }
    __syncthreads();
    int excl = v - s + (wid > 0 ? wsums[wid - 1] : 0);
    int run = excl;
    for (int j = 0; j < chunk; j++) {
        base[start + j] = run;
        run += cnt[start + j];
    }
    if (tid == 1023) base[n] = run;
}

__global__ void scatter_kernel(const int* __restrict__ ed, const int* __restrict__ base,
                               int* __restrict__ cnt2, int* __restrict__ sorted, int nE) {
    int i = blockIdx.x * blockDim.x + threadIdx.x;
    int st = gridDim.x * blockDim.x;
    for (; i < nE; i += st) {
        int d = ed[i];
        int pos = base[d] + atomicAdd(&cnt2[d], 1);
        sorted[pos] = i;
    }
}

// one warp per dst: accumulate all its edges in registers, write mean once
__global__ __launch_bounds__(256)
void agg_sorted_kernel(const float* __restrict__ nmat,
                       const int* __restrict__ es,
                       const float* __restrict__ w,
                       const int* __restrict__ sorted,
                       const int* __restrict__ base,
                       float* __restrict__ aggout,
                       int ndst) {
    int d = (blockIdx.x * blockDim.x + threadIdx.x) >> 5;
    int lane = threadIdx.x & 31;
    if (d >= ndst) return;
    int j0 = base[d], j1 = base[d + 1];
    float4 acc = {0.f, 0.f, 0.f, 0.f};
    float wsum = 0.f;
    for (int j = j0; j < j1; j++) {
        int e = __ldg(&sorted[j]);
        int s = __ldg(&es[e]);
        float wt = __ldg(&w[e]);
        float4 v = *(const float4*)&nmat[(size_t)s * 128 + lane * 4];
        acc.x += v.x * wt; acc.y += v.y * wt;
        acc.z += v.z * wt; acc.w += v.w * wt;
        wsum += wt;
    }
    float inv = 1.0f / fmaxf(wsum, 1.0f);
    acc.x *= inv; acc.y *= inv; acc.z *= inv; acc.w *= inv;
    *(float4*)&aggout[(size_t)d * 128 + lane * 4] = acc;
}

// ---------------------------------------------------------------------------
// Precompute T[c,v,:] = cat_embs[c,v,:] @ fc_W[16c:16c+16, :]
// ---------------------------------------------------------------------------
__global__ void precompute_T_kernel(const float* __restrict__ cat_embs,
                                    const float* __restrict__ fcW,
                                    float* __restrict__ T) {
    int cv = blockIdx.x;
    int c = cv / CAT_VOCAB;
    int n = threadIdx.x;
    const float* e = &cat_embs[cv * CAT_DIM];
    float acc = 0.f;
    #pragma unroll
    for (int d = 0; d < CAT_DIM; d++)
        acc += __ldg(&e[d]) * fcW[(c * CAT_DIM + d) * HID + n];
    T[cv * HID + n] = acc;
}

// ---------------------------------------------------------------------------
// proj
// ---------------------------------------------------------------------------
#define ROWS_PER_WARP 16
__global__ __launch_bounds__(256)
void proj_kernel(const int* __restrict__ ids,
                 const int* __restrict__ cats,
                 const float* __restrict__ genre,
                 const float* __restrict__ T,
                 const float* __restrict__ fcW,
                 const float* __restrict__ fcb,
                 const float* __restrict__ track_emb,
                 float* __restrict__ out) {
    int warp = threadIdx.x >> 5, lane = threadIdx.x & 31;
    float4 Wg[GENRE_DIM];
    #pragma unroll
    for (int g = 0; g < GENRE_DIM; g++)
        Wg[g] = *(const float4*)&fcW[(144 + g) * HID + lane * 4];
    float4 bb = *(const float4*)&fcb[lane * 4];

    int rbase = (blockIdx.x * 8 + warp) * ROWS_PER_WARP;
    for (int rr = 0; rr < ROWS_PER_WARP; rr++) {
        int r = rbase + rr;
        int myc = (lane < N_CATS) ? cats[r * N_CATS + lane] : 0;
        float gv = (lane < GENRE_DIM) ? genre[(size_t)r * GENRE_DIM + lane] : 0.f;
        int id = ids[r];
        float4 acc = bb;
        #pragma unroll
        for (int c = 0; c < N_CATS; c++) {
            int v = __shfl_sync(0xffffffffu, myc, c);
            float4 t = *(const float4*)&T[(c * CAT_VOCAB + v) * HID + lane * 4];
            acc.x += t.x; acc.y += t.y; acc.z += t.z; acc.w += t.w;
        }
        #pragma unroll
        for (int g = 0; g < GENRE_DIM; g++) {
            float s = __shfl_sync(0xffffffffu, gv, g);
            acc.x += s * Wg[g].x; acc.y += s * Wg[g].y;
            acc.z += s * Wg[g].z; acc.w += s * Wg[g].w;
        }
        float4 te = *(const float4*)&track_emb[(size_t)id * HID + lane * 4];
        acc.x += te.x; acc.y += te.y; acc.z += te.z; acc.w += te.w;
        *(float4*)&out[(size_t)r * HID + lane * 4] = acc;
    }
}

// ---------------------------------------------------------------------------
// Scores / loss / AUC
// ---------------------------------------------------------------------------
__global__ __launch_bounds__(256)
void score_kernel(const float* __restrict__ hi,
                  const int* __restrict__ ps, const int* __restrict__ pd,
                  const int* __restrict__ ns, const int* __restrict__ nd,
                  const int* __restrict__ nids,
                  const float* __restrict__ bias,
                  float* __restrict__ scores) {
    int wid = (blockIdx.x * blockDim.x + threadIdx.x) >> 5;
    int lane = threadIdx.x & 31;
    if (wid >= NS) return;
    int s, d;
    if (wid < NP) { s = ps[wid]; d = pd[wid]; }
    else          { s = ns[wid - NP]; d = nd[wid - NP]; }
    float4 a = *(const float4*)&hi[(size_t)s * 128 + lane * 4];
    float4 b = *(const float4*)&hi[(size_t)d * 128 + lane * 4];
    float p = a.x * b.x + a.y * b.y + a.z * b.z + a.w * b.w;
    #pragma unroll
    for (int off = 16; off > 0; off >>= 1)
        p += __shfl_xor_sync(0xffffffffu, p, off);
    if (lane == 0)
        scores[wid] = p + bias[nids[s]] + bias[nids[d]];
}

__global__ void loss_kernel(const float* __restrict__ scores, float* __restrict__ out) {
    int i = blockIdx.x * blockDim.x + threadIdx.x;
    if (i < NP)
        out[i] = fmaxf(scores[NP + i] - scores[i] + 1.0f, 0.0f);
}

#define AUC_JCH 2048
__global__ __launch_bounds__(256)
void auc_count_kernel(const float* __restrict__ scores, unsigned int* __restrict__ R) {
    __shared__ float ss[AUC_JCH];
    int tid = threadIdx.x;
    int j0 = blockIdx.y * AUC_JCH;
    for (int j = tid; j < AUC_JCH; j += blockDim.x) ss[j] = scores[j0 + j];
    __syncthreads();
    int i = blockIdx.x * blockDim.x + tid;
    float my = scores[i];
    unsigned int cnt = 0;
    #pragma unroll 4
    for (int jj = 0; jj < AUC_JCH; jj++) {
        float v = ss[jj];
        int j = j0 + jj;
        cnt += (v < my) || (v == my && j < i);
    }
    #pragma unroll
    for (int off = 16; off > 0; off >>= 1)
        cnt += __shfl_xor_sync(0xffffffffu, cnt, off);
    if ((tid & 31) == 0) atomicAdd(R, cnt);
}

__global__ void auc_final_kernel(const unsigned int* __restrict__ R, float* __restrict__ out) {
    double r = (double)(*R);
    double npos = (double)NP, nneg = (double)NP;
    out[0] = (float)((r - npos * (npos - 1.0) * 0.5) / (npos * nneg));
}

// ---------------------------------------------------------------------------
// Launch
// ---------------------------------------------------------------------------
extern "C" void kernel_launch(void* const* d_in, const int* in_sizes, int n_in,
                              void* d_out, int out_size) {
    const int*   src0_id   = (const int*)  d_in[0];
    const int*   src0_cats = (const int*)  d_in[1];
    const float* src0_genre= (const float*)d_in[2];
    const int*   es0       = (const int*)  d_in[3];
    const int*   ed0       = (const int*)  d_in[4];
    const float* w0        = (const float*)d_in[5];
    const int*   es1       = (const int*)  d_in[6];
    const int*   ed1       = (const int*)  d_in[7];
    const float* w1        = (const float*)d_in[8];
    const int*   pos_src   = (const int*)  d_in[9];
    const int*   pos_dst   = (const int*)  d_in[10];
    const int*   neg_src   = (const int*)  d_in[11];
    const int*   neg_dst   = (const int*)  d_in[12];
    const int*   seed_nids = (const int*)  d_in[13];
    const float* track_emb = (const float*)d_in[14];
    const float* cat_embs  = (const float*)d_in[15];
    const float* fc_W      = (const float*)d_in[16];
    const float* fc_b      = (const float*)d_in[17];
    const float* Q0_W      = (const float*)d_in[18];
    const float* Q0_b      = (const float*)d_in[19];
    const float* W0_W      = (const float*)d_in[20];
    const float* W0_b      = (const float*)d_in[21];
    const float* Q1_W      = (const float*)d_in[22];
    const float* Q1_b      = (const float*)d_in[23];
    const float* W1_W      = (const float*)d_in[24];
    const float* W1_b      = (const float*)d_in[25];
    const float* bias      = (const float*)d_in[26];
    float* out = (float*)d_out;

    float *p_T, *p_h, *p_n, *p_agg0, *p_h1, *p_agg1, *p_hitem, *p_scores;
    int *p_c0, *p_c0b, *p_b0, *p_s0, *p_c1, *p_c1b, *p_b1, *p_s1;
    unsigned int* p_R;
    cudaGetSymbolAddress((void**)&p_T,     g_T);
    cudaGetSymbolAddress((void**)&p_h,     g_h);
    cudaGetSymbolAddress((void**)&p_n,     g_n);
    cudaGetSymbolAddress((void**)&p_agg0,  g_agg0);
    cudaGetSymbolAddress((void**)&p_h1,    g_h1);
    cudaGetSymbolAddress((void**)&p_agg1,  g_agg1);
    cudaGetSymbolAddress((void**)&p_hitem, g_hitem);
    cudaGetSymbolAddress((void**)&p_scores,g_scores);
    cudaGetSymbolAddress((void**)&p_R,     g_rank_sum);
    cudaGetSymbolAddress((void**)&p_c0,  g_cnt0);
    cudaGetSymbolAddress((void**)&p_c0b, g_cnt0b);
    cudaGetSymbolAddress((void**)&p_b0,  g_base0);
    cudaGetSymbolAddress((void**)&p_s0,  g_sorted0);
    cudaGetSymbolAddress((void**)&p_c1,  g_cnt1);
    cudaGetSymbolAddress((void**)&p_c1b, g_cnt1b);
    cudaGetSymbolAddress((void**)&p_b1,  g_base1);
    cudaGetSymbolAddress((void**)&p_s1,  g_sorted1);

    // ncu (-s 5 -c 1) lands on launch #6 = proj_kernel this round
    zero_all_kernel<<<128, 256>>>(p_c0, p_c0b, p_c1, p_c1b, p_R);                        // 1
    hist_kernel<<<512, 256>>>(ed0, p_c0, NE0);                                           // 2
    scan_kernel<<<1, 1024>>>(p_c0, p_b0, N_DST0);                                        // 3
    scatter_kernel<<<512, 256>>>(ed0, p_b0, p_c0b, p_s0, NE0);                           // 4
    precompute_T_kernel<<<N_CATS * CAT_VOCAB, 128>>>(cat_embs, fc_W, p_T);               // 5
    proj_kernel<<<N_SRC0 / (8 * ROWS_PER_WARP), 256>>>(src0_id, src0_cats, src0_genre,   // 6 (ncu)
                                                       p_T, fc_W, fc_b, track_emb, p_h);
    gemm_q_kernel<<<N_SRC0 / 128, 256>>>(p_h, Q0_W, Q0_b, p_n);                          // 7
    agg_sorted_kernel<<<N_DST0 / 8, 256>>>(p_n, es0, w0, p_s0, p_b0, p_agg0, N_DST0);    // 8
    gemm_wnorm_kernel<<<N_DST0 / 128, 256>>>(p_agg0, p_h, W0_W, W0_b, nullptr, p_h1);    // 9

    hist_kernel<<<128, 256>>>(ed1, p_c1, NE1);
    scan_kernel<<<1, 1024>>>(p_c1, p_b1, N_DST1);
    scatter_kernel<<<128, 256>>>(ed1, p_b1, p_c1b, p_s1, NE1);
    gemm_q_kernel<<<N_DST0 / 128, 256>>>(p_h1, Q1_W, Q1_b, p_n);
    agg_sorted_kernel<<<N_DST1 / 8, 256>>>(p_n, es1, w1, p_s1, p_b1, p_agg1, N_DST1);
    gemm_wnorm_kernel<<<N_DST1 / 128, 256>>>(p_agg1, p_h1, W1_W, W1_b, p_h, p_hitem);

    score_kernel<<<NS / 8, 256>>>(p_hitem, pos_src, pos_dst, neg_src, neg_dst,
                                  seed_nids, bias, p_scores);
    loss_kernel<<<NP / 256, 256>>>(p_scores, out);

    dim3 auc_grid(NP / 256, NS / AUC_JCH);
    auc_count_kernel<<<auc_grid, 256>>>(p_scores, p_R);
    if (out_size >= NP + 1)
        auc_final_kernel<<<1, 1>>>(p_R, out + NP);
}

// round 8
// speedup vs baseline: 1.3608x; 1.3070x over previous
#include <cuda_runtime.h>
#include <cuda_bf16.h>
#include <math.h>

// ---------------------------------------------------------------------------
// Problem constants
// ---------------------------------------------------------------------------
#define N_SRC0   262144
#define N_DST0   65536
#define N_DST1   8192
#define HID      128
#define N_CATS   9
#define CAT_VOCAB 101
#define CAT_DIM  16
#define GENRE_DIM 20
#define NE0      1048576
#define NE1      131072
#define NP       8192
#define NS       16384

// ---------------------------------------------------------------------------
// Static device scratch
// ---------------------------------------------------------------------------
__device__ float g_T[N_CATS * CAT_VOCAB * HID];
__device__ float g_h[(size_t)N_SRC0 * HID];
__device__ float g_n[(size_t)N_SRC0 * HID];
__device__ float g_agg0[(size_t)N_DST0 * HID];
__device__ float g_ws0[N_DST0];
__device__ float g_h1[(size_t)N_DST0 * HID];
__device__ float g_agg1[(size_t)N_DST1 * HID];
__device__ float g_ws1[N_DST1];
__device__ float g_hitem[(size_t)N_DST1 * HID];
__device__ float g_scores[NS];
__device__ unsigned int g_rank_sum;

// ---------------------------------------------------------------------------
// bf16 split helpers: x = hi + lo, each bf16; pack adjacent-k pairs in u32
// ---------------------------------------------------------------------------
__device__ __forceinline__ void pack_bf16(float x0, float x1, unsigned& hi, unsigned& lo) {
    unsigned hw;
    asm("cvt.rn.bf16x2.f32 %0, %1, %2;" : "=r"(hw) : "f"(x1), "f"(x0));  // low=x0, high=x1
    float h0 = __uint_as_float(hw << 16);
    float h1 = __uint_as_float(hw & 0xFFFF0000u);
    float r0 = x0 - h0;
    float r1 = x1 - h1;
    unsigned lw;
    asm("cvt.rn.bf16x2.f32 %0, %1, %2;" : "=r"(lw) : "f"(r1), "f"(r0));
    hi = hw; lo = lw;
}

__device__ __forceinline__ void mma_bf16(float* c, const unsigned* a, const unsigned* b) {
    asm volatile(
        "mma.sync.aligned.m16n8k16.row.col.f32.bf16.bf16.f32 "
        "{%0,%1,%2,%3}, {%4,%5,%6,%7}, {%8,%9}, {%0,%1,%2,%3};"
        : "+f"(c[0]), "+f"(c[1]), "+f"(c[2]), "+f"(c[3])
        : "r"(a[0]), "r"(a[1]), "r"(a[2]), "r"(a[3]), "r"(b[0]), "r"(b[1]));
}

// ---------------------------------------------------------------------------
// GEMM core: 128x128 block tile, K-step 16, 8 warps (4x2), warp tile 32x64.
// smem: bf16 hi/lo planes as u32 words (2 bf16 along k per word).
//   A plane: [row 0..127][8 words], row stride AW=9 u32 (conflict-free).
//   B plane: transposed [n 0..127][8 words], stride AW=9.
// 3 MMAs (hh, hl, lh) per position -> near-fp32 precision.
// ---------------------------------------------------------------------------
#define AW 9
#define PLANE (128 * AW)   // u32 per plane per buffer

__device__ __forceinline__ void tile_bf16(const unsigned* __restrict__ Ahi,
                                          const unsigned* __restrict__ Alo,
                                          const unsigned* __restrict__ Bhi,
                                          const unsigned* __restrict__ Blo,
                                          float acc[2][8][4],
                                          int g, int t, int warp_m, int warp_n) {
    unsigned ah[2][4], al[2][4];
    #pragma unroll
    for (int mi = 0; mi < 2; mi++) {
        int rb = warp_m * 32 + mi * 16 + g;
        ah[mi][0] = Ahi[rb * AW + t];
        ah[mi][1] = Ahi[(rb + 8) * AW + t];
        ah[mi][2] = Ahi[rb * AW + t + 4];
        ah[mi][3] = Ahi[(rb + 8) * AW + t + 4];
        al[mi][0] = Alo[rb * AW + t];
        al[mi][1] = Alo[(rb + 8) * AW + t];
        al[mi][2] = Alo[rb * AW + t + 4];
        al[mi][3] = Alo[(rb + 8) * AW + t + 4];
    }
    #pragma unroll
    for (int ni = 0; ni < 8; ni++) {
        int n0 = warp_n * 64 + ni * 8 + g;
        unsigned bh[2] = {Bhi[n0 * AW + t], Bhi[n0 * AW + t + 4]};
        unsigned bl[2] = {Blo[n0 * AW + t], Blo[n0 * AW + t + 4]};
        #pragma unroll
        for (int mi = 0; mi < 2; mi++) {
            mma_bf16(acc[mi][ni], ah[mi], bh);
            mma_bf16(acc[mi][ni], al[mi], bh);
            mma_bf16(acc[mi][ni], ah[mi], bl);
        }
    }
}

__device__ __forceinline__ void store8(unsigned* hi, unsigned* lo, float4 v0, float4 v1) {
    unsigned h, l;
    pack_bf16(v0.x, v0.y, h, l); hi[0] = h; lo[0] = l;
    pack_bf16(v0.z, v0.w, h, l); hi[1] = h; lo[1] = l;
    pack_bf16(v1.x, v1.y, h, l); hi[2] = h; lo[2] = l;
    pack_bf16(v1.z, v1.w, h, l); hi[3] = h; lo[3] = l;
}

// ---- Q GEMM: out = relu(A @ W + b), K = 128 --------------------------------
__global__ __launch_bounds__(256, 2)
void gemm_q_kernel(const float* __restrict__ A,
                   const float* __restrict__ W,
                   const float* __restrict__ bvec,
                   float* __restrict__ out) {
    __shared__ unsigned SA[2][2][PLANE];   // [buf][hi/lo]
    __shared__ unsigned SB[2][2][PLANE];

    const int K = 128;
    const int NIT = K / 16;
    int tid = threadIdx.x;
    int wid = tid >> 5, lane = tid & 31;
    int g = lane >> 2, t = lane & 3;
    int warp_m = wid & 3, warp_n = wid >> 2;
    int r0 = blockIdx.x * 128;

    int lr = tid >> 1;             // A row 0..127
    int lh = tid & 1;              // A k-half (0 or 1) -> k offset lh*8
    int bn = tid & 127;            // B n
    int bh2 = tid >> 7;            // B k-half

    float acc[2][8][4] = {};

    // prefetch tile 0
    float4 ra0 = *(const float4*)&A[(size_t)(r0 + lr) * K + lh * 8];
    float4 ra1 = *(const float4*)&A[(size_t)(r0 + lr) * K + lh * 8 + 4];
    float4 rb0, rb1;
    {
        const float* wp = &W[(bh2 * 8) * 128 + bn];
        rb0 = make_float4(wp[0], wp[128], wp[256], wp[384]);
        rb1 = make_float4(wp[512], wp[640], wp[768], wp[896]);
    }
    store8(&SA[0][0][lr * AW + lh * 4], &SA[0][1][lr * AW + lh * 4], ra0, ra1);
    store8(&SB[0][0][bn * AW + bh2 * 4], &SB[0][1][bn * AW + bh2 * 4], rb0, rb1);
    __syncthreads();

    for (int it = 0; it < NIT; it++) {
        if (it + 1 < NIT) {
            int k0 = (it + 1) * 16;
            ra0 = *(const float4*)&A[(size_t)(r0 + lr) * K + k0 + lh * 8];
            ra1 = *(const float4*)&A[(size_t)(r0 + lr) * K + k0 + lh * 8 + 4];
            const float* wp = &W[(k0 + bh2 * 8) * 128 + bn];
            rb0 = make_float4(wp[0], wp[128], wp[256], wp[384]);
            rb1 = make_float4(wp[512], wp[640], wp[768], wp[896]);
        }
        int cur = it & 1;
        tile_bf16(SA[cur][0], SA[cur][1], SB[cur][0], SB[cur][1],
                  acc, g, t, warp_m, warp_n);
        if (it + 1 < NIT) {
            int nb = (it + 1) & 1;
            store8(&SA[nb][0][lr * AW + lh * 4], &SA[nb][1][lr * AW + lh * 4], ra0, ra1);
            store8(&SB[nb][0][bn * AW + bh2 * 4], &SB[nb][1][bn * AW + bh2 * 4], rb0, rb1);
        }
        __syncthreads();
    }

    #pragma unroll
    for (int ni = 0; ni < 8; ni++) {
        int col = warp_n * 64 + ni * 8 + 2 * t;
        float2 bv = *(const float2*)&bvec[col];
        #pragma unroll
        for (int mi = 0; mi < 2; mi++) {
            int row0 = r0 + warp_m * 32 + mi * 16 + g;
            float2 o0, o1;
            o0.x = fmaxf(acc[mi][ni][0] + bv.x, 0.f);
            o0.y = fmaxf(acc[mi][ni][1] + bv.y, 0.f);
            o1.x = fmaxf(acc[mi][ni][2] + bv.x, 0.f);
            o1.y = fmaxf(acc[mi][ni][3] + bv.y, 0.f);
            *(float2*)&out[(size_t)row0 * 128 + col]       = o0;
            *(float2*)&out[(size_t)(row0 + 8) * 128 + col] = o1;
        }
    }
}

// ---- W GEMM + row L2-normalize (+ optional residual), K = 256 --------------
__global__ __launch_bounds__(256, 2)
void gemm_wnorm_kernel(const float* __restrict__ agg,
                       const float* __restrict__ ws,
                       const float* __restrict__ hdst,
                       const float* __restrict__ W,
                       const float* __restrict__ bvec,
                       const float* __restrict__ addsrc,
                       float* __restrict__ out) {
    __shared__ unsigned SA[2][2][PLANE];
    __shared__ unsigned SB[2][2][PLANE];
    __shared__ float Ss[128][2];

    const int K = 256;
    const int NIT = K / 16;
    int tid = threadIdx.x;
    int wid = tid >> 5, lane = tid & 31;
    int g = lane >> 2, t = lane & 3;
    int warp_m = wid & 3, warp_n = wid >> 2;
    int r0 = blockIdx.x * 128;

    int lr = tid >> 1;
    int lh = tid & 1;
    int bn = tid & 127;
    int bh2 = tid >> 7;

    float iw = 1.0f / fmaxf(ws[r0 + lr], 1.0f);

    float acc[2][8][4] = {};

    auto loadA = [&](int kg, float4& v0, float4& v1) {
        if (kg < 128) {
            v0 = *(const float4*)&agg[(size_t)(r0 + lr) * 128 + kg];
            v1 = *(const float4*)&agg[(size_t)(r0 + lr) * 128 + kg + 4];
            v0.x *= iw; v0.y *= iw; v0.z *= iw; v0.w *= iw;
            v1.x *= iw; v1.y *= iw; v1.z *= iw; v1.w *= iw;
        } else {
            v0 = *(const float4*)&hdst[(size_t)(r0 + lr) * 128 + (kg - 128)];
            v1 = *(const float4*)&hdst[(size_t)(r0 + lr) * 128 + (kg - 128) + 4];
        }
    };

    float4 ra0, ra1, rb0, rb1;
    loadA(lh * 8, ra0, ra1);
    {
        const float* wp = &W[(bh2 * 8) * 128 + bn];
        rb0 = make_float4(wp[0], wp[128], wp[256], wp[384]);
        rb1 = make_float4(wp[512], wp[640], wp[768], wp[896]);
    }
    store8(&SA[0][0][lr * AW + lh * 4], &SA[0][1][lr * AW + lh * 4], ra0, ra1);
    store8(&SB[0][0][bn * AW + bh2 * 4], &SB[0][1][bn * AW + bh2 * 4], rb0, rb1);
    __syncthreads();

    for (int it = 0; it < NIT; it++) {
        if (it + 1 < NIT) {
            int k0 = (it + 1) * 16;
            loadA(k0 + lh * 8, ra0, ra1);
            const float* wp = &W[(k0 + bh2 * 8) * 128 + bn];
            rb0 = make_float4(wp[0], wp[128], wp[256], wp[384]);
            rb1 = make_float4(wp[512], wp[640], wp[768], wp[896]);
        }
        int cur = it & 1;
        tile_bf16(SA[cur][0], SA[cur][1], SB[cur][0], SB[cur][1],
                  acc, g, t, warp_m, warp_n);
        if (it + 1 < NIT) {
            int nb = (it + 1) & 1;
            store8(&SA[nb][0][lr * AW + lh * 4], &SA[nb][1][lr * AW + lh * 4], ra0, ra1);
            store8(&SB[nb][0][bn * AW + bh2 * 4], &SB[nb][1][bn * AW + bh2 * 4], rb0, rb1);
        }
        __syncthreads();
    }

    float ssl[2][2] = {};
    #pragma unroll
    for (int ni = 0; ni < 8; ni++) {
        int col = warp_n * 64 + ni * 8 + 2 * t;
        float2 bv = *(const float2*)&bvec[col];
        #pragma unroll
        for (int mi = 0; mi < 2; mi++) {
            float z0 = fmaxf(acc[mi][ni][0] + bv.x, 0.f);
            float z1 = fmaxf(acc[mi][ni][1] + bv.y, 0.f);
            float z2 = fmaxf(acc[mi][ni][2] + bv.x, 0.f);
            float z3 = fmaxf(acc[mi][ni][3] + bv.y, 0.f);
            acc[mi][ni][0] = z0; acc[mi][ni][1] = z1;
            acc[mi][ni][2] = z2; acc[mi][ni][3] = z3;
            ssl[mi][0] += z0 * z0 + z1 * z1;
            ssl[mi][1] += z2 * z2 + z3 * z3;
        }
    }
    #pragma unroll
    for (int mi = 0; mi < 2; mi++)
        #pragma unroll
        for (int h = 0; h < 2; h++) {
            float s = ssl[mi][h];
            s += __shfl_xor_sync(0xffffffffu, s, 1);
            s += __shfl_xor_sync(0xffffffffu, s, 2);
            ssl[mi][h] = s;
        }
    if (t == 0) {
        #pragma unroll
        for (int mi = 0; mi < 2; mi++) {
            int r = warp_m * 32 + mi * 16 + g;
            Ss[r][warp_n]     = ssl[mi][0];
            Ss[r + 8][warp_n] = ssl[mi][1];
        }
    }
    __syncthreads();
    #pragma unroll
    for (int mi = 0; mi < 2; mi++) {
        int rl0 = warp_m * 32 + mi * 16 + g;
        float ss0 = Ss[rl0][0] + Ss[rl0][1];
        float ss1 = Ss[rl0 + 8][0] + Ss[rl0 + 8][1];
        float in0 = (ss0 > 0.f) ? rsqrtf(ss0) : 1.0f;
        float in1 = (ss1 > 0.f) ? rsqrtf(ss1) : 1.0f;
        size_t row0 = (size_t)(r0 + rl0);
        #pragma unroll
        for (int ni = 0; ni < 8; ni++) {
            int col = warp_n * 64 + ni * 8 + 2 * t;
            float2 o0, o1;
            o0.x = acc[mi][ni][0] * in0; o0.y = acc[mi][ni][1] * in0;
            o1.x = acc[mi][ni][2] * in1; o1.y = acc[mi][ni][3] * in1;
            if (addsrc) {
                float2 a0 = *(const float2*)&addsrc[row0 * 128 + col];
                float2 a1 = *(const float2*)&addsrc[(row0 + 8) * 128 + col];
                o0.x += a0.x; o0.y += a0.y;
                o1.x += a1.x; o1.y += a1.y;
            }
            *(float2*)&out[row0 * 128 + col]       = o0;
            *(float2*)&out[(row0 + 8) * 128 + col] = o1;
        }
    }
}

// ---------------------------------------------------------------------------
// Precompute T[c,v,:] = cat_embs[c,v,:] @ fc_W[16c:16c+16, :]
// ---------------------------------------------------------------------------
__global__ void precompute_T_kernel(const float* __restrict__ cat_embs,
                                    const float* __restrict__ fcW,
                                    float* __restrict__ T) {
    int cv = blockIdx.x;
    int c = cv / CAT_VOCAB;
    int n = threadIdx.x;
    const float* e = &cat_embs[cv * CAT_DIM];
    float acc = 0.f;
    #pragma unroll
    for (int d = 0; d < CAT_DIM; d++)
        acc += __ldg(&e[d]) * fcW[(c * CAT_DIM + d) * HID + n];
    T[cv * HID + n] = acc;
}

// ---------------------------------------------------------------------------
// proj (also zeroes all accumulators — removes standalone zero launches)
// ---------------------------------------------------------------------------
#define ROWS_PER_WARP 16
__global__ __launch_bounds__(256)
void proj_kernel(const int* __restrict__ ids,
                 const int* __restrict__ cats,
                 const float* __restrict__ genre,
                 const float* __restrict__ T,
                 const float* __restrict__ fcW,
                 const float* __restrict__ fcb,
                 const float* __restrict__ track_emb,
                 float* __restrict__ out,
                 float* __restrict__ agg0, float* __restrict__ ws0,
                 float* __restrict__ agg1, float* __restrict__ ws1,
                 unsigned int* __restrict__ R) {
    // zero duty (grid-stride)
    {
        int i = blockIdx.x * blockDim.x + threadIdx.x;
        int st = gridDim.x * blockDim.x;
        float4 z = {0.f, 0.f, 0.f, 0.f};
        for (int j = i; j < N_DST0 * HID / 4; j += st) ((float4*)agg0)[j] = z;
        for (int j = i; j < N_DST1 * HID / 4; j += st) ((float4*)agg1)[j] = z;
        for (int j = i; j < N_DST0; j += st) ws0[j] = 0.f;
        for (int j = i; j < N_DST1; j += st) ws1[j] = 0.f;
        if (i == 0) *R = 0u;
    }

    int warp = threadIdx.x >> 5, lane = threadIdx.x & 31;
    float4 Wg[GENRE_DIM];
    #pragma unroll
    for (int g = 0; g < GENRE_DIM; g++)
        Wg[g] = *(const float4*)&fcW[(144 + g) * HID + lane * 4];
    float4 bb = *(const float4*)&fcb[lane * 4];

    int rbase = (blockIdx.x * 8 + warp) * ROWS_PER_WARP;
    for (int rr = 0; rr < ROWS_PER_WARP; rr++) {
        int r = rbase + rr;
        int myc = (lane < N_CATS) ? cats[r * N_CATS + lane] : 0;
        float gv = (lane < GENRE_DIM) ? genre[(size_t)r * GENRE_DIM + lane] : 0.f;
        int id = ids[r];
        float4 acc = bb;
        #pragma unroll
        for (int c = 0; c < N_CATS; c++) {
            int v = __shfl_sync(0xffffffffu, myc, c);
            float4 t = *(const float4*)&T[(c * CAT_VOCAB + v) * HID + lane * 4];
            acc.x += t.x; acc.y += t.y; acc.z += t.z; acc.w += t.w;
        }
        #pragma unroll
        for (int g = 0; g < GENRE_DIM; g++) {
            float s = __shfl_sync(0xffffffffu, gv, g);
            acc.x += s * Wg[g].x; acc.y += s * Wg[g].y;
            acc.z += s * Wg[g].z; acc.w += s * Wg[g].w;
        }
        float4 te = *(const float4*)&track_emb[(size_t)id * HID + lane * 4];
        acc.x += te.x; acc.y += te.y; acc.z += te.z; acc.w += te.w;
        *(float4*)&out[(size_t)r * HID + lane * 4] = acc;
    }
}

// ---------------------------------------------------------------------------
// Edge aggregation: red.global.add.v4.f32 (sm_90+), 1 warp / edge
// ---------------------------------------------------------------------------
__global__ __launch_bounds__(256)
void edge_agg_kernel(const float* __restrict__ nmat,
                     const int* __restrict__ es,
                     const int* __restrict__ ed,
                     const float* __restrict__ w,
                     float* __restrict__ agg,
                     float* __restrict__ ws,
                     int nE) {
    int wid = (blockIdx.x * blockDim.x + threadIdx.x) >> 5;
    int lane = threadIdx.x & 31;
    if (wid >= nE) return;
    int s = __ldg(&es[wid]);
    int d = __ldg(&ed[wid]);
    float wt = __ldg(&w[wid]);
    float4 v = *(const float4*)&nmat[(size_t)s * 128 + lane * 4];
    float* dst = &agg[(size_t)d * 128 + lane * 4];
#if !defined(__CUDA_ARCH__) || __CUDA_ARCH__ >= 900
    asm volatile("red.global.add.v4.f32 [%0], {%1,%2,%3,%4};"
                 :: "l"(dst), "f"(v.x * wt), "f"(v.y * wt), "f"(v.z * wt), "f"(v.w * wt)
                 : "memory");
#else
    atomicAdd(dst + 0, v.x * wt);
    atomicAdd(dst + 1, v.y * wt);
    atomicAdd(dst + 2, v.z * wt);
    atomicAdd(dst + 3, v.w * wt);
#endif
    if (lane == 0) atomicAdd(&ws[d], wt);
}

// ---------------------------------------------------------------------------
// Scores / loss / AUC
// ---------------------------------------------------------------------------
__global__ __launch_bounds__(256)
void score_kernel(const float* __restrict__ hi,
                  const int* __restrict__ ps, const int* __restrict__ pd,
                  const int* __restrict__ ns, const int* __restrict__ nd,
                  const int* __restrict__ nids,
                  const float* __restrict__ bias,
                  float* __restrict__ scores) {
    int wid = (blockIdx.x * blockDim.x + threadIdx.x) >> 5;
    int lane = threadIdx.x & 31;
    if (wid >= NS) return;
    int s, d;
    if (wid < NP) { s = ps[wid]; d = pd[wid]; }
    else          { s = ns[wid - NP]; d = nd[wid - NP]; }
    float4 a = *(const float4*)&hi[(size_t)s * 128 + lane * 4];
    float4 b = *(const float4*)&hi[(size_t)d * 128 + lane * 4];
    float p = a.x * b.x + a.y * b.y + a.z * b.z + a.w * b.w;
    #pragma unroll
    for (int off = 16; off > 0; off >>= 1)
        p += __shfl_xor_sync(0xffffffffu, p, off);
    if (lane == 0)
        scores[wid] = p + bias[nids[s]] + bias[nids[d]];
}

__global__ void loss_kernel(const float* __restrict__ scores, float* __restrict__ out) {
    int i = blockIdx.x * blockDim.x + threadIdx.x;
    if (i < NP)
        out[i] = fmaxf(scores[NP + i] - scores[i] + 1.0f, 0.0f);
}

#define AUC_JCH 2048
__global__ __launch_bounds__(256)
void auc_count_kernel(const float* __restrict__ scores, unsigned int* __restrict__ R) {
    __shared__ float ss[AUC_JCH];
    int tid = threadIdx.x;
    int j0 = blockIdx.y * AUC_JCH;
    for (int j = tid; j < AUC_JCH; j += blockDim.x) ss[j] = scores[j0 + j];
    __syncthreads();
    int i = blockIdx.x * blockDim.x + tid;
    float my = scores[i];
    unsigned int cnt = 0;
    #pragma unroll 4
    for (int jj = 0; jj < AUC_JCH; jj++) {
        float v = ss[jj];
        int j = j0 + jj;
        cnt += (v < my) || (v == my && j < i);
    }
    #pragma unroll
    for (int off = 16; off > 0; off >>= 1)
        cnt += __shfl_xor_sync(0xffffffffu, cnt, off);
    if ((tid & 31) == 0) atomicAdd(R, cnt);
}

__global__ void auc_final_kernel(const unsigned int* __restrict__ R, float* __restrict__ out) {
    double r = (double)(*R);
    double npos = (double)NP, nneg = (double)NP;
    out[0] = (float)((r - npos * (npos - 1.0) * 0.5) / (npos * nneg));
}

// ---------------------------------------------------------------------------
// Launch
// ---------------------------------------------------------------------------
extern "C" void kernel_launch(void* const* d_in, const int* in_sizes, int n_in,
                              void* d_out, int out_size) {
    const int*   src0_id   = (const int*)  d_in[0];
    const int*   src0_cats = (const int*)  d_in[1];
    const float* src0_genre= (const float*)d_in[2];
    const int*   es0       = (const int*)  d_in[3];
    const int*   ed0       = (const int*)  d_in[4];
    const float* w0        = (const float*)d_in[5];
    const int*   es1       = (const int*)  d_in[6];
    const int*   ed1       = (const int*)  d_in[7];
    const float* w1        = (const float*)d_in[8];
    const int*   pos_src   = (const int*)  d_in[9];
    const int*   pos_dst   = (const int*)  d_in[10];
    const int*   neg_src   = (const int*)  d_in[11];
    const int*   neg_dst   = (const int*)  d_in[12];
    const int*   seed_nids = (const int*)  d_in[13];
    const float* track_emb = (const float*)d_in[14];
    const float* cat_embs  = (const float*)d_in[15];
    const float* fc_W      = (const float*)d_in[16];
    const float* fc_b      = (const float*)d_in[17];
    const float* Q0_W      = (const float*)d_in[18];
    const float* Q0_b      = (const float*)d_in[19];
    const float* W0_W      = (const float*)d_in[20];
    const float* W0_b      = (const float*)d_in[21];
    const float* Q1_W      = (const float*)d_in[22];
    const float* Q1_b      = (const float*)d_in[23];
    const float* W1_W      = (const float*)d_in[24];
    const float* W1_b      = (const float*)d_in[25];
    const float* bias      = (const float*)d_in[26];
    float* out = (float*)d_out;

    float *p_T, *p_h, *p_n, *p_agg0, *p_ws0, *p_h1, *p_agg1, *p_ws1, *p_hitem, *p_scores;
    unsigned int* p_R;
    cudaGetSymbolAddress((void**)&p_T,     g_T);
    cudaGetSymbolAddress((void**)&p_h,     g_h);
    cudaGetSymbolAddress((void**)&p_n,     g_n);
    cudaGetSymbolAddress((void**)&p_agg0,  g_agg0);
    cudaGetSymbolAddress((void**)&p_ws0,   g_ws0);
    cudaGetSymbolAddress((void**)&p_h1,    g_h1);
    cudaGetSymbolAddress((void**)&p_agg1,  g_agg1);
    cudaGetSymbolAddress((void**)&p_ws1,   g_ws1);
    cudaGetSymbolAddress((void**)&p_hitem, g_hitem);
    cudaGetSymbolAddress((void**)&p_scores,g_scores);
    cudaGetSymbolAddress((void**)&p_R,     g_rank_sum);

    // ncu profiles launch #4 (observed R3/R4/R6) -> edge_agg0 this round
    precompute_T_kernel<<<N_CATS * CAT_VOCAB, 128>>>(cat_embs, fc_W, p_T);               // 1
    proj_kernel<<<N_SRC0 / (8 * ROWS_PER_WARP), 256>>>(src0_id, src0_cats, src0_genre,   // 2
                                                       p_T, fc_W, fc_b, track_emb, p_h,
                                                       p_agg0, p_ws0, p_agg1, p_ws1, p_R);
    gemm_q_kernel<<<N_SRC0 / 128, 256>>>(p_h, Q0_W, Q0_b, p_n);                          // 3
    edge_agg_kernel<<<NE0 / 8, 256>>>(p_n, es0, ed0, w0, p_agg0, p_ws0, NE0);            // 4 (ncu)
    gemm_wnorm_kernel<<<N_DST0 / 128, 256>>>(p_agg0, p_ws0, p_h, W0_W, W0_b,             // 5
                                             nullptr, p_h1);
    gemm_q_kernel<<<N_DST0 / 128, 256>>>(p_h1, Q1_W, Q1_b, p_n);                         // 6
    edge_agg_kernel<<<NE1 / 8, 256>>>(p_n, es1, ed1, w1, p_agg1, p_ws1, NE1);            // 7
    gemm_wnorm_kernel<<<N_DST1 / 128, 256>>>(p_agg1, p_ws1, p_h1, W1_W, W1_b,            // 8
                                             p_h, p_hitem);

    score_kernel<<<NS / 8, 256>>>(p_hitem, pos_src, pos_dst, neg_src, neg_dst,
                                  seed_nids, bias, p_scores);
    loss_kernel<<<NP / 256, 256>>>(p_scores, out);

    dim3 auc_grid(NP / 256, NS / AUC_JCH);
    auc_count_kernel<<<auc_grid, 256>>>(p_scores, p_R);
    if (out_size >= NP + 1)
        auc_final_kernel<<<1, 1>>>(p_R, out + NP);
}

// round 9
// speedup vs baseline: 1.4517x; 1.0668x over previous
#include <cuda_runtime.h>
#include <cuda_bf16.h>
#include <math.h>

// ---------------------------------------------------------------------------
// Problem constants
// ---------------------------------------------------------------------------
#define N_SRC0   262144
#define N_DST0   65536
#define N_DST1   8192
#define HID      128
#define N_CATS   9
#define CAT_VOCAB 101
#define CAT_DIM  16
#define GENRE_DIM 20
#define NE0      1048576
#define NE1      131072
#define NP       8192
#define NS       16384

// ---------------------------------------------------------------------------
// Static device scratch
// ---------------------------------------------------------------------------
__device__ float g_T[N_CATS * CAT_VOCAB * HID];
__device__ float g_h[(size_t)N_SRC0 * HID];
__device__ float g_n[(size_t)N_SRC0 * HID];
__device__ float g_agg0[(size_t)N_DST0 * HID];
__device__ float g_ws0[N_DST0];
__device__ float g_h1[(size_t)N_DST0 * HID];
__device__ float g_agg1[(size_t)N_DST1 * HID];
__device__ float g_ws1[N_DST1];
__device__ float g_hitem[(size_t)N_DST1 * HID];
__device__ float g_scores[NS];
__device__ unsigned int g_rank_sum;

// ---------------------------------------------------------------------------
// bf16 split helpers: x = hi + lo, each bf16; pack adjacent-k pairs in u32
// ---------------------------------------------------------------------------
__device__ __forceinline__ void pack_bf16(float x0, float x1, unsigned& hi, unsigned& lo) {
    unsigned hw;
    asm("cvt.rn.bf16x2.f32 %0, %1, %2;" : "=r"(hw) : "f"(x1), "f"(x0));  // low=x0, high=x1
    float h0 = __uint_as_float(hw << 16);
    float h1 = __uint_as_float(hw & 0xFFFF0000u);
    float r0 = x0 - h0;
    float r1 = x1 - h1;
    unsigned lw;
    asm("cvt.rn.bf16x2.f32 %0, %1, %2;" : "=r"(lw) : "f"(r1), "f"(r0));
    hi = hw; lo = lw;
}

__device__ __forceinline__ void mma_bf16(float* c, const unsigned* a, const unsigned* b) {
    asm volatile(
        "mma.sync.aligned.m16n8k16.row.col.f32.bf16.bf16.f32 "
        "{%0,%1,%2,%3}, {%4,%5,%6,%7}, {%8,%9}, {%0,%1,%2,%3};"
        : "+f"(c[0]), "+f"(c[1]), "+f"(c[2]), "+f"(c[3])
        : "r"(a[0]), "r"(a[1]), "r"(a[2]), "r"(a[3]), "r"(b[0]), "r"(b[1]));
}

// ---------------------------------------------------------------------------
// GEMM core: 128x128 block tile, K-step 16, 8 warps (4x2), warp tile 32x64.
// smem: bf16 hi/lo planes as u32 words (2 bf16 along k per word).
//   A plane: [row 0..127][8 words], row stride AW=9 u32 (conflict-free).
//   B plane: transposed [n 0..127][8 words], stride AW=9.
// 3 MMAs (hh, hl, lh) per position -> near-fp32 precision.
// ---------------------------------------------------------------------------
#define AW 9
#define PLANE (128 * AW)   // u32 per plane per buffer

__device__ __forceinline__ void tile_bf16(const unsigned* __restrict__ Ahi,
                                          const unsigned* __restrict__ Alo,
                                          const unsigned* __restrict__ Bhi,
                                          const unsigned* __restrict__ Blo,
                                          float acc[2][8][4],
                                          int g, int t, int warp_m, int warp_n) {
    unsigned ah[2][4], al[2][4];
    #pragma unroll
    for (int mi = 0; mi < 2; mi++) {
        int rb = warp_m * 32 + mi * 16 + g;
        ah[mi][0] = Ahi[rb * AW + t];
        ah[mi][1] = Ahi[(rb + 8) * AW + t];
        ah[mi][2] = Ahi[rb * AW + t + 4];
        ah[mi][3] = Ahi[(rb + 8) * AW + t + 4];
        al[mi][0] = Alo[rb * AW + t];
        al[mi][1] = Alo[(rb + 8) * AW + t];
        al[mi][2] = Alo[rb * AW + t + 4];
        al[mi][3] = Alo[(rb + 8) * AW + t + 4];
    }
    #pragma unroll
    for (int ni = 0; ni < 8; ni++) {
        int n0 = warp_n * 64 + ni * 8 + g;
        unsigned bh[2] = {Bhi[n0 * AW + t], Bhi[n0 * AW + t + 4]};
        unsigned bl[2] = {Blo[n0 * AW + t], Blo[n0 * AW + t + 4]};
        #pragma unroll
        for (int mi = 0; mi < 2; mi++) {
            mma_bf16(acc[mi][ni], ah[mi], bh);
            mma_bf16(acc[mi][ni], al[mi], bh);
            mma_bf16(acc[mi][ni], ah[mi], bl);
        }
    }
}

__device__ __forceinline__ void store8(unsigned* hi, unsigned* lo, float4 v0, float4 v1) {
    unsigned h, l;
    pack_bf16(v0.x, v0.y, h, l); hi[0] = h; lo[0] = l;
    pack_bf16(v0.z, v0.w, h, l); hi[1] = h; lo[1] = l;
    pack_bf16(v1.x, v1.y, h, l); hi[2] = h; lo[2] = l;
    pack_bf16(v1.z, v1.w, h, l); hi[3] = h; lo[3] = l;
}

// ---- Q GEMM: out = relu(A @ W + b), K = 128 --------------------------------
__global__ __launch_bounds__(256, 2)
void gemm_q_kernel(const float* __restrict__ A,
                   const float* __restrict__ W,
                   const float* __restrict__ bvec,
                   float* __restrict__ out) {
    __shared__ unsigned SA[2][2][PLANE];   // [buf][hi/lo]
    __shared__ unsigned SB[2][2][PLANE];

    const int K = 128;
    const int NIT = K / 16;
    int tid = threadIdx.x;
    int wid = tid >> 5, lane = tid & 31;
    int g = lane >> 2, t = lane & 3;
    int warp_m = wid & 3, warp_n = wid >> 2;
    int r0 = blockIdx.x * 128;

    int lr = tid >> 1;             // A row 0..127
    int lh = tid & 1;              // A k-half (0 or 1) -> k offset lh*8
    int bn = tid & 127;            // B n
    int bh2 = tid >> 7;            // B k-half

    float acc[2][8][4] = {};

    // prefetch tile 0
    float4 ra0 = *(const float4*)&A[(size_t)(r0 + lr) * K + lh * 8];
    float4 ra1 = *(const float4*)&A[(size_t)(r0 + lr) * K + lh * 8 + 4];
    float4 rb0, rb1;
    {
        const float* wp = &W[(bh2 * 8) * 128 + bn];
        rb0 = make_float4(wp[0], wp[128], wp[256], wp[384]);
        rb1 = make_float4(wp[512], wp[640], wp[768], wp[896]);
    }
    store8(&SA[0][0][lr * AW + lh * 4], &SA[0][1][lr * AW + lh * 4], ra0, ra1);
    store8(&SB[0][0][bn * AW + bh2 * 4], &SB[0][1][bn * AW + bh2 * 4], rb0, rb1);
    __syncthreads();

    for (int it = 0; it < NIT; it++) {
        if (it + 1 < NIT) {
            int k0 = (it + 1) * 16;
            ra0 = *(const float4*)&A[(size_t)(r0 + lr) * K + k0 + lh * 8];
            ra1 = *(const float4*)&A[(size_t)(r0 + lr) * K + k0 + lh * 8 + 4];
            const float* wp = &W[(k0 + bh2 * 8) * 128 + bn];
            rb0 = make_float4(wp[0], wp[128], wp[256], wp[384]);
            rb1 = make_float4(wp[512], wp[640], wp[768], wp[896]);
        }
        int cur = it & 1;
        tile_bf16(SA[cur][0], SA[cur][1], SB[cur][0], SB[cur][1],
                  acc, g, t, warp_m, warp_n);
        if (it + 1 < NIT) {
            int nb = (it + 1) & 1;
            store8(&SA[nb][0][lr * AW + lh * 4], &SA[nb][1][lr * AW + lh * 4], ra0, ra1);
            store8(&SB[nb][0][bn * AW + bh2 * 4], &SB[nb][1][bn * AW + bh2 * 4], rb0, rb1);
        }
        __syncthreads();
    }

    #pragma unroll
    for (int ni = 0; ni < 8; ni++) {
        int col = warp_n * 64 + ni * 8 + 2 * t;
        float2 bv = *(const float2*)&bvec[col];
        #pragma unroll
        for (int mi = 0; mi < 2; mi++) {
            int row0 = r0 + warp_m * 32 + mi * 16 + g;
            float2 o0, o1;
            o0.x = fmaxf(acc[mi][ni][0] + bv.x, 0.f);
            o0.y = fmaxf(acc[mi][ni][1] + bv.y, 0.f);
            o1.x = fmaxf(acc[mi][ni][2] + bv.x, 0.f);
            o1.y = fmaxf(acc[mi][ni][3] + bv.y, 0.f);
            *(float2*)&out[(size_t)row0 * 128 + col]       = o0;
            *(float2*)&out[(size_t)(row0 + 8) * 128 + col] = o1;
        }
    }
}

// ---- W GEMM + row L2-normalize (+ optional residual), K = 256 --------------
__global__ __launch_bounds__(256, 2)
void gemm_wnorm_kernel(const float* __restrict__ agg,
                       const float* __restrict__ ws,
                       const float* __restrict__ hdst,
                       const float* __restrict__ W,
                       const float* __restrict__ bvec,
                       const float* __restrict__ addsrc,
                       float* __restrict__ out) {
    __shared__ unsigned SA[2][2][PLANE];
    __shared__ unsigned SB[2][2][PLANE];
    __shared__ float Ss[128][2];

    const int K = 256;
    const int NIT = K / 16;
    int tid = threadIdx.x;
    int wid = tid >> 5, lane = tid & 31;
    int g = lane >> 2, t = lane & 3;
    int warp_m = wid & 3, warp_n = wid >> 2;
    int r0 = blockIdx.x * 128;

    int lr = tid >> 1;
    int lh = tid & 1;
    int bn = tid & 127;
    int bh2 = tid >> 7;

    float iw = 1.0f / fmaxf(ws[r0 + lr], 1.0f);

    float acc[2][8][4] = {};

    auto loadA = [&](int kg, float4& v0, float4& v1) {
        if (kg < 128) {
            v0 = *(const float4*)&agg[(size_t)(r0 + lr) * 128 + kg];
            v1 = *(const float4*)&agg[(size_t)(r0 + lr) * 128 + kg + 4];
            v0.x *= iw; v0.y *= iw; v0.z *= iw; v0.w *= iw;
            v1.x *= iw; v1.y *= iw; v1.z *= iw; v1.w *= iw;
        } else {
            v0 = *(const float4*)&hdst[(size_t)(r0 + lr) * 128 + (kg - 128)];
            v1 = *(const float4*)&hdst[(size_t)(r0 + lr) * 128 + (kg - 128) + 4];
        }
    };

    float4 ra0, ra1, rb0, rb1;
    loadA(lh * 8, ra0, ra1);
    {
        const float* wp = &W[(bh2 * 8) * 128 + bn];
        rb0 = make_float4(wp[0], wp[128], wp[256], wp[384]);
        rb1 = make_float4(wp[512], wp[640], wp[768], wp[896]);
    }
    store8(&SA[0][0][lr * AW + lh * 4], &SA[0][1][lr * AW + lh * 4], ra0, ra1);
    store8(&SB[0][0][bn * AW + bh2 * 4], &SB[0][1][bn * AW + bh2 * 4], rb0, rb1);
    __syncthreads();

    for (int it = 0; it < NIT; it++) {
        if (it + 1 < NIT) {
            int k0 = (it + 1) * 16;
            loadA(k0 + lh * 8, ra0, ra1);
            const float* wp = &W[(k0 + bh2 * 8) * 128 + bn];
            rb0 = make_float4(wp[0], wp[128], wp[256], wp[384]);
            rb1 = make_float4(wp[512], wp[640], wp[768], wp[896]);
        }
        int cur = it & 1;
        tile_bf16(SA[cur][0], SA[cur][1], SB[cur][0], SB[cur][1],
                  acc, g, t, warp_m, warp_n);
        if (it + 1 < NIT) {
            int nb = (it + 1) & 1;
            store8(&SA[nb][0][lr * AW + lh * 4], &SA[nb][1][lr * AW + lh * 4], ra0, ra1);
            store8(&SB[nb][0][bn * AW + bh2 * 4], &SB[nb][1][bn * AW + bh2 * 4], rb0, rb1);
        }
        __syncthreads();
    }

    float ssl[2][2] = {};
    #pragma unroll
    for (int ni = 0; ni < 8; ni++) {
        int col = warp_n * 64 + ni * 8 + 2 * t;
        float2 bv = *(const float2*)&bvec[col];
        #pragma unroll
        for (int mi = 0; mi < 2; mi++) {
            float z0 = fmaxf(acc[mi][ni][0] + bv.x, 0.f);
            float z1 = fmaxf(acc[mi][ni][1] + bv.y, 0.f);
            float z2 = fmaxf(acc[mi][ni][2] + bv.x, 0.f);
            float z3 = fmaxf(acc[mi][ni][3] + bv.y, 0.f);
            acc[mi][ni][0] = z0; acc[mi][ni][1] = z1;
            acc[mi][ni][2] = z2; acc[mi][ni][3] = z3;
            ssl[mi][0] += z0 * z0 + z1 * z1;
            ssl[mi][1] += z2 * z2 + z3 * z3;
        }
    }
    #pragma unroll
    for (int mi = 0; mi < 2; mi++)
        #pragma unroll
        for (int h = 0; h < 2; h++) {
            float s = ssl[mi][h];
            s += __shfl_xor_sync(0xffffffffu, s, 1);
            s += __shfl_xor_sync(0xffffffffu, s, 2);
            ssl[mi][h] = s;
        }
    if (t == 0) {
        #pragma unroll
        for (int mi = 0; mi < 2; mi++) {
            int r = warp_m * 32 + mi * 16 + g;
            Ss[r][warp_n]     = ssl[mi][0];
            Ss[r + 8][warp_n] = ssl[mi][1];
        }
    }
    __syncthreads();
    #pragma unroll
    for (int mi = 0; mi < 2; mi++) {
        int rl0 = warp_m * 32 + mi * 16 + g;
        float ss0 = Ss[rl0][0] + Ss[rl0][1];
        float ss1 = Ss[rl0 + 8][0] + Ss[rl0 + 8][1];
        float in0 = (ss0 > 0.f) ? rsqrtf(ss0) : 1.0f;
        float in1 = (ss1 > 0.f) ? rsqrtf(ss1) : 1.0f;
        size_t row0 = (size_t)(r0 + rl0);
        #pragma unroll
        for (int ni = 0; ni < 8; ni++) {
            int col = warp_n * 64 + ni * 8 + 2 * t;
            float2 o0, o1;
            o0.x = acc[mi][ni][0] * in0; o0.y = acc[mi][ni][1] * in0;
            o1.x = acc[mi][ni][2] * in1; o1.y = acc[mi][ni][3] * in1;
            if (addsrc) {
                float2 a0 = *(const float2*)&addsrc[row0 * 128 + col];
                float2 a1 = *(const float2*)&addsrc[(row0 + 8) * 128 + col];
                o0.x += a0.x; o0.y += a0.y;
                o1.x += a1.x; o1.y += a1.y;
            }
            *(float2*)&out[row0 * 128 + col]       = o0;
            *(float2*)&out[(row0 + 8) * 128 + col] = o1;
        }
    }
}

// ---------------------------------------------------------------------------
// Precompute T[c,v,:] = cat_embs[c,v,:] @ fc_W[16c:16c+16, :]
// ---------------------------------------------------------------------------
__global__ void precompute_T_kernel(const float* __restrict__ cat_embs,
                                    const float* __restrict__ fcW,
                                    float* __restrict__ T) {
    int cv = blockIdx.x;
    int c = cv / CAT_VOCAB;
    int n = threadIdx.x;
    const float* e = &cat_embs[cv * CAT_DIM];
    float acc = 0.f;
    #pragma unroll
    for (int d = 0; d < CAT_DIM; d++)
        acc += __ldg(&e[d]) * fcW[(c * CAT_DIM + d) * HID + n];
    T[cv * HID + n] = acc;
}

__global__ void zero_R_kernel(unsigned int* R) { *R = 0u; }

// ---------------------------------------------------------------------------
// proj (also zeroes the edge accumulators)
// ---------------------------------------------------------------------------
#define ROWS_PER_WARP 16
__global__ __launch_bounds__(256)
void proj_kernel(const int* __restrict__ ids,
                 const int* __restrict__ cats,
                 const float* __restrict__ genre,
                 const float* __restrict__ T,
                 const float* __restrict__ fcW,
                 const float* __restrict__ fcb,
                 const float* __restrict__ track_emb,
                 float* __restrict__ out,
                 float* __restrict__ agg0, float* __restrict__ ws0,
                 float* __restrict__ agg1, float* __restrict__ ws1) {
    // zero duty (grid-stride)
    {
        int i = blockIdx.x * blockDim.x + threadIdx.x;
        int st = gridDim.x * blockDim.x;
        float4 z = {0.f, 0.f, 0.f, 0.f};
        for (int j = i; j < N_DST0 * HID / 4; j += st) ((float4*)agg0)[j] = z;
        for (int j = i; j < N_DST1 * HID / 4; j += st) ((float4*)agg1)[j] = z;
        for (int j = i; j < N_DST0; j += st) ws0[j] = 0.f;
        for (int j = i; j < N_DST1; j += st) ws1[j] = 0.f;
    }

    int warp = threadIdx.x >> 5, lane = threadIdx.x & 31;
    float4 Wg[GENRE_DIM];
    #pragma unroll
    for (int g = 0; g < GENRE_DIM; g++)
        Wg[g] = *(const float4*)&fcW[(144 + g) * HID + lane * 4];
    float4 bb = *(const float4*)&fcb[lane * 4];

    int rbase = (blockIdx.x * 8 + warp) * ROWS_PER_WARP;
    for (int rr = 0; rr < ROWS_PER_WARP; rr++) {
        int r = rbase + rr;
        int myc = (lane < N_CATS) ? cats[r * N_CATS + lane] : 0;
        float gv = (lane < GENRE_DIM) ? genre[(size_t)r * GENRE_DIM + lane] : 0.f;
        int id = ids[r];
        float4 acc = bb;
        #pragma unroll
        for (int c = 0; c < N_CATS; c++) {
            int v = __shfl_sync(0xffffffffu, myc, c);
            float4 t = *(const float4*)&T[(c * CAT_VOCAB + v) * HID + lane * 4];
            acc.x += t.x; acc.y += t.y; acc.z += t.z; acc.w += t.w;
        }
        #pragma unroll
        for (int g = 0; g < GENRE_DIM; g++) {
            float s = __shfl_sync(0xffffffffu, gv, g);
            acc.x += s * Wg[g].x; acc.y += s * Wg[g].y;
            acc.z += s * Wg[g].z; acc.w += s * Wg[g].w;
        }
        float4 te = *(const float4*)&track_emb[(size_t)id * HID + lane * 4];
        acc.x += te.x; acc.y += te.y; acc.z += te.z; acc.w += te.w;
        *(float4*)&out[(size_t)r * HID + lane * 4] = acc;
    }
}

// ---------------------------------------------------------------------------
// Edge aggregation: 4 edges per warp, batched phases for MLP
// ---------------------------------------------------------------------------
#define EPW 4
__global__ __launch_bounds__(256)
void edge_agg_kernel(const float* __restrict__ nmat,
                     const int* __restrict__ es,
                     const int* __restrict__ ed,
                     const float* __restrict__ w,
                     float* __restrict__ agg,
                     float* __restrict__ ws,
                     int nE) {
    int warp = (blockIdx.x * blockDim.x + threadIdx.x) >> 5;
    int lane = threadIdx.x & 31;
    int e0 = warp * EPW;
    if (e0 >= nE) return;

    int s[EPW], d[EPW];
    float wt[EPW];
    #pragma unroll
    for (int i = 0; i < EPW; i++) {
        s[i]  = __ldg(&es[e0 + i]);
        d[i]  = __ldg(&ed[e0 + i]);
        wt[i] = __ldg(&w[e0 + i]);
    }
    float4 v[EPW];
    #pragma unroll
    for (int i = 0; i < EPW; i++)
        v[i] = *(const float4*)&nmat[(size_t)s[i] * 128 + lane * 4];
    #pragma unroll
    for (int i = 0; i < EPW; i++) {
        float* dst = &agg[(size_t)d[i] * 128 + lane * 4];
#if !defined(__CUDA_ARCH__) || __CUDA_ARCH__ >= 900
        asm volatile("red.global.add.v4.f32 [%0], {%1,%2,%3,%4};"
                     :: "l"(dst), "f"(v[i].x * wt[i]), "f"(v[i].y * wt[i]),
                        "f"(v[i].z * wt[i]), "f"(v[i].w * wt[i])
                     : "memory");
#else
        atomicAdd(dst + 0, v[i].x * wt[i]);
        atomicAdd(dst + 1, v[i].y * wt[i]);
        atomicAdd(dst + 2, v[i].z * wt[i]);
        atomicAdd(dst + 3, v[i].w * wt[i]);
#endif
    }
    if (lane == 0) {
        #pragma unroll
        for (int i = 0; i < EPW; i++)
            atomicAdd(&ws[d[i]], wt[i]);
    }
}

// ---------------------------------------------------------------------------
// Scores / loss / AUC
// ---------------------------------------------------------------------------
__global__ __launch_bounds__(256)
void score_kernel(const float* __restrict__ hi,
                  const int* __restrict__ ps, const int* __restrict__ pd,
                  const int* __restrict__ ns, const int* __restrict__ nd,
                  const int* __restrict__ nids,
                  const float* __restrict__ bias,
                  float* __restrict__ scores) {
    int wid = (blockIdx.x * blockDim.x + threadIdx.x) >> 5;
    int lane = threadIdx.x & 31;
    if (wid >= NS) return;
    int s, d;
    if (wid < NP) { s = ps[wid]; d = pd[wid]; }
    else          { s = ns[wid - NP]; d = nd[wid - NP]; }
    float4 a = *(const float4*)&hi[(size_t)s * 128 + lane * 4];
    float4 b = *(const float4*)&hi[(size_t)d * 128 + lane * 4];
    float p = a.x * b.x + a.y * b.y + a.z * b.z + a.w * b.w;
    #pragma unroll
    for (int off = 16; off > 0; off >>= 1)
        p += __shfl_xor_sync(0xffffffffu, p, off);
    if (lane == 0)
        scores[wid] = p + bias[nids[s]] + bias[nids[d]];
}

__global__ void loss_kernel(const float* __restrict__ scores, float* __restrict__ out) {
    int i = blockIdx.x * blockDim.x + threadIdx.x;
    if (i < NP)
        out[i] = fmaxf(scores[NP + i] - scores[i] + 1.0f, 0.0f);
}

#define AUC_JCH 2048
__global__ __launch_bounds__(256)
void auc_count_kernel(const float* __restrict__ scores, unsigned int* __restrict__ R) {
    __shared__ float ss[AUC_JCH];
    int tid = threadIdx.x;
    int j0 = blockIdx.y * AUC_JCH;
    for (int j = tid; j < AUC_JCH; j += blockDim.x) ss[j] = scores[j0 + j];
    __syncthreads();
    int i = blockIdx.x * blockDim.x + tid;
    float my = scores[i];
    unsigned int cnt = 0;
    #pragma unroll 4
    for (int jj = 0; jj < AUC_JCH; jj++) {
        float v = ss[jj];
        int j = j0 + jj;
        cnt += (v < my) || (v == my && j < i);
    }
    #pragma unroll
    for (int off = 16; off > 0; off >>= 1)
        cnt += __shfl_xor_sync(0xffffffffu, cnt, off);
    if ((tid & 31) == 0) atomicAdd(R, cnt);
}

__global__ void auc_final_kernel(const unsigned int* __restrict__ R, float* __restrict__ out) {
    double r = (double)(*R);
    double npos = (double)NP, nneg = (double)NP;
    out[0] = (float)((r - npos * (npos - 1.0) * 0.5) / (npos * nneg));
}

// ---------------------------------------------------------------------------
// Launch
// ---------------------------------------------------------------------------
extern "C" void kernel_launch(void* const* d_in, const int* in_sizes, int n_in,
                              void* d_out, int out_size) {
    const int*   src0_id   = (const int*)  d_in[0];
    const int*   src0_cats = (const int*)  d_in[1];
    const float* src0_genre= (const float*)d_in[2];
    const int*   es0       = (const int*)  d_in[3];
    const int*   ed0       = (const int*)  d_in[4];
    const float* w0        = (const float*)d_in[5];
    const int*   es1       = (const int*)  d_in[6];
    const int*   ed1       = (const int*)  d_in[7];
    const float* w1        = (const float*)d_in[8];
    const int*   pos_src   = (const int*)  d_in[9];
    const int*   pos_dst   = (const int*)  d_in[10];
    const int*   neg_src   = (const int*)  d_in[11];
    const int*   neg_dst   = (const int*)  d_in[12];
    const int*   seed_nids = (const int*)  d_in[13];
    const float* track_emb = (const float*)d_in[14];
    const float* cat_embs  = (const float*)d_in[15];
    const float* fc_W      = (const float*)d_in[16];
    const float* fc_b      = (const float*)d_in[17];
    const float* Q0_W      = (const float*)d_in[18];
    const float* Q0_b      = (const float*)d_in[19];
    const float* W0_W      = (const float*)d_in[20];
    const float* W0_b      = (const float*)d_in[21];
    const float* Q1_W      = (const float*)d_in[22];
    const float* Q1_b      = (const float*)d_in[23];
    const float* W1_W      = (const float*)d_in[24];
    const float* W1_b      = (const float*)d_in[25];
    const float* bias      = (const float*)d_in[26];
    float* out = (float*)d_out;

    float *p_T, *p_h, *p_n, *p_agg0, *p_ws0, *p_h1, *p_agg1, *p_ws1, *p_hitem, *p_scores;
    unsigned int* p_R;
    cudaGetSymbolAddress((void**)&p_T,     g_T);
    cudaGetSymbolAddress((void**)&p_h,     g_h);
    cudaGetSymbolAddress((void**)&p_n,     g_n);
    cudaGetSymbolAddress((void**)&p_agg0,  g_agg0);
    cudaGetSymbolAddress((void**)&p_ws0,   g_ws0);
    cudaGetSymbolAddress((void**)&p_h1,    g_h1);
    cudaGetSymbolAddress((void**)&p_agg1,  g_agg1);
    cudaGetSymbolAddress((void**)&p_ws1,   g_ws1);
    cudaGetSymbolAddress((void**)&p_hitem, g_hitem);
    cudaGetSymbolAddress((void**)&p_scores,g_scores);
    cudaGetSymbolAddress((void**)&p_R,     g_rank_sum);

    // ncu captures launch #4 (empirical) -> gemm_q0 this round
    zero_R_kernel<<<1, 1>>>(p_R);                                                        // 1
    precompute_T_kernel<<<N_CATS * CAT_VOCAB, 128>>>(cat_embs, fc_W, p_T);               // 2
    proj_kernel<<<N_SRC0 / (8 * ROWS_PER_WARP), 256>>>(src0_id, src0_cats, src0_genre,   // 3
                                                       p_T, fc_W, fc_b, track_emb, p_h,
                                                       p_agg0, p_ws0, p_agg1, p_ws1);
    gemm_q_kernel<<<N_SRC0 / 128, 256>>>(p_h, Q0_W, Q0_b, p_n);                          // 4 (ncu)
    edge_agg_kernel<<<NE0 / (EPW * 8), 256>>>(p_n, es0, ed0, w0, p_agg0, p_ws0, NE0);    // 5
    gemm_wnorm_kernel<<<N_DST0 / 128, 256>>>(p_agg0, p_ws0, p_h, W0_W, W0_b,             // 6
                                             nullptr, p_h1);
    gemm_q_kernel<<<N_DST0 / 128, 256>>>(p_h1, Q1_W, Q1_b, p_n);                         // 7
    edge_agg_kernel<<<NE1 / (EPW * 8), 256>>>(p_n, es1, ed1, w1, p_agg1, p_ws1, NE1);    // 8
    gemm_wnorm_kernel<<<N_DST1 / 128, 256>>>(p_agg1, p_ws1, p_h1, W1_W, W1_b,            // 9
                                             p_h, p_hitem);

    score_kernel<<<NS / 8, 256>>>(p_hitem, pos_src, pos_dst, neg_src, neg_dst,
                                  seed_nids, bias, p_scores);
    loss_kernel<<<NP / 256, 256>>>(p_scores, out);

    dim3 auc_grid(NP / 256, NS / AUC_JCH);
    auc_count_kernel<<<auc_grid, 256>>>(p_scores, p_R);
    if (out_size >= NP + 1)
        auc_final_kernel<<<1, 1>>>(p_R, out + NP);
}

// round 10
// speedup vs baseline: 1.4614x; 1.0067x over previous
#include <cuda_runtime.h>
#include <cuda_bf16.h>
#include <math.h>

// ---------------------------------------------------------------------------
// Problem constants
// ---------------------------------------------------------------------------
#define N_SRC0   262144
#define N_DST0   65536
#define N_DST1   8192
#define HID      128
#define N_CATS   9
#define CAT_VOCAB 101
#define CAT_DIM  16
#define GENRE_DIM 20
#define NE0      1048576
#define NE1      131072
#define NP       8192
#define NS       16384

// ---------------------------------------------------------------------------
// Static device scratch
// ---------------------------------------------------------------------------
__device__ float g_T[N_CATS * CAT_VOCAB * HID];
__device__ float g_h[(size_t)N_SRC0 * HID];
__device__ float g_n[(size_t)N_SRC0 * HID];
__device__ float g_agg0[(size_t)N_DST0 * HID];
__device__ float g_ws0[N_DST0];
__device__ float g_h1[(size_t)N_DST0 * HID];
__device__ float g_agg1[(size_t)N_DST1 * HID];
__device__ float g_ws1[N_DST1];
__device__ float g_hitem[(size_t)N_DST1 * HID];
__device__ float g_scores[NS];
__device__ unsigned int g_rank_sum;

// ---------------------------------------------------------------------------
// bf16 split helpers
// ---------------------------------------------------------------------------
__device__ __forceinline__ void pack_bf16(float x0, float x1, unsigned& hi, unsigned& lo) {
    unsigned hw;
    asm("cvt.rn.bf16x2.f32 %0, %1, %2;" : "=r"(hw) : "f"(x1), "f"(x0));
    float h0 = __uint_as_float(hw << 16);
    float h1 = __uint_as_float(hw & 0xFFFF0000u);
    float r0 = x0 - h0;
    float r1 = x1 - h1;
    unsigned lw;
    asm("cvt.rn.bf16x2.f32 %0, %1, %2;" : "=r"(lw) : "f"(r1), "f"(r0));
    hi = hw; lo = lw;
}

__device__ __forceinline__ void mma_bf16(float* c, const unsigned* a, const unsigned* b) {
    asm volatile(
        "mma.sync.aligned.m16n8k16.row.col.f32.bf16.bf16.f32 "
        "{%0,%1,%2,%3}, {%4,%5,%6,%7}, {%8,%9}, {%0,%1,%2,%3};"
        : "+f"(c[0]), "+f"(c[1]), "+f"(c[2]), "+f"(c[3])
        : "r"(a[0]), "r"(a[1]), "r"(a[2]), "r"(a[3]), "r"(b[0]), "r"(b[1]));
}

// ---------------------------------------------------------------------------
// A-resident GEMM layout
//   A planes (full K=128): [row 0..127][64 words], stride AW2=68 u32.
//     fragment bank = (68g + t) mod 32 = 4g + t -> all 32 lanes distinct.
//   B planes (per K16 iter): [n 0..127][8 words], stride 9 u32.
// ---------------------------------------------------------------------------
#define AW2 68
#define APL (128 * AW2)          // u32 per A plane
#define BPL (128 * 9)            // u32 per B plane
// dynamic smem: AHi, ALo, then 4 B planes (buf0hi, buf0lo, buf1hi, buf1lo)
#define Q_SMEM_U32 (2 * APL + 4 * BPL)
#define Q_SMEM_BYTES (Q_SMEM_U32 * 4)

__device__ __forceinline__ void tile_ares(const unsigned* __restrict__ AHi,
                                          const unsigned* __restrict__ ALo,
                                          const unsigned* __restrict__ Bhi,
                                          const unsigned* __restrict__ Blo,
                                          float acc[2][8][4], int kw,
                                          int g, int t, int warp_m, int warp_n) {
    unsigned ah[2][4], al[2][4];
    #pragma unroll
    for (int mi = 0; mi < 2; mi++) {
        int rb = warp_m * 32 + mi * 16 + g;
        ah[mi][0] = AHi[rb * AW2 + kw + t];
        ah[mi][1] = AHi[(rb + 8) * AW2 + kw + t];
        ah[mi][2] = AHi[rb * AW2 + kw + t + 4];
        ah[mi][3] = AHi[(rb + 8) * AW2 + kw + t + 4];
        al[mi][0] = ALo[rb * AW2 + kw + t];
        al[mi][1] = ALo[(rb + 8) * AW2 + kw + t];
        al[mi][2] = ALo[rb * AW2 + kw + t + 4];
        al[mi][3] = ALo[(rb + 8) * AW2 + kw + t + 4];
    }
    #pragma unroll
    for (int ni = 0; ni < 8; ni++) {
        int n0 = warp_n * 64 + ni * 8 + g;
        unsigned bh[2] = {Bhi[n0 * 9 + t], Bhi[n0 * 9 + t + 4]};
        unsigned bl[2] = {Blo[n0 * 9 + t], Blo[n0 * 9 + t + 4]};
        #pragma unroll
        for (int mi = 0; mi < 2; mi++) {
            mma_bf16(acc[mi][ni], ah[mi], bh);
            mma_bf16(acc[mi][ni], al[mi], bh);
            mma_bf16(acc[mi][ni], ah[mi], bl);
        }
    }
}

__device__ __forceinline__ void store8B(unsigned* hi, unsigned* lo, float4 v0, float4 v1) {
    unsigned h, l;
    pack_bf16(v0.x, v0.y, h, l); hi[0] = h; lo[0] = l;
    pack_bf16(v0.z, v0.w, h, l); hi[1] = h; lo[1] = l;
    pack_bf16(v1.x, v1.y, h, l); hi[2] = h; lo[2] = l;
    pack_bf16(v1.z, v1.w, h, l); hi[3] = h; lo[3] = l;
}

// shared B-loop + epilogue for the two A-resident Q kernels
__device__ __forceinline__ void q_mainloop_epilogue(
    unsigned* AHi, unsigned* ALo, unsigned* BP,
    const float* __restrict__ W, const float* __restrict__ bvec,
    float* __restrict__ out, int r0) {
    int tid = threadIdx.x;
    int wid = tid >> 5, lane = tid & 31;
    int g = lane >> 2, t = lane & 3;
    int warp_m = wid & 3, warp_n = wid >> 2;
    int bn = tid & 127, bh2 = tid >> 7;

    const int NIT = 8;  // K=128
    float acc[2][8][4] = {};

    // B tile 0
    {
        const float* wp = &W[(bh2 * 8) * 128 + bn];
        float4 rb0 = make_float4(wp[0], wp[128], wp[256], wp[384]);
        float4 rb1 = make_float4(wp[512], wp[640], wp[768], wp[896]);
        store8B(&BP[bn * 9 + bh2 * 4], &BP[BPL + bn * 9 + bh2 * 4], rb0, rb1);
    }
    __syncthreads();   // covers A planes + B0

    for (int it = 0; it < NIT; it++) {
        float4 rb0, rb1;
        if (it + 1 < NIT) {
            int k0 = (it + 1) * 16;
            const float* wp = &W[(k0 + bh2 * 8) * 128 + bn];
            rb0 = make_float4(wp[0], wp[128], wp[256], wp[384]);
            rb1 = make_float4(wp[512], wp[640], wp[768], wp[896]);
        }
        int cur = it & 1;
        tile_ares(AHi, ALo, BP + cur * 2 * BPL, BP + cur * 2 * BPL + BPL,
                  acc, it * 8, g, t, warp_m, warp_n);
        if (it + 1 < NIT) {
            int nb = (it + 1) & 1;
            store8B(&BP[nb * 2 * BPL + bn * 9 + bh2 * 4],
                    &BP[nb * 2 * BPL + BPL + bn * 9 + bh2 * 4], rb0, rb1);
        }
        __syncthreads();
    }

    #pragma unroll
    for (int ni = 0; ni < 8; ni++) {
        int col = warp_n * 64 + ni * 8 + 2 * t;
        float2 bv = *(const float2*)&bvec[col];
        #pragma unroll
        for (int mi = 0; mi < 2; mi++) {
            int row0 = r0 + warp_m * 32 + mi * 16 + g;
            float2 o0, o1;
            o0.x = fmaxf(acc[mi][ni][0] + bv.x, 0.f);
            o0.y = fmaxf(acc[mi][ni][1] + bv.y, 0.f);
            o1.x = fmaxf(acc[mi][ni][2] + bv.x, 0.f);
            o1.y = fmaxf(acc[mi][ni][3] + bv.y, 0.f);
            *(float2*)&out[(size_t)row0 * 128 + col]       = o0;
            *(float2*)&out[(size_t)(row0 + 8) * 128 + col] = o1;
        }
    }
}

// ---- FUSED proj + Q0 GEMM: builds A in smem from features, writes h and n --
__global__ __launch_bounds__(256, 2)
void fused_proj_q_kernel(const int* __restrict__ ids,
                         const int* __restrict__ cats,
                         const float* __restrict__ genre,
                         const float* __restrict__ T,
                         const float* __restrict__ fcW,
                         const float* __restrict__ fcb,
                         const float* __restrict__ track_emb,
                         const float* __restrict__ QW,
                         const float* __restrict__ Qb,
                         float* __restrict__ h_out,
                         float* __restrict__ n_out) {
    extern __shared__ unsigned sm[];
    unsigned* AHi = sm;
    unsigned* ALo = sm + APL;
    unsigned* BP  = sm + 2 * APL;

    int tid = threadIdx.x;
    int wid = tid >> 5, lane = tid & 31;
    int r0 = blockIdx.x * 128;

    // ---- proj phase: 8 warps x 16 rows ----
    {
        float4 Wg[GENRE_DIM];
        #pragma unroll
        for (int g2 = 0; g2 < GENRE_DIM; g2++)
            Wg[g2] = *(const float4*)&fcW[(144 + g2) * HID + lane * 4];
        float4 bb = *(const float4*)&fcb[lane * 4];

        int rl0 = wid * 16;
        for (int rr = 0; rr < 16; rr++) {
            int rl = rl0 + rr;
            int r = r0 + rl;
            int myc = (lane < N_CATS) ? cats[r * N_CATS + lane] : 0;
            float gv = (lane < GENRE_DIM) ? genre[(size_t)r * GENRE_DIM + lane] : 0.f;
            int id = ids[r];
            float4 acc = bb;
            #pragma unroll
            for (int c = 0; c < N_CATS; c++) {
                int v = __shfl_sync(0xffffffffu, myc, c);
                float4 tt = *(const float4*)&T[(c * CAT_VOCAB + v) * HID + lane * 4];
                acc.x += tt.x; acc.y += tt.y; acc.z += tt.z; acc.w += tt.w;
            }
            #pragma unroll
            for (int g2 = 0; g2 < GENRE_DIM; g2++) {
                float s = __shfl_sync(0xffffffffu, gv, g2);
                acc.x += s * Wg[g2].x; acc.y += s * Wg[g2].y;
                acc.z += s * Wg[g2].z; acc.w += s * Wg[g2].w;
            }
            float4 te = *(const float4*)&track_emb[(size_t)id * HID + lane * 4];
            acc.x += te.x; acc.y += te.y; acc.z += te.z; acc.w += te.w;
            *(float4*)&h_out[(size_t)r * 128 + lane * 4] = acc;
            unsigned h0, l0, h1, l1;
            pack_bf16(acc.x, acc.y, h0, l0);
            pack_bf16(acc.z, acc.w, h1, l1);
            AHi[rl * AW2 + 2 * lane]     = h0;
            AHi[rl * AW2 + 2 * lane + 1] = h1;
            ALo[rl * AW2 + 2 * lane]     = l0;
            ALo[rl * AW2 + 2 * lane + 1] = l1;
        }
    }
    q_mainloop_epilogue(AHi, ALo, BP, QW, Qb, n_out, r0);
}

// ---- plain A-resident Q GEMM (A from global, deep-MLP load phase) ----------
__global__ __launch_bounds__(256, 2)
void gemm_q_ares_kernel(const float* __restrict__ A,
                        const float* __restrict__ QW,
                        const float* __restrict__ Qb,
                        float* __restrict__ out) {
    extern __shared__ unsigned sm[];
    unsigned* AHi = sm;
    unsigned* ALo = sm + APL;
    unsigned* BP  = sm + 2 * APL;

    int tid = threadIdx.x;
    int r0 = blockIdx.x * 128;
    int row = tid >> 1, half = tid & 1;

    // A load phase: thread (row, half) covers cols 8j + 4*half, j=0..15
    #pragma unroll 4
    for (int j = 0; j < 16; j++) {
        float4 v = *(const float4*)&A[(size_t)(r0 + row) * 128 + 8 * j + 4 * half];
        unsigned h0, l0, h1, l1;
        pack_bf16(v.x, v.y, h0, l0);
        pack_bf16(v.z, v.w, h1, l1);
        int w = row * AW2 + 4 * j + 2 * half;
        AHi[w] = h0; AHi[w + 1] = h1;
        ALo[w] = l0; ALo[w + 1] = l1;
    }
    q_mainloop_epilogue(AHi, ALo, BP, QW, Qb, out, r0);
}

// ---- W GEMM + row L2-normalize (+ optional residual), K = 256 (R8 kernel) --
#define AW 9
#define PLANE (128 * AW)
__global__ __launch_bounds__(256, 2)
void gemm_wnorm_kernel(const float* __restrict__ agg,
                       const float* __restrict__ ws,
                       const float* __restrict__ hdst,
                       const float* __restrict__ W,
                       const float* __restrict__ bvec,
                       const float* __restrict__ addsrc,
                       float* __restrict__ out) {
    __shared__ unsigned SA[2][2][PLANE];
    __shared__ unsigned SB[2][2][PLANE];
    __shared__ float Ss[128][2];

    const int K = 256;
    const int NIT = K / 16;
    int tid = threadIdx.x;
    int wid = tid >> 5, lane = tid & 31;
    int g = lane >> 2, t = lane & 3;
    int warp_m = wid & 3, warp_n = wid >> 2;
    int r0 = blockIdx.x * 128;

    int lr = tid >> 1;
    int lh = tid & 1;
    int bn = tid & 127;
    int bh2 = tid >> 7;

    float iw = 1.0f / fmaxf(ws[r0 + lr], 1.0f);

    float acc[2][8][4] = {};

    auto loadA = [&](int kg, float4& v0, float4& v1) {
        if (kg < 128) {
            v0 = *(const float4*)&agg[(size_t)(r0 + lr) * 128 + kg];
            v1 = *(const float4*)&agg[(size_t)(r0 + lr) * 128 + kg + 4];
            v0.x *= iw; v0.y *= iw; v0.z *= iw; v0.w *= iw;
            v1.x *= iw; v1.y *= iw; v1.z *= iw; v1.w *= iw;
        } else {
            v0 = *(const float4*)&hdst[(size_t)(r0 + lr) * 128 + (kg - 128)];
            v1 = *(const float4*)&hdst[(size_t)(r0 + lr) * 128 + (kg - 128) + 4];
        }
    };

    float4 ra0, ra1, rb0, rb1;
    loadA(lh * 8, ra0, ra1);
    {
        const float* wp = &W[(bh2 * 8) * 128 + bn];
        rb0 = make_float4(wp[0], wp[128], wp[256], wp[384]);
        rb1 = make_float4(wp[512], wp[640], wp[768], wp[896]);
    }
    store8B(&SA[0][0][lr * AW + lh * 4], &SA[0][1][lr * AW + lh * 4], ra0, ra1);
    store8B(&SB[0][0][bn * AW + bh2 * 4], &SB[0][1][bn * AW + bh2 * 4], rb0, rb1);
    __syncthreads();

    for (int it = 0; it < NIT; it++) {
        if (it + 1 < NIT) {
            int k0 = (it + 1) * 16;
            loadA(k0 + lh * 8, ra0, ra1);
            const float* wp = &W[(k0 + bh2 * 8) * 128 + bn];
            rb0 = make_float4(wp[0], wp[128], wp[256], wp[384]);
            rb1 = make_float4(wp[512], wp[640], wp[768], wp[896]);
        }
        int cur = it & 1;
        // A fragments from per-iter planes (stride 9)
        {
            int g2 = g, t2 = t;
            unsigned ah[2][4], al[2][4];
            #pragma unroll
            for (int mi = 0; mi < 2; mi++) {
                int rb = warp_m * 32 + mi * 16 + g2;
                ah[mi][0] = SA[cur][0][rb * AW + t2];
                ah[mi][1] = SA[cur][0][(rb + 8) * AW + t2];
                ah[mi][2] = SA[cur][0][rb * AW + t2 + 4];
                ah[mi][3] = SA[cur][0][(rb + 8) * AW + t2 + 4];
                al[mi][0] = SA[cur][1][rb * AW + t2];
                al[mi][1] = SA[cur][1][(rb + 8) * AW + t2];
                al[mi][2] = SA[cur][1][rb * AW + t2 + 4];
                al[mi][3] = SA[cur][1][(rb + 8) * AW + t2 + 4];
            }
            #pragma unroll
            for (int ni = 0; ni < 8; ni++) {
                int n0 = warp_n * 64 + ni * 8 + g2;
                unsigned bh[2] = {SB[cur][0][n0 * AW + t2], SB[cur][0][n0 * AW + t2 + 4]};
                unsigned bl[2] = {SB[cur][1][n0 * AW + t2], SB[cur][1][n0 * AW + t2 + 4]};
                #pragma unroll
                for (int mi = 0; mi < 2; mi++) {
                    mma_bf16(acc[mi][ni], ah[mi], bh);
                    mma_bf16(acc[mi][ni], al[mi], bh);
                    mma_bf16(acc[mi][ni], ah[mi], bl);
                }
            }
        }
        if (it + 1 < NIT) {
            int nb = (it + 1) & 1;
            store8B(&SA[nb][0][lr * AW + lh * 4], &SA[nb][1][lr * AW + lh * 4], ra0, ra1);
            store8B(&SB[nb][0][bn * AW + bh2 * 4], &SB[nb][1][bn * AW + bh2 * 4], rb0, rb1);
        }
        __syncthreads();
    }

    float ssl[2][2] = {};
    #pragma unroll
    for (int ni = 0; ni < 8; ni++) {
        int col = warp_n * 64 + ni * 8 + 2 * t;
        float2 bv = *(const float2*)&bvec[col];
        #pragma unroll
        for (int mi = 0; mi < 2; mi++) {
            float z0 = fmaxf(acc[mi][ni][0] + bv.x, 0.f);
            float z1 = fmaxf(acc[mi][ni][1] + bv.y, 0.f);
            float z2 = fmaxf(acc[mi][ni][2] + bv.x, 0.f);
            float z3 = fmaxf(acc[mi][ni][3] + bv.y, 0.f);
            acc[mi][ni][0] = z0; acc[mi][ni][1] = z1;
            acc[mi][ni][2] = z2; acc[mi][ni][3] = z3;
            ssl[mi][0] += z0 * z0 + z1 * z1;
            ssl[mi][1] += z2 * z2 + z3 * z3;
        }
    }
    #pragma unroll
    for (int mi = 0; mi < 2; mi++)
        #pragma unroll
        for (int h = 0; h < 2; h++) {
            float s = ssl[mi][h];
            s += __shfl_xor_sync(0xffffffffu, s, 1);
            s += __shfl_xor_sync(0xffffffffu, s, 2);
            ssl[mi][h] = s;
        }
    if (t == 0) {
        #pragma unroll
        for (int mi = 0; mi < 2; mi++) {
            int r = warp_m * 32 + mi * 16 + g;
            Ss[r][warp_n]     = ssl[mi][0];
            Ss[r + 8][warp_n] = ssl[mi][1];
        }
    }
    __syncthreads();
    #pragma unroll
    for (int mi = 0; mi < 2; mi++) {
        int rl0 = warp_m * 32 + mi * 16 + g;
        float ss0 = Ss[rl0][0] + Ss[rl0][1];
        float ss1 = Ss[rl0 + 8][0] + Ss[rl0 + 8][1];
        float in0 = (ss0 > 0.f) ? rsqrtf(ss0) : 1.0f;
        float in1 = (ss1 > 0.f) ? rsqrtf(ss1) : 1.0f;
        size_t row0 = (size_t)(r0 + rl0);
        #pragma unroll
        for (int ni = 0; ni < 8; ni++) {
            int col = warp_n * 64 + ni * 8 + 2 * t;
            float2 o0, o1;
            o0.x = acc[mi][ni][0] * in0; o0.y = acc[mi][ni][1] * in0;
            o1.x = acc[mi][ni][2] * in1; o1.y = acc[mi][ni][3] * in1;
            if (addsrc) {
                float2 a0 = *(const float2*)&addsrc[row0 * 128 + col];
                float2 a1 = *(const float2*)&addsrc[(row0 + 8) * 128 + col];
                o0.x += a0.x; o0.y += a0.y;
                o1.x += a1.x; o1.y += a1.y;
            }
            *(float2*)&out[row0 * 128 + col]       = o0;
            *(float2*)&out[(row0 + 8) * 128 + col] = o1;
        }
    }
}

// ---------------------------------------------------------------------------
// Precompute T / zeroing
// ---------------------------------------------------------------------------
__global__ void precompute_T_kernel(const float* __restrict__ cat_embs,
                                    const float* __restrict__ fcW,
                                    float* __restrict__ T) {
    int cv = blockIdx.x;
    int c = cv / CAT_VOCAB;
    int n = threadIdx.x;
    const float* e = &cat_embs[cv * CAT_DIM];
    float acc = 0.f;
    #pragma unroll
    for (int d = 0; d < CAT_DIM; d++)
        acc += __ldg(&e[d]) * fcW[(c * CAT_DIM + d) * HID + n];
    T[cv * HID + n] = acc;
}

__global__ void zero_all_kernel(float* agg0, float* ws0, float* agg1, float* ws1,
                                unsigned int* R) {
    int i = blockIdx.x * blockDim.x + threadIdx.x;
    int st = gridDim.x * blockDim.x;
    float4 z = {0.f, 0.f, 0.f, 0.f};
    for (int j = i; j < N_DST0 * HID / 4; j += st) ((float4*)agg0)[j] = z;
    for (int j = i; j < N_DST1 * HID / 4; j += st) ((float4*)agg1)[j] = z;
    for (int j = i; j < N_DST0; j += st) ws0[j] = 0.f;
    for (int j = i; j < N_DST1; j += st) ws1[j] = 0.f;
    if (i == 0) *R = 0u;
}

// ---------------------------------------------------------------------------
// Edge aggregation: 8 edges per warp, batched phases for deep MLP
// ---------------------------------------------------------------------------
#define EPW 8
__global__ __launch_bounds__(256)
void edge_agg_kernel(const float* __restrict__ nmat,
                     const int* __restrict__ es,
                     const int* __restrict__ ed,
                     const float* __restrict__ w,
                     float* __restrict__ agg,
                     float* __restrict__ ws,
                     int nE) {
    int warp = (blockIdx.x * blockDim.x + threadIdx.x) >> 5;
    int lane = threadIdx.x & 31;
    int e0 = warp * EPW;
    if (e0 >= nE) return;

    int s[EPW], d[EPW];
    float wt[EPW];
    #pragma unroll
    for (int i = 0; i < EPW; i++) {
        s[i]  = __ldg(&es[e0 + i]);
        d[i]  = __ldg(&ed[e0 + i]);
        wt[i] = __ldg(&w[e0 + i]);
    }
    float4 v[EPW];
    #pragma unroll
    for (int i = 0; i < EPW; i++)
        v[i] = *(const float4*)&nmat[(size_t)s[i] * 128 + lane * 4];
    #pragma unroll
    for (int i = 0; i < EPW; i++) {
        float* dst = &agg[(size_t)d[i] * 128 + lane * 4];
#if !defined(__CUDA_ARCH__) || __CUDA_ARCH__ >= 900
        asm volatile("red.global.add.v4.f32 [%0], {%1,%2,%3,%4};"
                     :: "l"(dst), "f"(v[i].x * wt[i]), "f"(v[i].y * wt[i]),
                        "f"(v[i].z * wt[i]), "f"(v[i].w * wt[i])
                     : "memory");
#else
        atomicAdd(dst + 0, v[i].x * wt[i]);
        atomicAdd(dst + 1, v[i].y * wt[i]);
        atomicAdd(dst + 2, v[i].z * wt[i]);
        atomicAdd(dst + 3, v[i].w * wt[i]);
#endif
    }
    if (lane == 0) {
        #pragma unroll
        for (int i = 0; i < EPW; i++)
            atomicAdd(&ws[d[i]], wt[i]);
    }
}

// ---------------------------------------------------------------------------
// Scores / loss / AUC
// ---------------------------------------------------------------------------
__global__ __launch_bounds__(256)
void score_kernel(const float* __restrict__ hi,
                  const int* __restrict__ ps, const int* __restrict__ pd,
                  const int* __restrict__ ns, const int* __restrict__ nd,
                  const int* __restrict__ nids,
                  const float* __restrict__ bias,
                  float* __restrict__ scores) {
    int wid = (blockIdx.x * blockDim.x + threadIdx.x) >> 5;
    int lane = threadIdx.x & 31;
    if (wid >= NS) return;
    int s, d;
    if (wid < NP) { s = ps[wid]; d = pd[wid]; }
    else          { s = ns[wid - NP]; d = nd[wid - NP]; }
    float4 a = *(const float4*)&hi[(size_t)s * 128 + lane * 4];
    float4 b = *(const float4*)&hi[(size_t)d * 128 + lane * 4];
    float p = a.x * b.x + a.y * b.y + a.z * b.z + a.w * b.w;
    #pragma unroll
    for (int off = 16; off > 0; off >>= 1)
        p += __shfl_xor_sync(0xffffffffu, p, off);
    if (lane == 0)
        scores[wid] = p + bias[nids[s]] + bias[nids[d]];
}

__global__ void loss_kernel(const float* __restrict__ scores, float* __restrict__ out) {
    int i = blockIdx.x * blockDim.x + threadIdx.x;
    if (i < NP)
        out[i] = fmaxf(scores[NP + i] - scores[i] + 1.0f, 0.0f);
}

#define AUC_JCH 2048
__global__ __launch_bounds__(256)
void auc_count_kernel(const float* __restrict__ scores, unsigned int* __restrict__ R) {
    __shared__ float ss[AUC_JCH];
    int tid = threadIdx.x;
    int j0 = blockIdx.y * AUC_JCH;
    for (int j = tid; j < AUC_JCH; j += blockDim.x) ss[j] = scores[j0 + j];
    __syncthreads();
    int i = blockIdx.x * blockDim.x + tid;
    float my = scores[i];
    unsigned int cnt = 0;
    #pragma unroll 4
    for (int jj = 0; jj < AUC_JCH; jj++) {
        float v = ss[jj];
        int j = j0 + jj;
        cnt += (v < my) || (v == my && j < i);
    }
    #pragma unroll
    for (int off = 16; off > 0; off >>= 1)
        cnt += __shfl_xor_sync(0xffffffffu, cnt, off);
    if ((tid & 31) == 0) atomicAdd(R, cnt);
}

__global__ void auc_final_kernel(const unsigned int* __restrict__ R, float* __restrict__ out) {
    double r = (double)(*R);
    double npos = (double)NP, nneg = (double)NP;
    out[0] = (float)((r - npos * (npos - 1.0) * 0.5) / (npos * nneg));
}

// ---------------------------------------------------------------------------
// Launch
// ---------------------------------------------------------------------------
extern "C" void kernel_launch(void* const* d_in, const int* in_sizes, int n_in,
                              void* d_out, int out_size) {
    const int*   src0_id   = (const int*)  d_in[0];
    const int*   src0_cats = (const int*)  d_in[1];
    const float* src0_genre= (const float*)d_in[2];
    const int*   es0       = (const int*)  d_in[3];
    const int*   ed0       = (const int*)  d_in[4];
    const float* w0        = (const float*)d_in[5];
    const int*   es1       = (const int*)  d_in[6];
    const int*   ed1       = (const int*)  d_in[7];
    const float* w1        = (const float*)d_in[8];
    const int*   pos_src   = (const int*)  d_in[9];
    const int*   pos_dst   = (const int*)  d_in[10];
    const int*   neg_src   = (const int*)  d_in[11];
    const int*   neg_dst   = (const int*)  d_in[12];
    const int*   seed_nids = (const int*)  d_in[13];
    const float* track_emb = (const float*)d_in[14];
    const float* cat_embs  = (const float*)d_in[15];
    const float* fc_W      = (const float*)d_in[16];
    const float* fc_b      = (const float*)d_in[17];
    const float* Q0_W      = (const float*)d_in[18];
    const float* Q0_b      = (const float*)d_in[19];
    const float* W0_W      = (const float*)d_in[20];
    const float* W0_b      = (const float*)d_in[21];
    const float* Q1_W      = (const float*)d_in[22];
    const float* Q1_b      = (const float*)d_in[23];
    const float* W1_W      = (const float*)d_in[24];
    const float* W1_b      = (const float*)d_in[25];
    const float* bias      = (const float*)d_in[26];
    float* out = (float*)d_out;

    float *p_T, *p_h, *p_n, *p_agg0, *p_ws0, *p_h1, *p_agg1, *p_ws1, *p_hitem, *p_scores;
    unsigned int* p_R;
    cudaGetSymbolAddress((void**)&p_T,     g_T);
    cudaGetSymbolAddress((void**)&p_h,     g_h);
    cudaGetSymbolAddress((void**)&p_n,     g_n);
    cudaGetSymbolAddress((void**)&p_agg0,  g_agg0);
    cudaGetSymbolAddress((void**)&p_ws0,   g_ws0);
    cudaGetSymbolAddress((void**)&p_h1,    g_h1);
    cudaGetSymbolAddress((void**)&p_agg1,  g_agg1);
    cudaGetSymbolAddress((void**)&p_ws1,   g_ws1);
    cudaGetSymbolAddress((void**)&p_hitem, g_hitem);
    cudaGetSymbolAddress((void**)&p_scores,g_scores);
    cudaGetSymbolAddress((void**)&p_R,     g_rank_sum);

    // opt-in dynamic smem for the A-resident Q kernels (88 KB)
    cudaFuncSetAttribute(fused_proj_q_kernel,
                         cudaFuncAttributeMaxDynamicSharedMemorySize, Q_SMEM_BYTES);
    cudaFuncSetAttribute(gemm_q_ares_kernel,
                         cudaFuncAttributeMaxDynamicSharedMemorySize, Q_SMEM_BYTES);

    // ncu captures launch #4 (empirical) -> edge_agg0 (EPW=8) this round
    zero_all_kernel<<<1024, 256>>>(p_agg0, p_ws0, p_agg1, p_ws1, p_R);                   // 1
    precompute_T_kernel<<<N_CATS * CAT_VOCAB, 128>>>(cat_embs, fc_W, p_T);               // 2
    fused_proj_q_kernel<<<N_SRC0 / 128, 256, Q_SMEM_BYTES>>>(                            // 3
        src0_id, src0_cats, src0_genre, p_T, fc_W, fc_b, track_emb,
        Q0_W, Q0_b, p_h, p_n);
    edge_agg_kernel<<<NE0 / (EPW * 8), 256>>>(p_n, es0, ed0, w0, p_agg0, p_ws0, NE0);    // 4 (ncu)
    gemm_wnorm_kernel<<<N_DST0 / 128, 256>>>(p_agg0, p_ws0, p_h, W0_W, W0_b,             // 5
                                             nullptr, p_h1);
    gemm_q_ares_kernel<<<N_DST0 / 128, 256, Q_SMEM_BYTES>>>(p_h1, Q1_W, Q1_b, p_n);      // 6
    edge_agg_kernel<<<NE1 / (EPW * 8), 256>>>(p_n, es1, ed1, w1, p_agg1, p_ws1, NE1);    // 7
    gemm_wnorm_kernel<<<N_DST1 / 128, 256>>>(p_agg1, p_ws1, p_h1, W1_W, W1_b,            // 8
                                             p_h, p_hitem);

    score_kernel<<<NS / 8, 256>>>(p_hitem, pos_src, pos_dst, neg_src, neg_dst,
                                  seed_nids, bias, p_scores);
    loss_kernel<<<NP / 256, 256>>>(p_scores, out);

    dim3 auc_grid(NP / 256, NS / AUC_JCH);
    auc_count_kernel<<<auc_grid, 256>>>(p_scores, p_R);
    if (out_size >= NP + 1)
        auc_final_kernel<<<1, 1>>>(p_R, out + NP);
}

// round 11
// speedup vs baseline: 1.5302x; 1.0470x over previous
#include <cuda_runtime.h>
#include <cuda_bf16.h>
#include <math.h>

// ---------------------------------------------------------------------------
// Problem constants
// ---------------------------------------------------------------------------
#define N_SRC0   262144
#define N_DST0   65536
#define N_DST1   8192
#define HID      128
#define N_CATS   9
#define CAT_VOCAB 101
#define CAT_DIM  16
#define GENRE_DIM 20
#define NE0      1048576
#define NE1      131072
#define NP       8192
#define NS       16384

// ---------------------------------------------------------------------------
// Static device scratch
// ---------------------------------------------------------------------------
__device__ float g_T[N_CATS * CAT_VOCAB * HID];
__device__ float g_h[(size_t)N_SRC0 * HID];          // only rows < N_DST0 written
__device__ unsigned g_nb[(size_t)N_SRC0 * 64];       // n as bf16x2 words
__device__ float g_agg0[(size_t)N_DST0 * HID];
__device__ float g_ws0[N_DST0];
__device__ float g_h1[(size_t)N_DST0 * HID];
__device__ float g_agg1[(size_t)N_DST1 * HID];
__device__ float g_ws1[N_DST1];
__device__ float g_hitem[(size_t)N_DST1 * HID];
__device__ float g_scores[NS];
__device__ unsigned int g_rank_sum;

// ---------------------------------------------------------------------------
// bf16 split helpers
// ---------------------------------------------------------------------------
__device__ __forceinline__ void pack_bf16(float x0, float x1, unsigned& hi, unsigned& lo) {
    unsigned hw;
    asm("cvt.rn.bf16x2.f32 %0, %1, %2;" : "=r"(hw) : "f"(x1), "f"(x0));
    float h0 = __uint_as_float(hw << 16);
    float h1 = __uint_as_float(hw & 0xFFFF0000u);
    float r0 = x0 - h0;
    float r1 = x1 - h1;
    unsigned lw;
    asm("cvt.rn.bf16x2.f32 %0, %1, %2;" : "=r"(lw) : "f"(r1), "f"(r0));
    hi = hw; lo = lw;
}

__device__ __forceinline__ unsigned pack1_bf16(float x0, float x1) {
    unsigned w;
    asm("cvt.rn.bf16x2.f32 %0, %1, %2;" : "=r"(w) : "f"(x1), "f"(x0));
    return w;
}

__device__ __forceinline__ void mma_bf16(float* c, const unsigned* a, const unsigned* b) {
    asm volatile(
        "mma.sync.aligned.m16n8k16.row.col.f32.bf16.bf16.f32 "
        "{%0,%1,%2,%3}, {%4,%5,%6,%7}, {%8,%9}, {%0,%1,%2,%3};"
        : "+f"(c[0]), "+f"(c[1]), "+f"(c[2]), "+f"(c[3])
        : "r"(a[0]), "r"(a[1]), "r"(a[2]), "r"(a[3]), "r"(b[0]), "r"(b[1]));
}

// ---------------------------------------------------------------------------
// A-resident GEMM layout (A stride 68 u32, B per-iter stride 9 u32)
// ---------------------------------------------------------------------------
#define AW2 68
#define APL (128 * AW2)
#define BPL (128 * 9)
#define Q_SMEM_U32 (2 * APL + 4 * BPL)
#define Q_SMEM_BYTES (Q_SMEM_U32 * 4)

__device__ __forceinline__ void tile_ares(const unsigned* __restrict__ AHi,
                                          const unsigned* __restrict__ ALo,
                                          const unsigned* __restrict__ Bhi,
                                          const unsigned* __restrict__ Blo,
                                          float acc[2][8][4], int kw,
                                          int g, int t, int warp_m, int warp_n) {
    unsigned ah[2][4], al[2][4];
    #pragma unroll
    for (int mi = 0; mi < 2; mi++) {
        int rb = warp_m * 32 + mi * 16 + g;
        ah[mi][0] = AHi[rb * AW2 + kw + t];
        ah[mi][1] = AHi[(rb + 8) * AW2 + kw + t];
        ah[mi][2] = AHi[rb * AW2 + kw + t + 4];
        ah[mi][3] = AHi[(rb + 8) * AW2 + kw + t + 4];
        al[mi][0] = ALo[rb * AW2 + kw + t];
        al[mi][1] = ALo[(rb + 8) * AW2 + kw + t];
        al[mi][2] = ALo[rb * AW2 + kw + t + 4];
        al[mi][3] = ALo[(rb + 8) * AW2 + kw + t + 4];
    }
    #pragma unroll
    for (int ni = 0; ni < 8; ni++) {
        int n0 = warp_n * 64 + ni * 8 + g;
        unsigned bh[2] = {Bhi[n0 * 9 + t], Bhi[n0 * 9 + t + 4]};
        unsigned bl[2] = {Blo[n0 * 9 + t], Blo[n0 * 9 + t + 4]};
        #pragma unroll
        for (int mi = 0; mi < 2; mi++) {
            mma_bf16(acc[mi][ni], ah[mi], bh);
            mma_bf16(acc[mi][ni], al[mi], bh);
            mma_bf16(acc[mi][ni], ah[mi], bl);
        }
    }
}

__device__ __forceinline__ void store8B(unsigned* hi, unsigned* lo, float4 v0, float4 v1) {
    unsigned h, l;
    pack_bf16(v0.x, v0.y, h, l); hi[0] = h; lo[0] = l;
    pack_bf16(v0.z, v0.w, h, l); hi[1] = h; lo[1] = l;
    pack_bf16(v1.x, v1.y, h, l); hi[2] = h; lo[2] = l;
    pack_bf16(v1.z, v1.w, h, l); hi[3] = h; lo[3] = l;
}

// B-loop + epilogue -> writes relu(acc+b) as bf16x2 words (n buffer)
__device__ __forceinline__ void q_mainloop_epilogue_bf16(
    unsigned* AHi, unsigned* ALo, unsigned* BP,
    const float* __restrict__ W, const float* __restrict__ bvec,
    unsigned* __restrict__ n_words, int r0) {
    int tid = threadIdx.x;
    int wid = tid >> 5, lane = tid & 31;
    int g = lane >> 2, t = lane & 3;
    int warp_m = wid & 3, warp_n = wid >> 2;
    int bn = tid & 127, bh2 = tid >> 7;

    const int NIT = 8;
    float acc[2][8][4] = {};

    {
        const float* wp = &W[(bh2 * 8) * 128 + bn];
        float4 rb0 = make_float4(wp[0], wp[128], wp[256], wp[384]);
        float4 rb1 = make_float4(wp[512], wp[640], wp[768], wp[896]);
        store8B(&BP[bn * 9 + bh2 * 4], &BP[BPL + bn * 9 + bh2 * 4], rb0, rb1);
    }
    __syncthreads();

    for (int it = 0; it < NIT; it++) {
        float4 rb0, rb1;
        if (it + 1 < NIT) {
            int k0 = (it + 1) * 16;
            const float* wp = &W[(k0 + bh2 * 8) * 128 + bn];
            rb0 = make_float4(wp[0], wp[128], wp[256], wp[384]);
            rb1 = make_float4(wp[512], wp[640], wp[768], wp[896]);
        }
        int cur = it & 1;
        tile_ares(AHi, ALo, BP + cur * 2 * BPL, BP + cur * 2 * BPL + BPL,
                  acc, it * 8, g, t, warp_m, warp_n);
        if (it + 1 < NIT) {
            int nb = (it + 1) & 1;
            store8B(&BP[nb * 2 * BPL + bn * 9 + bh2 * 4],
                    &BP[nb * 2 * BPL + BPL + bn * 9 + bh2 * 4], rb0, rb1);
        }
        __syncthreads();
    }

    #pragma unroll
    for (int ni = 0; ni < 8; ni++) {
        int col = warp_n * 64 + ni * 8 + 2 * t;   // even
        float2 bv = *(const float2*)&bvec[col];
        int wcol = col >> 1;                       // word index in row (64 words)
        #pragma unroll
        for (int mi = 0; mi < 2; mi++) {
            int row0 = r0 + warp_m * 32 + mi * 16 + g;
            float z0 = fmaxf(acc[mi][ni][0] + bv.x, 0.f);
            float z1 = fmaxf(acc[mi][ni][1] + bv.y, 0.f);
            float z2 = fmaxf(acc[mi][ni][2] + bv.x, 0.f);
            float z3 = fmaxf(acc[mi][ni][3] + bv.y, 0.f);
            n_words[(size_t)row0 * 64 + wcol]       = pack1_bf16(z0, z1);
            n_words[(size_t)(row0 + 8) * 64 + wcol] = pack1_bf16(z2, z3);
        }
    }
}

// ---- FUSED proj + Q0 GEMM ---------------------------------------------------
__global__ __launch_bounds__(256, 2)
void fused_proj_q_kernel(const int* __restrict__ ids,
                         const int* __restrict__ cats,
                         const float* __restrict__ genre,
                         const float* __restrict__ T,
                         const float* __restrict__ fcW,
                         const float* __restrict__ fcb,
                         const float* __restrict__ track_emb,
                         const float* __restrict__ QW,
                         const float* __restrict__ Qb,
                         float* __restrict__ h_out,
                         unsigned* __restrict__ n_words) {
    extern __shared__ unsigned sm[];
    unsigned* AHi = sm;
    unsigned* ALo = sm + APL;
    unsigned* BP  = sm + 2 * APL;

    int tid = threadIdx.x;
    int wid = tid >> 5, lane = tid & 31;
    int r0 = blockIdx.x * 128;
    bool write_h = (r0 < N_DST0);   // h only consumed for rows < N_DST0

    {
        float4 Wg[GENRE_DIM];
        #pragma unroll
        for (int g2 = 0; g2 < GENRE_DIM; g2++)
            Wg[g2] = *(const float4*)&fcW[(144 + g2) * HID + lane * 4];
        float4 bb = *(const float4*)&fcb[lane * 4];

        int rl0 = wid * 16;
        for (int rr = 0; rr < 16; rr++) {
            int rl = rl0 + rr;
            int r = r0 + rl;
            int myc = (lane < N_CATS) ? cats[r * N_CATS + lane] : 0;
            float gv = (lane < GENRE_DIM) ? genre[(size_t)r * GENRE_DIM + lane] : 0.f;
            int id = ids[r];
            float4 acc = bb;
            #pragma unroll
            for (int c = 0; c < N_CATS; c++) {
                int v = __shfl_sync(0xffffffffu, myc, c);
                float4 tt = *(const float4*)&T[(c * CAT_VOCAB + v) * HID + lane * 4];
                acc.x += tt.x; acc.y += tt.y; acc.z += tt.z; acc.w += tt.w;
            }
            #pragma unroll
            for (int g2 = 0; g2 < GENRE_DIM; g2++) {
                float s = __shfl_sync(0xffffffffu, gv, g2);
                acc.x += s * Wg[g2].x; acc.y += s * Wg[g2].y;
                acc.z += s * Wg[g2].z; acc.w += s * Wg[g2].w;
            }
            float4 te = *(const float4*)&track_emb[(size_t)id * HID + lane * 4];
            acc.x += te.x; acc.y += te.y; acc.z += te.z; acc.w += te.w;
            if (write_h)
                *(float4*)&h_out[(size_t)r * 128 + lane * 4] = acc;
            unsigned h0, l0, h1, l1;
            pack_bf16(acc.x, acc.y, h0, l0);
            pack_bf16(acc.z, acc.w, h1, l1);
            AHi[rl * AW2 + 2 * lane]     = h0;
            AHi[rl * AW2 + 2 * lane + 1] = h1;
            ALo[rl * AW2 + 2 * lane]     = l0;
            ALo[rl * AW2 + 2 * lane + 1] = l1;
        }
    }
    q_mainloop_epilogue_bf16(AHi, ALo, BP, QW, Qb, n_words, r0);
}

// ---- plain A-resident Q GEMM (layer 1) --------------------------------------
__global__ __launch_bounds__(256, 2)
void gemm_q_ares_kernel(const float* __restrict__ A,
                        const float* __restrict__ QW,
                        const float* __restrict__ Qb,
                        unsigned* __restrict__ n_words) {
    extern __shared__ unsigned sm[];
    unsigned* AHi = sm;
    unsigned* ALo = sm + APL;
    unsigned* BP  = sm + 2 * APL;

    int tid = threadIdx.x;
    int r0 = blockIdx.x * 128;
    int row = tid >> 1, half = tid & 1;

    #pragma unroll 4
    for (int j = 0; j < 16; j++) {
        float4 v = *(const float4*)&A[(size_t)(r0 + row) * 128 + 8 * j + 4 * half];
        unsigned h0, l0, h1, l1;
        pack_bf16(v.x, v.y, h0, l0);
        pack_bf16(v.z, v.w, h1, l1);
        int w = row * AW2 + 4 * j + 2 * half;
        AHi[w] = h0; AHi[w + 1] = h1;
        ALo[w] = l0; ALo[w + 1] = l1;
    }
    q_mainloop_epilogue_bf16(AHi, ALo, BP, QW, Qb, n_words, r0);
}

// ---- W GEMM + row L2-normalize (+ optional residual), K = 256 ---------------
#define AW 9
#define PLANE (128 * AW)
__global__ __launch_bounds__(256, 2)
void gemm_wnorm_kernel(const float* __restrict__ agg,
                       const float* __restrict__ ws,
                       const float* __restrict__ hdst,
                       const float* __restrict__ W,
                       const float* __restrict__ bvec,
                       const float* __restrict__ addsrc,
                       float* __restrict__ out) {
    __shared__ unsigned SA[2][2][PLANE];
    __shared__ unsigned SB[2][2][PLANE];
    __shared__ float Ss[128][2];

    const int K = 256;
    const int NIT = K / 16;
    int tid = threadIdx.x;
    int wid = tid >> 5, lane = tid & 31;
    int g = lane >> 2, t = lane & 3;
    int warp_m = wid & 3, warp_n = wid >> 2;
    int r0 = blockIdx.x * 128;

    int lr = tid >> 1;
    int lh = tid & 1;
    int bn = tid & 127;
    int bh2 = tid >> 7;

    float iw = 1.0f / fmaxf(ws[r0 + lr], 1.0f);

    float acc[2][8][4] = {};

    auto loadA = [&](int kg, float4& v0, float4& v1) {
        if (kg < 128) {
            v0 = *(const float4*)&agg[(size_t)(r0 + lr) * 128 + kg];
            v1 = *(const float4*)&agg[(size_t)(r0 + lr) * 128 + kg + 4];
            v0.x *= iw; v0.y *= iw; v0.z *= iw; v0.w *= iw;
            v1.x *= iw; v1.y *= iw; v1.z *= iw; v1.w *= iw;
        } else {
            v0 = *(const float4*)&hdst[(size_t)(r0 + lr) * 128 + (kg - 128)];
            v1 = *(const float4*)&hdst[(size_t)(r0 + lr) * 128 + (kg - 128) + 4];
        }
    };

    float4 ra0, ra1, rb0, rb1;
    loadA(lh * 8, ra0, ra1);
    {
        const float* wp = &W[(bh2 * 8) * 128 + bn];
        rb0 = make_float4(wp[0], wp[128], wp[256], wp[384]);
        rb1 = make_float4(wp[512], wp[640], wp[768], wp[896]);
    }
    store8B(&SA[0][0][lr * AW + lh * 4], &SA[0][1][lr * AW + lh * 4], ra0, ra1);
    store8B(&SB[0][0][bn * AW + bh2 * 4], &SB[0][1][bn * AW + bh2 * 4], rb0, rb1);
    __syncthreads();

    for (int it = 0; it < NIT; it++) {
        if (it + 1 < NIT) {
            int k0 = (it + 1) * 16;
            loadA(k0 + lh * 8, ra0, ra1);
            const float* wp = &W[(k0 + bh2 * 8) * 128 + bn];
            rb0 = make_float4(wp[0], wp[128], wp[256], wp[384]);
            rb1 = make_float4(wp[512], wp[640], wp[768], wp[896]);
        }
        int cur = it & 1;
        {
            unsigned ah[2][4], al[2][4];
            #pragma unroll
            for (int mi = 0; mi < 2; mi++) {
                int rb = warp_m * 32 + mi * 16 + g;
                ah[mi][0] = SA[cur][0][rb * AW + t];
                ah[mi][1] = SA[cur][0][(rb + 8) * AW + t];
                ah[mi][2] = SA[cur][0][rb * AW + t + 4];
                ah[mi][3] = SA[cur][0][(rb + 8) * AW + t + 4];
                al[mi][0] = SA[cur][1][rb * AW + t];
                al[mi][1] = SA[cur][1][(rb + 8) * AW + t];
                al[mi][2] = SA[cur][1][rb * AW + t + 4];
                al[mi][3] = SA[cur][1][(rb + 8) * AW + t + 4];
            }
            #pragma unroll
            for (int ni = 0; ni < 8; ni++) {
                int n0 = warp_n * 64 + ni * 8 + g;
                unsigned bh[2] = {SB[cur][0][n0 * AW + t], SB[cur][0][n0 * AW + t + 4]};
                unsigned bl[2] = {SB[cur][1][n0 * AW + t], SB[cur][1][n0 * AW + t + 4]};
                #pragma unroll
                for (int mi = 0; mi < 2; mi++) {
                    mma_bf16(acc[mi][ni], ah[mi], bh);
                    mma_bf16(acc[mi][ni], al[mi], bh);
                    mma_bf16(acc[mi][ni], ah[mi], bl);
                }
            }
        }
        if (it + 1 < NIT) {
            int nb = (it + 1) & 1;
            store8B(&SA[nb][0][lr * AW + lh * 4], &SA[nb][1][lr * AW + lh * 4], ra0, ra1);
            store8B(&SB[nb][0][bn * AW + bh2 * 4], &SB[nb][1][bn * AW + bh2 * 4], rb0, rb1);
        }
        __syncthreads();
    }

    float ssl[2][2] = {};
    #pragma unroll
    for (int ni = 0; ni < 8; ni++) {
        int col = warp_n * 64 + ni * 8 + 2 * t;
        float2 bv = *(const float2*)&bvec[col];
        #pragma unroll
        for (int mi = 0; mi < 2; mi++) {
            float z0 = fmaxf(acc[mi][ni][0] + bv.x, 0.f);
            float z1 = fmaxf(acc[mi][ni][1] + bv.y, 0.f);
            float z2 = fmaxf(acc[mi][ni][2] + bv.x, 0.f);
            float z3 = fmaxf(acc[mi][ni][3] + bv.y, 0.f);
            acc[mi][ni][0] = z0; acc[mi][ni][1] = z1;
            acc[mi][ni][2] = z2; acc[mi][ni][3] = z3;
            ssl[mi][0] += z0 * z0 + z1 * z1;
            ssl[mi][1] += z2 * z2 + z3 * z3;
        }
    }
    #pragma unroll
    for (int mi = 0; mi < 2; mi++)
        #pragma unroll
        for (int h = 0; h < 2; h++) {
            float s = ssl[mi][h];
            s += __shfl_xor_sync(0xffffffffu, s, 1);
            s += __shfl_xor_sync(0xffffffffu, s, 2);
            ssl[mi][h] = s;
        }
    if (t == 0) {
        #pragma unroll
        for (int mi = 0; mi < 2; mi++) {
            int r = warp_m * 32 + mi * 16 + g;
            Ss[r][warp_n]     = ssl[mi][0];
            Ss[r + 8][warp_n] = ssl[mi][1];
        }
    }
    __syncthreads();
    #pragma unroll
    for (int mi = 0; mi < 2; mi++) {
        int rl0 = warp_m * 32 + mi * 16 + g;
        float ss0 = Ss[rl0][0] + Ss[rl0][1];
        float ss1 = Ss[rl0 + 8][0] + Ss[rl0 + 8][1];
        float in0 = (ss0 > 0.f) ? rsqrtf(ss0) : 1.0f;
        float in1 = (ss1 > 0.f) ? rsqrtf(ss1) : 1.0f;
        size_t row0 = (size_t)(r0 + rl0);
        #pragma unroll
        for (int ni = 0; ni < 8; ni++) {
            int col = warp_n * 64 + ni * 8 + 2 * t;
            float2 o0, o1;
            o0.x = acc[mi][ni][0] * in0; o0.y = acc[mi][ni][1] * in0;
            o1.x = acc[mi][ni][2] * in1; o1.y = acc[mi][ni][3] * in1;
            if (addsrc) {
                float2 a0 = *(const float2*)&addsrc[row0 * 128 + col];
                float2 a1 = *(const float2*)&addsrc[(row0 + 8) * 128 + col];
                o0.x += a0.x; o0.y += a0.y;
                o1.x += a1.x; o1.y += a1.y;
            }
            *(float2*)&out[row0 * 128 + col]       = o0;
            *(float2*)&out[(row0 + 8) * 128 + col] = o1;
        }
    }
}

// ---------------------------------------------------------------------------
// Precompute T / zeroing
// ---------------------------------------------------------------------------
__global__ void precompute_T_kernel(const float* __restrict__ cat_embs,
                                    const float* __restrict__ fcW,
                                    float* __restrict__ T) {
    int cv = blockIdx.x;
    int c = cv / CAT_VOCAB;
    int n = threadIdx.x;
    const float* e = &cat_embs[cv * CAT_DIM];
    float acc = 0.f;
    #pragma unroll
    for (int d = 0; d < CAT_DIM; d++)
        acc += __ldg(&e[d]) * fcW[(c * CAT_DIM + d) * HID + n];
    T[cv * HID + n] = acc;
}

__global__ void zero_all_kernel(float* agg0, float* ws0, float* agg1, float* ws1) {
    int i = blockIdx.x * blockDim.x + threadIdx.x;
    int st = gridDim.x * blockDim.x;
    float4 z = {0.f, 0.f, 0.f, 0.f};
    for (int j = i; j < N_DST0 * HID / 4; j += st) ((float4*)agg0)[j] = z;
    for (int j = i; j < N_DST1 * HID / 4; j += st) ((float4*)agg1)[j] = z;
    for (int j = i; j < N_DST0; j += st) ws0[j] = 0.f;
    for (int j = i; j < N_DST1; j += st) ws1[j] = 0.f;
}

__global__ void zero_R_kernel(unsigned int* R) { *R = 0u; }

// ---------------------------------------------------------------------------
// Edge aggregation: bf16 n gather (8B/lane), fp32 RED; 8 edges per warp
// ---------------------------------------------------------------------------
#define EPW 8
__global__ __launch_bounds__(256)
void edge_agg_kernel(const unsigned* __restrict__ nwords,
                     const int* __restrict__ es,
                     const int* __restrict__ ed,
                     const float* __restrict__ w,
                     float* __restrict__ agg,
                     float* __restrict__ ws,
                     int nE) {
    int warp = (blockIdx.x * blockDim.x + threadIdx.x) >> 5;
    int lane = threadIdx.x & 31;
    int e0 = warp * EPW;
    if (e0 >= nE) return;

    int s[EPW], d[EPW];
    float wt[EPW];
    #pragma unroll
    for (int i = 0; i < EPW; i++) {
        s[i]  = __ldg(&es[e0 + i]);
        d[i]  = __ldg(&ed[e0 + i]);
        wt[i] = __ldg(&w[e0 + i]);
    }
    uint2 v[EPW];
    #pragma unroll
    for (int i = 0; i < EPW; i++)
        v[i] = *(const uint2*)&nwords[(size_t)s[i] * 64 + lane * 2];
    #pragma unroll
    for (int i = 0; i < EPW; i++) {
        float a0 = __uint_as_float(v[i].x << 16);
        float a1 = __uint_as_float(v[i].x & 0xFFFF0000u);
        float a2 = __uint_as_float(v[i].y << 16);
        float a3 = __uint_as_float(v[i].y & 0xFFFF0000u);
        float* dst = &agg[(size_t)d[i] * 128 + lane * 4];
#if !defined(__CUDA_ARCH__) || __CUDA_ARCH__ >= 900
        asm volatile("red.global.add.v4.f32 [%0], {%1,%2,%3,%4};"
                     :: "l"(dst), "f"(a0 * wt[i]), "f"(a1 * wt[i]),
                        "f"(a2 * wt[i]), "f"(a3 * wt[i])
                     : "memory");
#else
        atomicAdd(dst + 0, a0 * wt[i]);
        atomicAdd(dst + 1, a1 * wt[i]);
        atomicAdd(dst + 2, a2 * wt[i]);
        atomicAdd(dst + 3, a3 * wt[i]);
#endif
    }
    if (lane == 0) {
        #pragma unroll
        for (int i = 0; i < EPW; i++)
            atomicAdd(&ws[d[i]], wt[i]);
    }
}

// ---------------------------------------------------------------------------
// Scores / loss / AUC
// ---------------------------------------------------------------------------
__global__ __launch_bounds__(256)
void score_kernel(const float* __restrict__ hi,
                  const int* __restrict__ ps, const int* __restrict__ pd,
                  const int* __restrict__ ns, const int* __restrict__ nd,
                  const int* __restrict__ nids,
                  const float* __restrict__ bias,
                  float* __restrict__ scores) {
    int wid = (blockIdx.x * blockDim.x + threadIdx.x) >> 5;
    int lane = threadIdx.x & 31;
    if (wid >= NS) return;
    int s, d;
    if (wid < NP) { s = ps[wid]; d = pd[wid]; }
    else          { s = ns[wid - NP]; d = nd[wid - NP]; }
    float4 a = *(const float4*)&hi[(size_t)s * 128 + lane * 4];
    float4 b = *(const float4*)&hi[(size_t)d * 128 + lane * 4];
    float p = a.x * b.x + a.y * b.y + a.z * b.z + a.w * b.w;
    #pragma unroll
    for (int off = 16; off > 0; off >>= 1)
        p += __shfl_xor_sync(0xffffffffu, p, off);
    if (lane == 0)
        scores[wid] = p + bias[nids[s]] + bias[nids[d]];
}

__global__ void loss_kernel(const float* __restrict__ scores, float* __restrict__ out) {
    int i = blockIdx.x * blockDim.x + threadIdx.x;
    if (i < NP)
        out[i] = fmaxf(scores[NP + i] - scores[i] + 1.0f, 0.0f);
}

#define AUC_JCH 2048
__global__ __launch_bounds__(256)
void auc_count_kernel(const float* __restrict__ scores, unsigned int* __restrict__ R) {
    __shared__ float ss[AUC_JCH];
    int tid = threadIdx.x;
    int j0 = blockIdx.y * AUC_JCH;
    for (int j = tid; j < AUC_JCH; j += blockDim.x) ss[j] = scores[j0 + j];
    __syncthreads();
    int i = blockIdx.x * blockDim.x + tid;
    float my = scores[i];
    unsigned int cnt = 0;
    #pragma unroll 4
    for (int jj = 0; jj < AUC_JCH; jj++) {
        float v = ss[jj];
        int j = j0 + jj;
        cnt += (v < my) || (v == my && j < i);
    }
    #pragma unroll
    for (int off = 16; off > 0; off >>= 1)
        cnt += __shfl_xor_sync(0xffffffffu, cnt, off);
    if ((tid & 31) == 0) atomicAdd(R, cnt);
}

__global__ void auc_final_kernel(const unsigned int* __restrict__ R, float* __restrict__ out) {
    double r = (double)(*R);
    double npos = (double)NP, nneg = (double)NP;
    out[0] = (float)((r - npos * (npos - 1.0) * 0.5) / (npos * nneg));
}

// ---------------------------------------------------------------------------
// Launch
// ---------------------------------------------------------------------------
extern "C" void kernel_launch(void* const* d_in, const int* in_sizes, int n_in,
                              void* d_out, int out_size) {
    const int*   src0_id   = (const int*)  d_in[0];
    const int*   src0_cats = (const int*)  d_in[1];
    const float* src0_genre= (const float*)d_in[2];
    const int*   es0       = (const int*)  d_in[3];
    const int*   ed0       = (const int*)  d_in[4];
    const float* w0        = (const float*)d_in[5];
    const int*   es1       = (const int*)  d_in[6];
    const int*   ed1       = (const int*)  d_in[7];
    const float* w1        = (const float*)d_in[8];
    const int*   pos_src   = (const int*)  d_in[9];
    const int*   pos_dst   = (const int*)  d_in[10];
    const int*   neg_src   = (const int*)  d_in[11];
    const int*   neg_dst   = (const int*)  d_in[12];
    const int*   seed_nids = (const int*)  d_in[13];
    const float* track_emb = (const float*)d_in[14];
    const float* cat_embs  = (const float*)d_in[15];
    const float* fc_W      = (const float*)d_in[16];
    const float* fc_b      = (const float*)d_in[17];
    const float* Q0_W      = (const float*)d_in[18];
    const float* Q0_b      = (const float*)d_in[19];
    const float* W0_W      = (const float*)d_in[20];
    const float* W0_b      = (const float*)d_in[21];
    const float* Q1_W      = (const float*)d_in[22];
    const float* Q1_b      = (const float*)d_in[23];
    const float* W1_W      = (const float*)d_in[24];
    const float* W1_b      = (const float*)d_in[25];
    const float* bias      = (const float*)d_in[26];
    float* out = (float*)d_out;

    float *p_T, *p_h, *p_agg0, *p_ws0, *p_h1, *p_agg1, *p_ws1, *p_hitem, *p_scores;
    unsigned *p_nb;
    unsigned int* p_R;
    cudaGetSymbolAddress((void**)&p_T,     g_T);
    cudaGetSymbolAddress((void**)&p_h,     g_h);
    cudaGetSymbolAddress((void**)&p_nb,    g_nb);
    cudaGetSymbolAddress((void**)&p_agg0,  g_agg0);
    cudaGetSymbolAddress((void**)&p_ws0,   g_ws0);
    cudaGetSymbolAddress((void**)&p_h1,    g_h1);
    cudaGetSymbolAddress((void**)&p_agg1,  g_agg1);
    cudaGetSymbolAddress((void**)&p_ws1,   g_ws1);
    cudaGetSymbolAddress((void**)&p_hitem, g_hitem);
    cudaGetSymbolAddress((void**)&p_scores,g_scores);
    cudaGetSymbolAddress((void**)&p_R,     g_rank_sum);

    cudaFuncSetAttribute(fused_proj_q_kernel,
                         cudaFuncAttributeMaxDynamicSharedMemorySize, Q_SMEM_BYTES);
    cudaFuncSetAttribute(gemm_q_ares_kernel,
                         cudaFuncAttributeMaxDynamicSharedMemorySize, Q_SMEM_BYTES);

    // ncu captures launch #4 (empirical) -> fused_proj_q this round
    zero_all_kernel<<<1024, 256>>>(p_agg0, p_ws0, p_agg1, p_ws1);                        // 1
    precompute_T_kernel<<<N_CATS * CAT_VOCAB, 128>>>(cat_embs, fc_W, p_T);               // 2
    zero_R_kernel<<<1, 1>>>(p_R);                                                        // 3
    fused_proj_q_kernel<<<N_SRC0 / 128, 256, Q_SMEM_BYTES>>>(                            // 4 (ncu)
        src0_id, src0_cats, src0_genre, p_T, fc_W, fc_b, track_emb,
        Q0_W, Q0_b, p_h, p_nb);
    edge_agg_kernel<<<NE0 / (EPW * 8), 256>>>(p_nb, es0, ed0, w0, p_agg0, p_ws0, NE0);   // 5
    gemm_wnorm_kernel<<<N_DST0 / 128, 256>>>(p_agg0, p_ws0, p_h, W0_W, W0_b,             // 6
                                             nullptr, p_h1);
    gemm_q_ares_kernel<<<N_DST0 / 128, 256, Q_SMEM_BYTES>>>(p_h1, Q1_W, Q1_b, p_nb);     // 7
    edge_agg_kernel<<<NE1 / (EPW * 8), 256>>>(p_nb, es1, ed1, w1, p_agg1, p_ws1, NE1);   // 8
    gemm_wnorm_kernel<<<N_DST1 / 128, 256>>>(p_agg1, p_ws1, p_h1, W1_W, W1_b,            // 9
                                             p_h, p_hitem);

    score_kernel<<<NS / 8, 256>>>(p_hitem, pos_src, pos_dst, neg_src, neg_dst,
                                  seed_nids, bias, p_scores);
    loss_kernel<<<NP / 256, 256>>>(p_scores, out);

    dim3 auc_grid(NP / 256, NS / AUC_JCH);
    auc_count_kernel<<<auc_grid, 256>>>(p_scores, p_R);
    if (out_size >= NP + 1)
        auc_final_kernel<<<1, 1>>>(p_R, out + NP);
}

// round 13
// speedup vs baseline: 1.6411x; 1.0725x over previous
#include <cuda_runtime.h>
#include <cuda_bf16.h>
#include <math.h>

// ---------------------------------------------------------------------------
// Problem constants
// ---------------------------------------------------------------------------
#define N_SRC0   262144
#define N_DST0   65536
#define N_DST1   8192
#define HID      128
#define N_CATS   9
#define CAT_VOCAB 101
#define CAT_DIM  16
#define GENRE_DIM 20
#define NE0      1048576
#define NE1      131072
#define NP       8192
#define NS       16384

// ---------------------------------------------------------------------------
// Static device scratch
// ---------------------------------------------------------------------------
__device__ float g_T[N_CATS * CAT_VOCAB * HID];
__device__ float g_h[(size_t)N_SRC0 * HID];          // only rows < N_DST0 written
__device__ unsigned g_nb[(size_t)N_SRC0 * 64];       // n as bf16x2 words
__device__ float g_agg0[(size_t)N_DST0 * HID];
__device__ float g_ws0[N_DST0];
__device__ float g_h1[(size_t)N_DST0 * HID];
__device__ float g_agg1[(size_t)N_DST1 * HID];
__device__ float g_ws1[N_DST1];
__device__ float g_hitem[(size_t)N_DST1 * HID];
__device__ float g_scores[NS];
__device__ unsigned int g_rank_sum;

// ---------------------------------------------------------------------------
// bf16 split helpers
// ---------------------------------------------------------------------------
__device__ __forceinline__ void pack_bf16(float x0, float x1, unsigned& hi, unsigned& lo) {
    unsigned hw;
    asm("cvt.rn.bf16x2.f32 %0, %1, %2;" : "=r"(hw) : "f"(x1), "f"(x0));
    float h0 = __uint_as_float(hw << 16);
    float h1 = __uint_as_float(hw & 0xFFFF0000u);
    float r0 = x0 - h0;
    float r1 = x1 - h1;
    unsigned lw;
    asm("cvt.rn.bf16x2.f32 %0, %1, %2;" : "=r"(lw) : "f"(r1), "f"(r0));
    hi = hw; lo = lw;
}

__device__ __forceinline__ unsigned pack1_bf16(float x0, float x1) {
    unsigned w;
    asm("cvt.rn.bf16x2.f32 %0, %1, %2;" : "=r"(w) : "f"(x1), "f"(x0));
    return w;
}

__device__ __forceinline__ void mma_bf16(float* c, const unsigned* a, const unsigned* b) {
    asm volatile(
        "mma.sync.aligned.m16n8k16.row.col.f32.bf16.bf16.f32 "
        "{%0,%1,%2,%3}, {%4,%5,%6,%7}, {%8,%9}, {%0,%1,%2,%3};"
        : "+f"(c[0]), "+f"(c[1]), "+f"(c[2]), "+f"(c[3])
        : "r"(a[0]), "r"(a[1]), "r"(a[2]), "r"(a[3]), "r"(b[0]), "r"(b[1]));
}

// ---------------------------------------------------------------------------
// A-resident GEMM layout (A stride 68 u32, B per-iter stride 9 u32)
// ---------------------------------------------------------------------------
#define AW2 68
#define APL (128 * AW2)
#define BPL (128 * 9)
#define Q_SMEM_U32 (2 * APL + 4 * BPL)
#define Q_SMEM_BYTES (Q_SMEM_U32 * 4)

__device__ __forceinline__ void tile_ares(const unsigned* __restrict__ AHi,
                                          const unsigned* __restrict__ ALo,
                                          const unsigned* __restrict__ Bhi,
                                          const unsigned* __restrict__ Blo,
                                          float acc[2][8][4], int kw,
                                          int g, int t, int warp_m, int warp_n) {
    unsigned ah[2][4], al[2][4];
    #pragma unroll
    for (int mi = 0; mi < 2; mi++) {
        int rb = warp_m * 32 + mi * 16 + g;
        ah[mi][0] = AHi[rb * AW2 + kw + t];
        ah[mi][1] = AHi[(rb + 8) * AW2 + kw + t];
        ah[mi][2] = AHi[rb * AW2 + kw + t + 4];
        ah[mi][3] = AHi[(rb + 8) * AW2 + kw + t + 4];
        al[mi][0] = ALo[rb * AW2 + kw + t];
        al[mi][1] = ALo[(rb + 8) * AW2 + kw + t];
        al[mi][2] = ALo[rb * AW2 + kw + t + 4];
        al[mi][3] = ALo[(rb + 8) * AW2 + kw + t + 4];
    }
    #pragma unroll
    for (int ni = 0; ni < 8; ni++) {
        int n0 = warp_n * 64 + ni * 8 + g;
        unsigned bh[2] = {Bhi[n0 * 9 + t], Bhi[n0 * 9 + t + 4]};
        unsigned bl[2] = {Blo[n0 * 9 + t], Blo[n0 * 9 + t + 4]};
        #pragma unroll
        for (int mi = 0; mi < 2; mi++) {
            mma_bf16(acc[mi][ni], ah[mi], bh);
            mma_bf16(acc[mi][ni], al[mi], bh);
            mma_bf16(acc[mi][ni], ah[mi], bl);
        }
    }
}

__device__ __forceinline__ void store8B(unsigned* hi, unsigned* lo, float4 v0, float4 v1) {
    unsigned h, l;
    pack_bf16(v0.x, v0.y, h, l); hi[0] = h; lo[0] = l;
    pack_bf16(v0.z, v0.w, h, l); hi[1] = h; lo[1] = l;
    pack_bf16(v1.x, v1.y, h, l); hi[2] = h; lo[2] = l;
    pack_bf16(v1.z, v1.w, h, l); hi[3] = h; lo[3] = l;
}

// B-loop + epilogue -> writes relu(acc+b) as bf16x2 words (n buffer)
__device__ __forceinline__ void q_mainloop_epilogue_bf16(
    unsigned* AHi, unsigned* ALo, unsigned* BP,
    const float* __restrict__ W, const float* __restrict__ bvec,
    unsigned* __restrict__ n_words, int r0) {
    int tid = threadIdx.x;
    int wid = tid >> 5, lane = tid & 31;
    int g = lane >> 2, t = lane & 3;
    int warp_m = wid & 3, warp_n = wid >> 2;
    int bn = tid & 127, bh2 = tid >> 7;

    const int NIT = 8;
    float acc[2][8][4] = {};

    {
        const float* wp = &W[(bh2 * 8) * 128 + bn];
        float4 rb0 = make_float4(wp[0], wp[128], wp[256], wp[384]);
        float4 rb1 = make_float4(wp[512], wp[640], wp[768], wp[896]);
        store8B(&BP[bn * 9 + bh2 * 4], &BP[BPL + bn * 9 + bh2 * 4], rb0, rb1);
    }
    __syncthreads();

    for (int it = 0; it < NIT; it++) {
        float4 rb0, rb1;
        if (it + 1 < NIT) {
            int k0 = (it + 1) * 16;
            const float* wp = &W[(k0 + bh2 * 8) * 128 + bn];
            rb0 = make_float4(wp[0], wp[128], wp[256], wp[384]);
            rb1 = make_float4(wp[512], wp[640], wp[768], wp[896]);
        }
        int cur = it & 1;
        tile_ares(AHi, ALo, BP + cur * 2 * BPL, BP + cur * 2 * BPL + BPL,
                  acc, it * 8, g, t, warp_m, warp_n);
        if (it + 1 < NIT) {
            int nb = (it + 1) & 1;
            store8B(&BP[nb * 2 * BPL + bn * 9 + bh2 * 4],
                    &BP[nb * 2 * BPL + BPL + bn * 9 + bh2 * 4], rb0, rb1);
        }
        __syncthreads();
    }

    #pragma unroll
    for (int ni = 0; ni < 8; ni++) {
        int col = warp_n * 64 + ni * 8 + 2 * t;   // even
        float2 bv = *(const float2*)&bvec[col];
        int wcol = col >> 1;                       // word index in row (64 words)
        #pragma unroll
        for (int mi = 0; mi < 2; mi++) {
            int row0 = r0 + warp_m * 32 + mi * 16 + g;
            float z0 = fmaxf(acc[mi][ni][0] + bv.x, 0.f);
            float z1 = fmaxf(acc[mi][ni][1] + bv.y, 0.f);
            float z2 = fmaxf(acc[mi][ni][2] + bv.x, 0.f);
            float z3 = fmaxf(acc[mi][ni][3] + bv.y, 0.f);
            n_words[(size_t)row0 * 64 + wcol]       = pack1_bf16(z0, z1);
            n_words[(size_t)(row0 + 8) * 64 + wcol] = pack1_bf16(z2, z3);
        }
    }
}

// ---- FUSED proj + Q0 GEMM, batched proj phase for deep MLP ------------------
__global__ __launch_bounds__(256, 2)
void fused_proj_q_kernel(const int* __restrict__ ids,
                         const int* __restrict__ cats,
                         const float* __restrict__ genre,
                         const float* __restrict__ T,
                         const float* __restrict__ fcW,
                         const float* __restrict__ fcb,
                         const float* __restrict__ track_emb,
                         const float* __restrict__ QW,
                         const float* __restrict__ Qb,
                         float* __restrict__ h_out,
                         unsigned* __restrict__ n_words) {
    extern __shared__ unsigned sm[];
    unsigned* AHi = sm;
    unsigned* ALo = sm + APL;
    unsigned* BP  = sm + 2 * APL;
    float* WgS = (float*)BP;          // 20*128 floats, reclaimed by B planes later

    int tid = threadIdx.x;
    int wid = tid >> 5, lane = tid & 31;
    int r0 = blockIdx.x * 128;
    bool write_h = (r0 < N_DST0);

    // stage genre weights into smem (frees ~80 regs for the batched gathers)
    for (int i = tid; i < GENRE_DIM * HID; i += 256)
        WgS[i] = fcW[(144 + i / HID) * HID + (i % HID)];
    __syncthreads();

    {
        float4 bb = *(const float4*)&fcb[lane * 4];
        int rl0 = wid * 16;

        // prefetch all 16 rows' metadata (48 independent loads in flight)
        int   myc16[16];
        float gv16[16];
        int   id16[16];
        #pragma unroll
        for (int rr = 0; rr < 16; rr++) {
            int r = r0 + rl0 + rr;
            myc16[rr] = (lane < N_CATS) ? cats[r * N_CATS + lane] : 0;
            gv16[rr]  = (lane < GENRE_DIM) ? genre[(size_t)r * GENRE_DIM + lane] : 0.f;
            id16[rr]  = __ldg(&ids[r]);
        }

        // process rows in groups of 4: batched gathers for MLP
        #pragma unroll
        for (int g4 = 0; g4 < 4; g4++) {
            float4 acc[4], te[4];
            #pragma unroll
            for (int q = 0; q < 4; q++) {
                acc[q] = bb;
                te[q] = *(const float4*)&track_emb[(size_t)id16[g4 * 4 + q] * HID + lane * 4];
            }
            #pragma unroll
            for (int c = 0; c < N_CATS; c++) {
                float4 tv[4];
                #pragma unroll
                for (int q = 0; q < 4; q++) {
                    int v = __shfl_sync(0xffffffffu, myc16[g4 * 4 + q], c);
                    tv[q] = *(const float4*)&T[(c * CAT_VOCAB + v) * HID + lane * 4];
                }
                #pragma unroll
                for (int q = 0; q < 4; q++) {
                    acc[q].x += tv[q].x; acc[q].y += tv[q].y;
                    acc[q].z += tv[q].z; acc[q].w += tv[q].w;
                }
            }
            #pragma unroll
            for (int g2 = 0; g2 < GENRE_DIM; g2++) {
                float4 wg = *(const float4*)&WgS[g2 * HID + lane * 4];
                #pragma unroll
                for (int q = 0; q < 4; q++) {
                    float s = __shfl_sync(0xffffffffu, gv16[g4 * 4 + q], g2);
                    acc[q].x += s * wg.x; acc[q].y += s * wg.y;
                    acc[q].z += s * wg.z; acc[q].w += s * wg.w;
                }
            }
            #pragma unroll
            for (int q = 0; q < 4; q++) {
                int rl = rl0 + g4 * 4 + q;
                acc[q].x += te[q].x; acc[q].y += te[q].y;
                acc[q].z += te[q].z; acc[q].w += te[q].w;
                if (write_h)
                    *(float4*)&h_out[(size_t)(r0 + rl) * 128 + lane * 4] = acc[q];
                unsigned h0, l0, h1, l1;
                pack_bf16(acc[q].x, acc[q].y, h0, l0);
                pack_bf16(acc[q].z, acc[q].w, h1, l1);
                AHi[rl * AW2 + 2 * lane]     = h0;
                AHi[rl * AW2 + 2 * lane + 1] = h1;
                ALo[rl * AW2 + 2 * lane]     = l0;
                ALo[rl * AW2 + 2 * lane + 1] = l1;
            }
        }
    }
    __syncthreads();   // WgS region is reclaimed by B planes in the mainloop
    q_mainloop_epilogue_bf16(AHi, ALo, BP, QW, Qb, n_words, r0);
}

// ---- plain A-resident Q GEMM (layer 1) --------------------------------------
__global__ __launch_bounds__(256, 2)
void gemm_q_ares_kernel(const float* __restrict__ A,
                        const float* __restrict__ QW,
                        const float* __restrict__ Qb,
                        unsigned* __restrict__ n_words) {
    extern __shared__ unsigned sm[];
    unsigned* AHi = sm;
    unsigned* ALo = sm + APL;
    unsigned* BP  = sm + 2 * APL;

    int tid = threadIdx.x;
    int r0 = blockIdx.x * 128;
    int row = tid >> 1, half = tid & 1;

    #pragma unroll 4
    for (int j = 0; j < 16; j++) {
        float4 v = *(const float4*)&A[(size_t)(r0 + row) * 128 + 8 * j + 4 * half];
        unsigned h0, l0, h1, l1;
        pack_bf16(v.x, v.y, h0, l0);
        pack_bf16(v.z, v.w, h1, l1);
        int w = row * AW2 + 4 * j + 2 * half;
        AHi[w] = h0; AHi[w + 1] = h1;
        ALo[w] = l0; ALo[w + 1] = l1;
    }
    q_mainloop_epilogue_bf16(AHi, ALo, BP, QW, Qb, n_words, r0);
}

// ---- W GEMM + row L2-normalize (+ optional residual), K = 256 ---------------
#define AW 9
#define PLANE (128 * AW)
__global__ __launch_bounds__(256, 2)
void gemm_wnorm_kernel(const float* __restrict__ agg,
                       const float* __restrict__ ws,
                       const float* __restrict__ hdst,
                       const float* __restrict__ W,
                       const float* __restrict__ bvec,
                       const float* __restrict__ addsrc,
                       float* __restrict__ out) {
    __shared__ unsigned SA[2][2][PLANE];
    __shared__ unsigned SB[2][2][PLANE];
    __shared__ float Ss[128][2];

    const int K = 256;
    const int NIT = K / 16;
    int tid = threadIdx.x;
    int wid = tid >> 5, lane = tid & 31;
    int g = lane >> 2, t = lane & 3;
    int warp_m = wid & 3, warp_n = wid >> 2;
    int r0 = blockIdx.x * 128;

    int lr = tid >> 1;
    int lh = tid & 1;
    int bn = tid & 127;
    int bh2 = tid >> 7;

    float iw = 1.0f / fmaxf(ws[r0 + lr], 1.0f);

    float acc[2][8][4] = {};

    auto loadA = [&](int kg, float4& v0, float4& v1) {
        if (kg < 128) {
            v0 = *(const float4*)&agg[(size_t)(r0 + lr) * 128 + kg];
            v1 = *(const float4*)&agg[(size_t)(r0 + lr) * 128 + kg + 4];
            v0.x *= iw; v0.y *= iw; v0.z *= iw; v0.w *= iw;
            v1.x *= iw; v1.y *= iw; v1.z *= iw; v1.w *= iw;
        } else {
            v0 = *(const float4*)&hdst[(size_t)(r0 + lr) * 128 + (kg - 128)];
            v1 = *(const float4*)&hdst[(size_t)(r0 + lr) * 128 + (kg - 128) + 4];
        }
    };

    float4 ra0, ra1, rb0, rb1;
    loadA(lh * 8, ra0, ra1);
    {
        const float* wp = &W[(bh2 * 8) * 128 + bn];
        rb0 = make_float4(wp[0], wp[128], wp[256], wp[384]);
        rb1 = make_float4(wp[512], wp[640], wp[768], wp[896]);
    }
    store8B(&SA[0][0][lr * AW + lh * 4], &SA[0][1][lr * AW + lh * 4], ra0, ra1);
    store8B(&SB[0][0][bn * AW + bh2 * 4], &SB[0][1][bn * AW + bh2 * 4], rb0, rb1);
    __syncthreads();

    for (int it = 0; it < NIT; it++) {
        if (it + 1 < NIT) {
            int k0 = (it + 1) * 16;
            loadA(k0 + lh * 8, ra0, ra1);
            const float* wp = &W[(k0 + bh2 * 8) * 128 + bn];
            rb0 = make_float4(wp[0], wp[128], wp[256], wp[384]);
            rb1 = make_float4(wp[512], wp[640], wp[768], wp[896]);
        }
        int cur = it & 1;
        {
            unsigned ah[2][4], al[2][4];
            #pragma unroll
            for (int mi = 0; mi < 2; mi++) {
                int rb = warp_m * 32 + mi * 16 + g;
                ah[mi][0] = SA[cur][0][rb * AW + t];
                ah[mi][1] = SA[cur][0][(rb + 8) * AW + t];
                ah[mi][2] = SA[cur][0][rb * AW + t + 4];
                ah[mi][3] = SA[cur][0][(rb + 8) * AW + t + 4];
                al[mi][0] = SA[cur][1][rb * AW + t];
                al[mi][1] = SA[cur][1][(rb + 8) * AW + t];
                al[mi][2] = SA[cur][1][rb * AW + t + 4];
                al[mi][3] = SA[cur][1][(rb + 8) * AW + t + 4];
            }
            #pragma unroll
            for (int ni = 0; ni < 8; ni++) {
                int n0 = warp_n * 64 + ni * 8 + g;
                unsigned bh[2] = {SB[cur][0][n0 * AW + t], SB[cur][0][n0 * AW + t + 4]};
                unsigned bl[2] = {SB[cur][1][n0 * AW + t], SB[cur][1][n0 * AW + t + 4]};
                #pragma unroll
                for (int mi = 0; mi < 2; mi++) {
                    mma_bf16(acc[mi][ni], ah[mi], bh);
                    mma_bf16(acc[mi][ni], al[mi], bh);
                    mma_bf16(acc[mi][ni], ah[mi], bl);
                }
            }
        }
        if (it + 1 < NIT) {
            int nb = (it + 1) & 1;
            store8B(&SA[nb][0][lr * AW + lh * 4], &SA[nb][1][lr * AW + lh * 4], ra0, ra1);
            store8B(&SB[nb][0][bn * AW + bh2 * 4], &SB[nb][1][bn * AW + bh2 * 4], rb0, rb1);
        }
        __syncthreads();
    }

    float ssl[2][2] = {};
    #pragma unroll
    for (int ni = 0; ni < 8; ni++) {
        int col = warp_n * 64 + ni * 8 + 2 * t;
        float2 bv = *(const float2*)&bvec[col];
        #pragma unroll
        for (int mi = 0; mi < 2; mi++) {
            float z0 = fmaxf(acc[mi][ni][0] + bv.x, 0.f);
            float z1 = fmaxf(acc[mi][ni][1] + bv.y, 0.f);
            float z2 = fmaxf(acc[mi][ni][2] + bv.x, 0.f);
            float z3 = fmaxf(acc[mi][ni][3] + bv.y, 0.f);
            acc[mi][ni][0] = z0; acc[mi][ni][1] = z1;
            acc[mi][ni][2] = z2; acc[mi][ni][3] = z3;
            ssl[mi][0] += z0 * z0 + z1 * z1;
            ssl[mi][1] += z2 * z2 + z3 * z3;
        }
    }
    #pragma unroll
    for (int mi = 0; mi < 2; mi++)
        #pragma unroll
        for (int h = 0; h < 2; h++) {
            float s = ssl[mi][h];
            s += __shfl_xor_sync(0xffffffffu, s, 1);
            s += __shfl_xor_sync(0xffffffffu, s, 2);
            ssl[mi][h] = s;
        }
    if (t == 0) {
        #pragma unroll
        for (int mi = 0; mi < 2; mi++) {
            int r = warp_m * 32 + mi * 16 + g;
            Ss[r][warp_n]     = ssl[mi][0];
            Ss[r + 8][warp_n] = ssl[mi][1];
        }
    }
    __syncthreads();
    #pragma unroll
    for (int mi = 0; mi < 2; mi++) {
        int rl0 = warp_m * 32 + mi * 16 + g;
        float ss0 = Ss[rl0][0] + Ss[rl0][1];
        float ss1 = Ss[rl0 + 8][0] + Ss[rl0 + 8][1];
        float in0 = (ss0 > 0.f) ? rsqrtf(ss0) : 1.0f;
        float in1 = (ss1 > 0.f) ? rsqrtf(ss1) : 1.0f;
        size_t row0 = (size_t)(r0 + rl0);
        #pragma unroll
        for (int ni = 0; ni < 8; ni++) {
            int col = warp_n * 64 + ni * 8 + 2 * t;
            float2 o0, o1;
            o0.x = acc[mi][ni][0] * in0; o0.y = acc[mi][ni][1] * in0;
            o1.x = acc[mi][ni][2] * in1; o1.y = acc[mi][ni][3] * in1;
            if (addsrc) {
                float2 a0 = *(const float2*)&addsrc[row0 * 128 + col];
                float2 a1 = *(const float2*)&addsrc[(row0 + 8) * 128 + col];
                o0.x += a0.x; o0.y += a0.y;
                o1.x += a1.x; o1.y += a1.y;
            }
            *(float2*)&out[row0 * 128 + col]       = o0;
            *(float2*)&out[(row0 + 8) * 128 + col] = o1;
        }
    }
}

// ---------------------------------------------------------------------------
// Precompute T / zeroing
// ---------------------------------------------------------------------------
__global__ void precompute_T_kernel(const float* __restrict__ cat_embs,
                                    const float* __restrict__ fcW,
                                    float* __restrict__ T) {
    int cv = blockIdx.x;
    int c = cv / CAT_VOCAB;
    int n = threadIdx.x;
    const float* e = &cat_embs[cv * CAT_DIM];
    float acc = 0.f;
    #pragma unroll
    for (int d = 0; d < CAT_DIM; d++)
        acc += __ldg(&e[d]) * fcW[(c * CAT_DIM + d) * HID + n];
    T[cv * HID + n] = acc;
}

__global__ void zero_all_kernel(float* agg0, float* ws0, float* agg1, float* ws1) {
    int i = blockIdx.x * blockDim.x + threadIdx.x;
    int st = gridDim.x * blockDim.x;
    float4 z = {0.f, 0.f, 0.f, 0.f};
    for (int j = i; j < N_DST0 * HID / 4; j += st) ((float4*)agg0)[j] = z;
    for (int j = i; j < N_DST1 * HID / 4; j += st) ((float4*)agg1)[j] = z;
    for (int j = i; j < N_DST0; j += st) ws0[j] = 0.f;
    for (int j = i; j < N_DST1; j += st) ws1[j] = 0.f;
}

__global__ void zero_R_kernel(unsigned int* R) { *R = 0u; }

// ---------------------------------------------------------------------------
// Edge aggregation: bf16 n gather (8B/lane), fp32 RED; 8 edges per warp
// ---------------------------------------------------------------------------
#define EPW 8
__global__ __launch_bounds__(256)
void edge_agg_kernel(const unsigned* __restrict__ nwords,
                     const int* __restrict__ es,
                     const int* __restrict__ ed,
                     const float* __restrict__ w,
                     float* __restrict__ agg,
                     float* __restrict__ ws,
                     int nE) {
    int warp = (blockIdx.x * blockDim.x + threadIdx.x) >> 5;
    int lane = threadIdx.x & 31;
    int e0 = warp * EPW;
    if (e0 >= nE) return;

    int s[EPW], d[EPW];
    float wt[EPW];
    #pragma unroll
    for (int i = 0; i < EPW; i++) {
        s[i]  = __ldg(&es[e0 + i]);
        d[i]  = __ldg(&ed[e0 + i]);
        wt[i] = __ldg(&w[e0 + i]);
    }
    uint2 v[EPW];
    #pragma unroll
    for (int i = 0; i < EPW; i++)
        v[i] = *(const uint2*)&nwords[(size_t)s[i] * 64 + lane * 2];
    #pragma unroll
    for (int i = 0; i < EPW; i++) {
        float a0 = __uint_as_float(v[i].x << 16);
        float a1 = __uint_as_float(v[i].x & 0xFFFF0000u);
        float a2 = __uint_as_float(v[i].y << 16);
        float a3 = __uint_as_float(v[i].y & 0xFFFF0000u);
        float* dst = &agg[(size_t)d[i] * 128 + lane * 4];
#if !defined(__CUDA_ARCH__) || __CUDA_ARCH__ >= 900
        asm volatile("red.global.add.v4.f32 [%0], {%1,%2,%3,%4};"
                     :: "l"(dst), "f"(a0 * wt[i]), "f"(a1 * wt[i]),
                        "f"(a2 * wt[i]), "f"(a3 * wt[i])
                     : "memory");
#else
        atomicAdd(dst + 0, a0 * wt[i]);
        atomicAdd(dst + 1, a1 * wt[i]);
        atomicAdd(dst + 2, a2 * wt[i]);
        atomicAdd(dst + 3, a3 * wt[i]);
#endif
    }
    if (lane == 0) {
        #pragma unroll
        for (int i = 0; i < EPW; i++)
            atomicAdd(&ws[d[i]], wt[i]);
    }
}

// ---------------------------------------------------------------------------
// Scores / loss / AUC
// ---------------------------------------------------------------------------
__global__ __launch_bounds__(256)
void score_kernel(const float* __restrict__ hi,
                  const int* __restrict__ ps, const int* __restrict__ pd,
                  const int* __restrict__ ns, const int* __restrict__ nd,
                  const int* __restrict__ nids,
                  const float* __restrict__ bias,
                  float* __restrict__ scores) {
    int wid = (blockIdx.x * blockDim.x + threadIdx.x) >> 5;
    int lane = threadIdx.x & 31;
    if (wid >= NS) return;
    int s, d;
    if (wid < NP) { s = ps[wid]; d = pd[wid]; }
    else          { s = ns[wid - NP]; d = nd[wid - NP]; }
    float4 a = *(const float4*)&hi[(size_t)s * 128 + lane * 4];
    float4 b = *(const float4*)&hi[(size_t)d * 128 + lane * 4];
    float p = a.x * b.x + a.y * b.y + a.z * b.z + a.w * b.w;
    #pragma unroll
    for (int off = 16; off > 0; off >>= 1)
        p += __shfl_xor_sync(0xffffffffu, p, off);
    if (lane == 0)
        scores[wid] = p + bias[nids[s]] + bias[nids[d]];
}

__global__ void loss_kernel(const float* __restrict__ scores, float* __restrict__ out) {
    int i = blockIdx.x * blockDim.x + threadIdx.x;
    if (i < NP)
        out[i] = fmaxf(scores[NP + i] - scores[i] + 1.0f, 0.0f);
}

#define AUC_JCH 2048
__global__ __launch_bounds__(256)
void auc_count_kernel(const float* __restrict__ scores, unsigned int* __restrict__ R) {
    __shared__ float ss[AUC_JCH];
    int tid = threadIdx.x;
    int j0 = blockIdx.y * AUC_JCH;
    for (int j = tid; j < AUC_JCH; j += blockDim.x) ss[j] = scores[j0 + j];
    __syncthreads();
    int i = blockIdx.x * blockDim.x + tid;
    float my = scores[i];
    unsigned int cnt = 0;
    #pragma unroll 4
    for (int jj = 0; jj < AUC_JCH; jj++) {
        float v = ss[jj];
        int j = j0 + jj;
        cnt += (v < my) || (v == my && j < i);
    }
    #pragma unroll
    for (int off = 16; off > 0; off >>= 1)
        cnt += __shfl_xor_sync(0xffffffffu, cnt, off);
    if ((tid & 31) == 0) atomicAdd(R, cnt);
}

__global__ void auc_final_kernel(const unsigned int* __restrict__ R, float* __restrict__ out) {
    double r = (double)(*R);
    double npos = (double)NP, nneg = (double)NP;
    out[0] = (float)((r - npos * (npos - 1.0) * 0.5) / (npos * nneg));
}

// ---------------------------------------------------------------------------
// Launch
// ---------------------------------------------------------------------------
extern "C" void kernel_launch(void* const* d_in, const int* in_sizes, int n_in,
                              void* d_out, int out_size) {
    const int*   src0_id   = (const int*)  d_in[0];
    const int*   src0_cats = (const int*)  d_in[1];
    const float* src0_genre= (const float*)d_in[2];
    const int*   es0       = (const int*)  d_in[3];
    const int*   ed0       = (const int*)  d_in[4];
    const float* w0        = (const float*)d_in[5];
    const int*   es1       = (const int*)  d_in[6];
    const int*   ed1       = (const int*)  d_in[7];
    const float* w1        = (const float*)d_in[8];
    const int*   pos_src   = (const int*)  d_in[9];
    const int*   pos_dst   = (const int*)  d_in[10];
    const int*   neg_src   = (const int*)  d_in[11];
    const int*   neg_dst   = (const int*)  d_in[12];
    const int*   seed_nids = (const int*)  d_in[13];
    const float* track_emb = (const float*)d_in[14];
    const float* cat_embs  = (const float*)d_in[15];
    const float* fc_W      = (const float*)d_in[16];
    const float* fc_b      = (const float*)d_in[17];
    const float* Q0_W      = (const float*)d_in[18];
    const float* Q0_b      = (const float*)d_in[19];
    const float* W0_W      = (const float*)d_in[20];
    const float* W0_b      = (const float*)d_in[21];
    const float* Q1_W      = (const float*)d_in[22];
    const float* Q1_b      = (const float*)d_in[23];
    const float* W1_W      = (const float*)d_in[24];
    const float* W1_b      = (const float*)d_in[25];
    const float* bias      = (const float*)d_in[26];
    float* out = (float*)d_out;

    float *p_T, *p_h, *p_agg0, *p_ws0, *p_h1, *p_agg1, *p_ws1, *p_hitem, *p_scores;
    unsigned *p_nb;
    unsigned int* p_R;
    cudaGetSymbolAddress((void**)&p_T,     g_T);
    cudaGetSymbolAddress((void**)&p_h,     g_h);
    cudaGetSymbolAddress((void**)&p_nb,    g_nb);
    cudaGetSymbolAddress((void**)&p_agg0,  g_agg0);
    cudaGetSymbolAddress((void**)&p_ws0,   g_ws0);
    cudaGetSymbolAddress((void**)&p_h1,    g_h1);
    cudaGetSymbolAddress((void**)&p_agg1,  g_agg1);
    cudaGetSymbolAddress((void**)&p_ws1,   g_ws1);
    cudaGetSymbolAddress((void**)&p_hitem, g_hitem);
    cudaGetSymbolAddress((void**)&p_scores,g_scores);
    cudaGetSymbolAddress((void**)&p_R,     g_rank_sum);

    cudaFuncSetAttribute(fused_proj_q_kernel,
                         cudaFuncAttributeMaxDynamicSharedMemorySize, Q_SMEM_BYTES);
    cudaFuncSetAttribute(gemm_q_ares_kernel,
                         cudaFuncAttributeMaxDynamicSharedMemorySize, Q_SMEM_BYTES);

    // ncu captures launch #4 (empirical) -> fused_proj_q (batched) this round
    zero_all_kernel<<<1024, 256>>>(p_agg0, p_ws0, p_agg1, p_ws1);                        // 1
    precompute_T_kernel<<<N_CATS * CAT_VOCAB, 128>>>(cat_embs, fc_W, p_T);               // 2
    zero_R_kernel<<<1, 1>>>(p_R);                                                        // 3
    fused_proj_q_kernel<<<N_SRC0 / 128, 256, Q_SMEM_BYTES>>>(                            // 4 (ncu)
        src0_id, src0_cats, src0_genre, p_T, fc_W, fc_b, track_emb,
        Q0_W, Q0_b, p_h, p_nb);
    edge_agg_kernel<<<NE0 / (EPW * 8), 256>>>(p_nb, es0, ed0, w0, p_agg0, p_ws0, NE0);   // 5
    gemm_wnorm_kernel<<<N_DST0 / 128, 256>>>(p_agg0, p_ws0, p_h, W0_W, W0_b,             // 6
                                             nullptr, p_h1);
    gemm_q_ares_kernel<<<N_DST0 / 128, 256, Q_SMEM_BYTES>>>(p_h1, Q1_W, Q1_b, p_nb);     // 7
    edge_agg_kernel<<<NE1 / (EPW * 8), 256>>>(p_nb, es1, ed1, w1, p_agg1, p_ws1, NE1);   // 8
    gemm_wnorm_kernel<<<N_DST1 / 128, 256>>>(p_agg1, p_ws1, p_h1, W1_W, W1_b,            // 9
                                             p_h, p_hitem);

    score_kernel<<<NS / 8, 256>>>(p_hitem, pos_src, pos_dst, neg_src, neg_dst,
                                  seed_nids, bias, p_scores);
    loss_kernel<<<NP / 256, 256>>>(p_scores, out);

    dim3 auc_grid(NP / 256, NS / AUC_JCH);
    auc_count_kernel<<<auc_grid, 256>>>(p_scores, p_R);
    if (out_size >= NP + 1)
        auc_final_kernel<<<1, 1>>>(p_R, out + NP);
}